// round 9
// baseline (speedup 1.0000x reference)
#include <cuda_runtime.h>
#include <math.h>

#define CC    128
#define GENES 4096
#define SRW   132                 // row stride (floats) for all row-major buffers

// ---- b16 kernel geometry (lenr<=16) ----
#define SKT16 17
#define B16   (16 * SRW)          // 2112 floats
#define KT16  (128 * SKT16)       // 2176 floats
#define SM16_BYTES ((3 * B16 + KT16) * 4)   // 34,048 B -> 5 CTAs/SM

// ---- b32 kernel geometry (lenr 24/32) ----
#define SKT32 33
#define B32   (32 * SRW)          // 4224 floats
#define KT32  (128 * SKT32)       // 4224 floats
#define SM32_BYTES ((3 * B32 + KT32) * 4)   // 67,584 B -> 3 CTAs/SM

// ---- long (len>32) kernel geometry ----
#define SR64  136
#define SKT64 69
#define B64   (64 * SR64)
#define KT64  (128 * SKT64)
#define SM64_BYTES ((3 * B64 + KT64) * 4)

// ---- tail kernel ----
#define SMT_BYTES (3 * B32 * 4)

__device__ int   g_starts[GENES + 1];
__device__ int   g_longcount;
__device__ int   g_longlist[GENES];
__device__ float g_qpma[CC];              // seed @ Wq[2] + bq[2]
__device__ float g_pma[GENES * CC];       // PMA attention output per gene

__device__ __forceinline__ float warp_sum(float v) {
#pragma unroll
    for (int o = 16; o; o >>= 1) v += __shfl_xor_sync(0xffffffffu, v, o);
    return v;
}
__device__ __forceinline__ float warp_max(float v) {
#pragma unroll
    for (int o = 16; o; o >>= 1) v = fmaxf(v, __shfl_xor_sync(0xffffffffu, v, o));
    return v;
}

// ============================================================================
// bounds + PMA-Q precompute
// ============================================================================
__global__ void seg_bounds_kernel(const int* __restrict__ gene_idx, int E)
{
    int e = blockIdx.x * 256 + threadIdx.x;
    if (e == 0) { g_starts[GENES] = E; g_longcount = 0; }
    if (e < E) {
        int gi = gene_idx[e];
        if (e == 0 || gene_idx[e - 1] != gi) g_starts[gi] = e;
    }
}

__global__ void prep_qpma_kernel(const float* __restrict__ Wq,
                                 const float* __restrict__ bq,
                                 const float* __restrict__ seed)
{
    int c = threadIdx.x;                       // 128 threads
    float acc = bq[2 * CC + c];
    const float* W2 = Wq + 2 * CC * CC;
#pragma unroll 8
    for (int k = 0; k < CC; k++) acc = fmaf(seed[k], W2[k * CC + c], acc);
    g_qpma[c] = acc;
}

// ============================================================================
// mm32s<NS,SKT>: X[NS*4 rows,128] @ W + b -> Y. 8 warps = 4 row-groups x 2 halves.
// NS = exact slots per warp (no guards). float2 W loads per lane.
// ============================================================================
template <int NS, int SKT, bool TRANS, bool RELU>
__device__ __forceinline__ void mm32s(const float* X, const float* __restrict__ W,
                                      const float* __restrict__ bias, float* Y,
                                      int w, int lane)
{
    int rg = w >> 1;                    // 0..3, rows rg, rg+4, ...
    int ch = w & 1;                     // col half
    int c0 = ch * 64 + lane * 2;
    float acc[NS][2];
#pragma unroll
    for (int i = 0; i < NS; i++) { acc[i][0] = 0.f; acc[i][1] = 0.f; }

#pragma unroll 2
    for (int kk = 0; kk < CC; kk += 4) {
        float2 w0 = *(const float2*)(W + (kk + 0) * CC + c0);
        float2 w1 = *(const float2*)(W + (kk + 1) * CC + c0);
        float2 w2 = *(const float2*)(W + (kk + 2) * CC + c0);
        float2 w3 = *(const float2*)(W + (kk + 3) * CC + c0);
#pragma unroll
        for (int i = 0; i < NS; i++) {
            float4 xv = *(const float4*)(X + (rg + 4 * i) * SRW + kk);
            acc[i][0] = fmaf(xv.x, w0.x, acc[i][0]);
            acc[i][1] = fmaf(xv.x, w0.y, acc[i][1]);
            acc[i][0] = fmaf(xv.y, w1.x, acc[i][0]);
            acc[i][1] = fmaf(xv.y, w1.y, acc[i][1]);
            acc[i][0] = fmaf(xv.z, w2.x, acc[i][0]);
            acc[i][1] = fmaf(xv.z, w2.y, acc[i][1]);
            acc[i][0] = fmaf(xv.w, w3.x, acc[i][0]);
            acc[i][1] = fmaf(xv.w, w3.y, acc[i][1]);
        }
    }
    float2 bv = *(const float2*)(bias + c0);
#pragma unroll
    for (int i = 0; i < NS; i++) {
        int r = rg + 4 * i;
        float o0 = acc[i][0] + bv.x, o1 = acc[i][1] + bv.y;
        if (RELU) { o0 = fmaxf(o0, 0.f); o1 = fmaxf(o1, 0.f); }
        if (!TRANS) {
            *(float2*)(Y + r * SRW + c0) = make_float2(o0, o1);
        } else {
            Y[(c0 + 0) * SKT + r] = o0;
            Y[(c0 + 1) * SKT + r] = o1;
        }
    }
}

// ============================================================================
// mm64row: row-split matmul for the long (64-row) kernel
// ============================================================================
template <bool TRANS, bool RELU>
__device__ void mm64row(const float* X, const float* __restrict__ W,
                        const float* __restrict__ bias, float* Y,
                        int rows, int w, int lane)
{
    int nr = (rows > w) ? (((rows - 1 - w) >> 3) + 1) : 0;
    if (nr == 0) return;
    int c0 = lane * 4;
    float acc[8][4];
#pragma unroll
    for (int i = 0; i < 8; i++) { acc[i][0]=0.f; acc[i][1]=0.f; acc[i][2]=0.f; acc[i][3]=0.f; }

#pragma unroll 2
    for (int kk = 0; kk < CC; kk += 4) {
        float4 w0 = *(const float4*)(W + (kk + 0) * CC + c0);
        float4 w1 = *(const float4*)(W + (kk + 1) * CC + c0);
        float4 w2 = *(const float4*)(W + (kk + 2) * CC + c0);
        float4 w3 = *(const float4*)(W + (kk + 3) * CC + c0);
#pragma unroll
        for (int i = 0; i < 8; i++) {
            if (i < nr) {
                float4 xv = *(const float4*)(X + (w + 8 * i) * SR64 + kk);
                acc[i][0]=fmaf(xv.x,w0.x,acc[i][0]); acc[i][1]=fmaf(xv.x,w0.y,acc[i][1]);
                acc[i][2]=fmaf(xv.x,w0.z,acc[i][2]); acc[i][3]=fmaf(xv.x,w0.w,acc[i][3]);
                acc[i][0]=fmaf(xv.y,w1.x,acc[i][0]); acc[i][1]=fmaf(xv.y,w1.y,acc[i][1]);
                acc[i][2]=fmaf(xv.y,w1.z,acc[i][2]); acc[i][3]=fmaf(xv.y,w1.w,acc[i][3]);
                acc[i][0]=fmaf(xv.z,w2.x,acc[i][0]); acc[i][1]=fmaf(xv.z,w2.y,acc[i][1]);
                acc[i][2]=fmaf(xv.z,w2.z,acc[i][2]); acc[i][3]=fmaf(xv.z,w2.w,acc[i][3]);
                acc[i][0]=fmaf(xv.w,w3.x,acc[i][0]); acc[i][1]=fmaf(xv.w,w3.y,acc[i][1]);
                acc[i][2]=fmaf(xv.w,w3.z,acc[i][2]); acc[i][3]=fmaf(xv.w,w3.w,acc[i][3]);
            }
        }
    }
    float4 bv = *(const float4*)(bias + c0);
#pragma unroll
    for (int i = 0; i < 8; i++) {
        if (i < nr) {
            int r = w + 8 * i;
            float o0=acc[i][0]+bv.x, o1=acc[i][1]+bv.y, o2=acc[i][2]+bv.z, o3=acc[i][3]+bv.w;
            if (RELU) { o0=fmaxf(o0,0.f); o1=fmaxf(o1,0.f); o2=fmaxf(o2,0.f); o3=fmaxf(o3,0.f); }
            if (!TRANS) {
                *(float4*)(Y + r * SR64 + c0) = make_float4(o0, o1, o2, o3);
            } else {
                Y[(c0+0)*SKT64 + r]=o0; Y[(c0+1)*SKT64 + r]=o1;
                Y[(c0+2)*SKT64 + r]=o2; Y[(c0+3)*SKT64 + r]=o3;
            }
        }
    }
}

// ============================================================================
// attention, kv rows = KVR (compile-time), K^T stride SKT.
// ============================================================================
template <int KVR, int SKT>
__device__ __forceinline__ void attn32s(const float* Q, const float* Kt, const float* V,
                                        float* outp, int outStride,
                                        int Lq, int len, int w, int lane)
{
    const float scale = 0.17677669529663687f;   // 1/sqrt(32)
    int ntask = Lq * 4;
    for (int t = w; t < ntask; t += 8) {
        int r = t >> 2, base = (t & 3) * 32;
        float s = 0.f;
#pragma unroll
        for (int d = 0; d < 32; d++)
            s = fmaf(Q[r * SRW + base + d], Kt[(base + d) * SKT + lane], s);
        s = (lane < len) ? s * scale : -1e30f;
        float m = warp_max(s);
        float p = __expf(s - m);
        float inv = 1.f / warp_sum(p);
        float a = p * inv;
        float acc = 0.f;
#pragma unroll
        for (int k = 0; k < KVR; k++)
            acc = fmaf(__shfl_sync(0xffffffffu, a, k), V[k * SRW + base + lane], acc);
        outp[r * outStride + base + lane] = acc;
    }
}

// attention (kv <= 64) for the long kernel
__device__ void attn64(const float* Q, const float* Kt, const float* V,
                       float* outp, int outStride,
                       int Lq, int len, int kvr, int w, int lane)
{
    const float scale = 0.17677669529663687f;
    int ntask = Lq * 4;
    for (int t = w; t < ntask; t += 8) {
        int r = t >> 2, base = (t & 3) * 32;
        float s0 = 0.f, s1 = 0.f;
#pragma unroll
        for (int d = 0; d < 32; d++) {
            float qd = Q[r * SR64 + base + d];
            s0 = fmaf(qd, Kt[(base + d) * SKT64 + lane], s0);
            s1 = fmaf(qd, Kt[(base + d) * SKT64 + lane + 32], s1);
        }
        s0 = (lane < len)      ? s0 * scale : -1e30f;
        s1 = (lane + 32 < len) ? s1 * scale : -1e30f;
        float m = warp_max(fmaxf(s0, s1));
        float p0 = __expf(s0 - m), p1 = __expf(s1 - m);
        float inv = 1.f / warp_sum(p0 + p1);
        float a0 = p0 * inv, a1 = p1 * inv;
        float acc = 0.f;
        int k0 = kvr < 32 ? kvr : 32;
        for (int k = 0; k < k0; k++)
            acc = fmaf(__shfl_sync(0xffffffffu, a0, k), V[k * SR64 + base + lane], acc);
        for (int k = 32; k < kvr; k++)
            acc = fmaf(__shfl_sync(0xffffffffu, a1, k - 32), V[k * SR64 + base + lane], acc);
        outp[r * outStride + base + lane] = acc;
    }
}

// ============================================================================
// LN(residual + masked A) over 128. resStride==0 -> broadcast residual.
// ============================================================================
template <int SROW>
__device__ void lnres(const float* A, const float* Res, int resStride, float* Out,
                      int rows, int qmasklen,
                      const float* __restrict__ g, const float* __restrict__ b,
                      int w, int lane)
{
    for (int r = w; r < rows; r += 8) {
        float4 a = (r < qmasklen) ? *(const float4*)(A + r * SROW + lane * 4)
                                  : make_float4(0.f, 0.f, 0.f, 0.f);
        float4 s = *(const float4*)(Res + r * resStride + lane * 4);
        float t0 = a.x + s.x, t1 = a.y + s.y, t2 = a.z + s.z, t3 = a.w + s.w;
        float sum = warp_sum(t0 + t1 + t2 + t3);
        float sq  = warp_sum(t0*t0 + t1*t1 + t2*t2 + t3*t3);
        float mean = sum * (1.f / 128.f);
        float var  = sq * (1.f / 128.f) - mean * mean;
        float rstd = rsqrtf(var + 1e-5f);
        float4 gv = *(const float4*)(g + lane * 4);
        float4 bv = *(const float4*)(b + lane * 4);
        float4 o;
        o.x = (t0 - mean) * rstd * gv.x + bv.x;
        o.y = (t1 - mean) * rstd * gv.y + bv.y;
        o.z = (t2 - mean) * rstd * gv.z + bv.z;
        o.w = (t3 - mean) * rstd * gv.w + bv.w;
        *(float4*)(Out + r * SROW + lane * 4) = o;
    }
}

// ============================================================================
// encoder(x2) + PMA-attention, specialized on NS (rows = NS*4) and SKT
// ============================================================================
template <int NS, int SKT>
__device__ __forceinline__ void enc_pma(
    float* Sst, float* SA, float* SB, float* SC,
    const float* __restrict__ Wq, const float* __restrict__ Wk,
    const float* __restrict__ Wv, const float* __restrict__ Wo,
    const float* __restrict__ bq, const float* __restrict__ bk,
    const float* __restrict__ bv, const float* __restrict__ bo,
    const float* __restrict__ Wlin, const float* __restrict__ blin,
    const float* __restrict__ g1, const float* __restrict__ b1,
    const float* __restrict__ g2, const float* __restrict__ b2,
    float* pma_out,
    int len, int w, int lane, int tid)
{
    constexpr int ROWS = NS * 4;

#pragma unroll 1
    for (int blk = 0; blk < 2; blk++) {
        const float* wq = Wq + blk * CC * CC;  const float* wk = Wk + blk * CC * CC;
        const float* wv = Wv + blk * CC * CC;  const float* wo = Wo + blk * CC * CC;
        const float* wl = Wlin + blk * CC * CC;
        mm32s<NS, SKT, false, false>(Sst, wq, bq + blk * CC, SA, w, lane);
        mm32s<NS, SKT, true,  false>(Sst, wk, bk + blk * CC, SB, w, lane);
        mm32s<NS, SKT, false, false>(Sst, wv, bv + blk * CC, SC, w, lane);
        __syncthreads();
        attn32s<ROWS, SKT>(SA, SB, SC, SA, SRW, ROWS, len, w, lane);
        __syncthreads();
        mm32s<NS, SKT, false, false>(SA, wo, bo + blk * CC, SB, w, lane);
        __syncthreads();
        lnres<SRW>(SB, Sst, SRW, Sst, ROWS, len, g1 + blk * CC, b1 + blk * CC, w, lane);
        __syncthreads();
        mm32s<NS, SKT, false, true>(Sst, wl, blin + blk * CC, SC, w, lane);
        __syncthreads();
        lnres<SRW>(SC, Sst, SRW, Sst, ROWS, ROWS, g2 + blk * CC, b2 + blk * CC, w, lane);
        __syncthreads();
    }

    // PMA attention (block 2): Q is the precomputed constant vector
    if (tid < CC) SA[tid] = g_qpma[tid];
    mm32s<NS, SKT, true,  false>(Sst, Wk + 2 * CC * CC, bk + 2 * CC, SB, w, lane);
    mm32s<NS, SKT, false, false>(Sst, Wv + 2 * CC * CC, bv + 2 * CC, SC, w, lane);
    __syncthreads();
    attn32s<ROWS, SKT>(SA, SB, SC, pma_out, CC, 1, len, w, lane);
}

// ============================================================================
// B16 kernel: lenr <= 16  (34KB smem -> 5 CTAs/SM)
// ============================================================================
__global__ __launch_bounds__(256, 5)
void gene_b16(const float* __restrict__ rf,
              const float* __restrict__ Wq, const float* __restrict__ Wk,
              const float* __restrict__ Wv, const float* __restrict__ Wo,
              const float* __restrict__ bq, const float* __restrict__ bk,
              const float* __restrict__ bv, const float* __restrict__ bo,
              const float* __restrict__ Wlin, const float* __restrict__ blin,
              const float* __restrict__ g1, const float* __restrict__ b1,
              const float* __restrict__ g2, const float* __restrict__ b2,
              const int* __restrict__ rxn_idx)
{
    extern __shared__ float sm[];
    float* Sst = sm;                    // [16][SRW]
    float* SA  = sm + B16;
    float* SB  = SA + B16;              // K^T [128][SKT16]
    float* SC  = SB + KT16;

    int g    = blockIdx.x;
    int tid  = threadIdx.x;
    int w    = tid >> 5;
    int lane = tid & 31;

    int start = g_starts[g];
    int len   = g_starts[g + 1] - start;
    if (len > 16) return;               // handled by b32 / long
    int lenr = (len + 7) & ~7;          // 8 or 16

    for (int r = w; r < lenr; r += 8) {
        if (r < len) {
            int rx = rxn_idx[start + r];
            ((float4*)(Sst + r * SRW))[lane] = ((const float4*)(rf + (size_t)rx * CC))[lane];
        } else {
            ((float4*)(Sst + r * SRW))[lane] = make_float4(0.f, 0.f, 0.f, 0.f);
        }
    }
    __syncthreads();

    float* pma_out = g_pma + (size_t)g * CC;
    if (lenr == 8)
        enc_pma<2, SKT16>(Sst, SA, SB, SC, Wq, Wk, Wv, Wo, bq, bk, bv, bo,
                          Wlin, blin, g1, b1, g2, b2, pma_out, len, w, lane, tid);
    else
        enc_pma<4, SKT16>(Sst, SA, SB, SC, Wq, Wk, Wv, Wo, bq, bk, bv, bo,
                          Wlin, blin, g1, b1, g2, b2, pma_out, len, w, lane, tid);
}

// ============================================================================
// B32 kernel: 16 < len <= 32  (67.6KB smem -> 3 CTAs/SM); registers long genes
// ============================================================================
__global__ __launch_bounds__(256, 3)
void gene_b32(const float* __restrict__ rf,
              const float* __restrict__ Wq, const float* __restrict__ Wk,
              const float* __restrict__ Wv, const float* __restrict__ Wo,
              const float* __restrict__ bq, const float* __restrict__ bk,
              const float* __restrict__ bv, const float* __restrict__ bo,
              const float* __restrict__ Wlin, const float* __restrict__ blin,
              const float* __restrict__ g1, const float* __restrict__ b1,
              const float* __restrict__ g2, const float* __restrict__ b2,
              const int* __restrict__ rxn_idx)
{
    extern __shared__ float sm[];
    float* Sst = sm;                    // [32][SRW]
    float* SA  = sm + B32;
    float* SB  = SA + B32;              // K^T [128][SKT32]
    float* SC  = SB + KT32;

    int g    = blockIdx.x;
    int tid  = threadIdx.x;
    int w    = tid >> 5;
    int lane = tid & 31;

    int start = g_starts[g];
    int len   = g_starts[g + 1] - start;
    if (len <= 16) return;              // handled by b16
    if (len > 32) {                     // defer to long kernel
        if (tid == 0) { int p = atomicAdd(&g_longcount, 1); g_longlist[p] = g; }
        return;
    }
    int lenr = (len + 7) & ~7;          // 24 or 32

    for (int r = w; r < lenr; r += 8) {
        if (r < len) {
            int rx = rxn_idx[start + r];
            ((float4*)(Sst + r * SRW))[lane] = ((const float4*)(rf + (size_t)rx * CC))[lane];
        } else {
            ((float4*)(Sst + r * SRW))[lane] = make_float4(0.f, 0.f, 0.f, 0.f);
        }
    }
    __syncthreads();

    float* pma_out = g_pma + (size_t)g * CC;
    if (lenr == 24)
        enc_pma<6, SKT32>(Sst, SA, SB, SC, Wq, Wk, Wv, Wo, bq, bk, bv, bo,
                          Wlin, blin, g1, b1, g2, b2, pma_out, len, w, lane, tid);
    else
        enc_pma<8, SKT32>(Sst, SA, SB, SC, Wq, Wk, Wv, Wo, bq, bk, bv, bo,
                          Wlin, blin, g1, b1, g2, b2, pma_out, len, w, lane, tid);
}

// ============================================================================
// LONG kernel: genes with len > 32 (rare); ends after PMA attention
// ============================================================================
__global__ __launch_bounds__(256, 1)
void gene_long64(const float* __restrict__ rf,
                 const float* __restrict__ Wq, const float* __restrict__ Wk,
                 const float* __restrict__ Wv, const float* __restrict__ Wo,
                 const float* __restrict__ bq, const float* __restrict__ bk,
                 const float* __restrict__ bv, const float* __restrict__ bo,
                 const float* __restrict__ Wlin, const float* __restrict__ blin,
                 const float* __restrict__ g1, const float* __restrict__ b1,
                 const float* __restrict__ g2, const float* __restrict__ b2,
                 const int* __restrict__ rxn_idx)
{
    extern __shared__ float sm[];
    float* Sst = sm;                    // [64][SR64]
    float* SA  = sm + B64;
    float* SB  = SA + B64;              // K^T [128][SKT64]
    float* SC  = SB + KT64;

    int tid  = threadIdx.x;
    int w    = tid >> 5;
    int lane = tid & 31;
    int nlong = g_longcount;

    for (int i = blockIdx.x; i < nlong; i += gridDim.x) {
        int g     = g_longlist[i];
        int start = g_starts[g];
        int cnt   = g_starts[g + 1] - start;
        int len   = cnt < 64 ? cnt : 64;
        int lenr  = (len + 7) & ~7;
        if (lenr > 64) lenr = 64;

        for (int r = w; r < lenr; r += 8) {
            if (r < len) {
                int rx = rxn_idx[start + r];
                ((float4*)(Sst + r * SR64))[lane] = ((const float4*)(rf + (size_t)rx * CC))[lane];
            } else {
                ((float4*)(Sst + r * SR64))[lane] = make_float4(0.f, 0.f, 0.f, 0.f);
            }
        }
        __syncthreads();

        for (int blk = 0; blk < 2; blk++) {
            const float* wq = Wq + blk * CC * CC;  const float* wk = Wk + blk * CC * CC;
            const float* wv = Wv + blk * CC * CC;  const float* wo = Wo + blk * CC * CC;
            const float* wl = Wlin + blk * CC * CC;
            mm64row<false, false>(Sst, wq, bq + blk * CC, SA, lenr, w, lane);
            mm64row<true,  false>(Sst, wk, bk + blk * CC, SB, lenr, w, lane);
            mm64row<false, false>(Sst, wv, bv + blk * CC, SC, lenr, w, lane);
            __syncthreads();
            attn64(SA, SB, SC, SA, SR64, lenr, len, lenr, w, lane);
            __syncthreads();
            mm64row<false, false>(SA, wo, bo + blk * CC, SB, lenr, w, lane);
            __syncthreads();
            lnres<SR64>(SB, Sst, SR64, Sst, lenr, len, g1 + blk * CC, b1 + blk * CC, w, lane);
            __syncthreads();
            mm64row<false, true>(Sst, wl, blin + blk * CC, SC, lenr, w, lane);
            __syncthreads();
            lnres<SR64>(SC, Sst, SR64, Sst, lenr, lenr, g2 + blk * CC, b2 + blk * CC, w, lane);
            __syncthreads();
        }
        if (tid < CC) SA[tid] = g_qpma[tid];
        mm64row<true,  false>(Sst, Wk + 2 * CC * CC, bk + 2 * CC, SB, lenr, w, lane);
        mm64row<false, false>(Sst, Wv + 2 * CC * CC, bv + 2 * CC, SC, lenr, w, lane);
        __syncthreads();
        attn64(SA, SB, SC, g_pma + (size_t)g * CC, CC, 1, len, lenr, w, lane);
        __syncthreads();
    }
}

// ============================================================================
// TAIL kernel: batched PMA-projection + decoder over 32 genes per CTA
// ============================================================================
__global__ __launch_bounds__(256)
void gene_tail(const float* __restrict__ Wv, const float* __restrict__ Wo,
               const float* __restrict__ bv, const float* __restrict__ bo,
               const float* __restrict__ Wlin, const float* __restrict__ blin,
               const float* __restrict__ g1, const float* __restrict__ b1,
               const float* __restrict__ g2, const float* __restrict__ b2,
               const float* __restrict__ seed,
               float* __restrict__ out)
{
    extern __shared__ float sm[];
    float* Sst = sm;                    // [32][SRW]
    float* SA  = sm + B32;
    float* SC  = SA + B32;

    int g0   = blockIdx.x * 32;
    int tid  = threadIdx.x;
    int w    = tid >> 5;
    int lane = tid & 31;

    for (int r = w; r < 32; r += 8)
        ((float4*)(Sst + r * SRW))[lane] = ((const float4*)(g_pma + (size_t)(g0 + r) * CC))[lane];
    __syncthreads();

    // PMA projection + LN/FF (block 2); residual = seed (broadcast)
    mm32s<8, SKT32, false, false>(Sst, Wo + 2 * CC * CC, bo + 2 * CC, SA, w, lane);
    __syncthreads();
    lnres<SRW>(SA, seed, 0, Sst, 32, 32, g1 + 2 * CC, b1 + 2 * CC, w, lane);
    __syncthreads();
    mm32s<8, SKT32, false, true>(Sst, Wlin + 2 * CC * CC, blin + 2 * CC, SC, w, lane);
    __syncthreads();
    lnres<SRW>(SC, Sst, SRW, Sst, 32, 32, g2 + 2 * CC, b2 + 2 * CC, w, lane);
    __syncthreads();

    // decoder SAB (block 3): Lq=Lk=1 -> attn = V
    mm32s<8, SKT32, false, false>(Sst, Wv + 3 * CC * CC, bv + 3 * CC, SA, w, lane);
    __syncthreads();
    mm32s<8, SKT32, false, false>(SA, Wo + 3 * CC * CC, bo + 3 * CC, SC, w, lane);
    __syncthreads();
    lnres<SRW>(SC, Sst, SRW, Sst, 32, 32, g1 + 3 * CC, b1 + 3 * CC, w, lane);
    __syncthreads();
    mm32s<8, SKT32, false, true>(Sst, Wlin + 3 * CC * CC, blin + 3 * CC, SC, w, lane);
    __syncthreads();
    lnres<SRW>(SC, Sst, SRW, Sst, 32, 32, g2 + 3 * CC, b2 + 3 * CC, w, lane);
    __syncthreads();

    for (int r = w; r < 32; r += 8) {
        float4 v = ((const float4*)(Sst + r * SRW))[lane];
        float o[4] = {v.x, v.y, v.z, v.w};
#pragma unroll
        for (int j = 0; j < 4; j++) {
            float x = o[j];
            if (x != x) x = 0.f;
            x = fminf(fmaxf(x, -3.402823466e38f), 3.402823466e38f);
            o[j] = x;
        }
        ((float4*)(out + (size_t)(g0 + r) * CC))[lane] = make_float4(o[0], o[1], o[2], o[3]);
    }
}

extern "C" void kernel_launch(void* const* d_in, const int* in_sizes, int n_in,
                              void* d_out, int out_size)
{
    const float* rf   = (const float*)d_in[0];
    const float* Wq   = (const float*)d_in[1];
    const float* Wk   = (const float*)d_in[2];
    const float* Wv   = (const float*)d_in[3];
    const float* Wo   = (const float*)d_in[4];
    const float* bq   = (const float*)d_in[5];
    const float* bk   = (const float*)d_in[6];
    const float* bv   = (const float*)d_in[7];
    const float* bo   = (const float*)d_in[8];
    const float* Wlin = (const float*)d_in[9];
    const float* blin = (const float*)d_in[10];
    const float* g1   = (const float*)d_in[11];
    const float* b1   = (const float*)d_in[12];
    const float* g2   = (const float*)d_in[13];
    const float* b2   = (const float*)d_in[14];
    const float* seed = (const float*)d_in[15];
    const int*   rxn  = (const int*)d_in[16];
    const int*   gidx = (const int*)d_in[17];
    int E = in_sizes[16];

    cudaFuncSetAttribute(gene_b16,    cudaFuncAttributeMaxDynamicSharedMemorySize, SM16_BYTES);
    cudaFuncSetAttribute(gene_b32,    cudaFuncAttributeMaxDynamicSharedMemorySize, SM32_BYTES);
    cudaFuncSetAttribute(gene_long64, cudaFuncAttributeMaxDynamicSharedMemorySize, SM64_BYTES);
    cudaFuncSetAttribute(gene_tail,   cudaFuncAttributeMaxDynamicSharedMemorySize, SMT_BYTES);

    seg_bounds_kernel<<<(E + 255) / 256, 256>>>(gidx, E);
    prep_qpma_kernel<<<1, 128>>>(Wq, bq, seed);
    gene_b16<<<GENES, 256, SM16_BYTES>>>(rf, Wq, Wk, Wv, Wo, bq, bk, bv, bo,
                                         Wlin, blin, g1, b1, g2, b2, rxn);
    gene_b32<<<GENES, 256, SM32_BYTES>>>(rf, Wq, Wk, Wv, Wo, bq, bk, bv, bo,
                                         Wlin, blin, g1, b1, g2, b2, rxn);
    gene_long64<<<128, 256, SM64_BYTES>>>(rf, Wq, Wk, Wv, Wo, bq, bk, bv, bo,
                                          Wlin, blin, g1, b1, g2, b2, rxn);
    gene_tail<<<GENES / 32, 256, SMT_BYTES>>>(Wv, Wo, bv, bo, Wlin, blin,
                                              g1, b1, g2, b2, seed, (float*)d_out);
}

// round 10
// speedup vs baseline: 1.0830x; 1.0830x over previous
#include <cuda_runtime.h>
#include <math.h>

#define CC    128
#define GENES 4096
#define SRW   132                 // row stride (floats)

// ---- 32-row packed kernel geometry ----
#define SKT32 33
#define B32   (32 * SRW)          // 4224 floats
#define KT32  (128 * SKT32)       // 4224 floats
#define SM32_BYTES ((3 * B32 + KT32) * 4)   // 67,584 B -> 3 CTAs/SM

// ---- long (len>32) kernel geometry ----
#define SR64  136
#define SKT64 69
#define B64   (64 * SR64)
#define KT64  (128 * SKT64)
#define SM64_BYTES ((3 * B64 + KT64) * 4)

// ---- tail kernel ----
#define SMT_BYTES (3 * B32 * 4)

__device__ int   g_starts[GENES + 1];
__device__ int   g_nsmall, g_nmid, g_longcount;
__device__ int   g_smalllist[GENES];
__device__ int   g_midlist[GENES];
__device__ int   g_longlist[GENES];
__device__ float g_qpma[CC];              // seed @ Wq[2] + bq[2]
__device__ float g_pma[GENES * CC];       // PMA attention output per gene

__device__ __forceinline__ float warp_sum(float v) {
#pragma unroll
    for (int o = 16; o; o >>= 1) v += __shfl_xor_sync(0xffffffffu, v, o);
    return v;
}
__device__ __forceinline__ float warp_max(float v) {
#pragma unroll
    for (int o = 16; o; o >>= 1) v = fmaxf(v, __shfl_xor_sync(0xffffffffu, v, o));
    return v;
}

// ============================================================================
// bounds + classify + PMA-Q precompute
// ============================================================================
__global__ void seg_bounds_kernel(const int* __restrict__ gene_idx, int E)
{
    int e = blockIdx.x * 256 + threadIdx.x;
    if (e == 0) { g_starts[GENES] = E; g_nsmall = 0; g_nmid = 0; g_longcount = 0; }
    if (e < E) {
        int gi = gene_idx[e];
        if (e == 0 || gene_idx[e - 1] != gi) g_starts[gi] = e;
    }
}

__global__ void classify_kernel()
{
    int g = blockIdx.x * 256 + threadIdx.x;
    if (g < GENES) {
        int len = g_starts[g + 1] - g_starts[g];
        if (len <= 16)      { int p = atomicAdd(&g_nsmall, 1);    g_smalllist[p] = g; }
        else if (len <= 32) { int p = atomicAdd(&g_nmid, 1);      g_midlist[p]   = g; }
        else                { int p = atomicAdd(&g_longcount, 1); g_longlist[p]  = g; }
    }
}

__global__ void prep_qpma_kernel(const float* __restrict__ Wq,
                                 const float* __restrict__ bq,
                                 const float* __restrict__ seed)
{
    int c = threadIdx.x;                       // 128 threads
    float acc = bq[2 * CC + c];
    const float* W2 = Wq + 2 * CC * CC;
#pragma unroll 8
    for (int k = 0; k < CC; k++) acc = fmaf(seed[k], W2[k * CC + c], acc);
    g_qpma[c] = acc;
}

// ============================================================================
// mm32s<NS>: X[NS*4 rows,128] @ W + b -> Y. 8 warps = 4 row-groups x 2 halves.
// ============================================================================
template <int NS, bool TRANS, bool RELU>
__device__ __forceinline__ void mm32s(const float* X, const float* __restrict__ W,
                                      const float* __restrict__ bias, float* Y,
                                      int w, int lane)
{
    int rg = w >> 1;
    int ch = w & 1;
    int c0 = ch * 64 + lane * 2;
    float acc[NS][2];
#pragma unroll
    for (int i = 0; i < NS; i++) { acc[i][0] = 0.f; acc[i][1] = 0.f; }

#pragma unroll 2
    for (int kk = 0; kk < CC; kk += 4) {
        float2 w0 = *(const float2*)(W + (kk + 0) * CC + c0);
        float2 w1 = *(const float2*)(W + (kk + 1) * CC + c0);
        float2 w2 = *(const float2*)(W + (kk + 2) * CC + c0);
        float2 w3 = *(const float2*)(W + (kk + 3) * CC + c0);
#pragma unroll
        for (int i = 0; i < NS; i++) {
            float4 xv = *(const float4*)(X + (rg + 4 * i) * SRW + kk);
            acc[i][0] = fmaf(xv.x, w0.x, acc[i][0]);
            acc[i][1] = fmaf(xv.x, w0.y, acc[i][1]);
            acc[i][0] = fmaf(xv.y, w1.x, acc[i][0]);
            acc[i][1] = fmaf(xv.y, w1.y, acc[i][1]);
            acc[i][0] = fmaf(xv.z, w2.x, acc[i][0]);
            acc[i][1] = fmaf(xv.z, w2.y, acc[i][1]);
            acc[i][0] = fmaf(xv.w, w3.x, acc[i][0]);
            acc[i][1] = fmaf(xv.w, w3.y, acc[i][1]);
        }
    }
    float2 bv = *(const float2*)(bias + c0);
#pragma unroll
    for (int i = 0; i < NS; i++) {
        int r = rg + 4 * i;
        float o0 = acc[i][0] + bv.x, o1 = acc[i][1] + bv.y;
        if (RELU) { o0 = fmaxf(o0, 0.f); o1 = fmaxf(o1, 0.f); }
        if (!TRANS) {
            *(float2*)(Y + r * SRW + c0) = make_float2(o0, o1);
        } else {
            Y[(c0 + 0) * SKT32 + r] = o0;
            Y[(c0 + 1) * SKT32 + r] = o1;
        }
    }
}

// ============================================================================
// mm64row: row-split matmul for the long (64-row) kernel
// ============================================================================
template <bool TRANS, bool RELU>
__device__ void mm64row(const float* X, const float* __restrict__ W,
                        const float* __restrict__ bias, float* Y,
                        int rows, int w, int lane)
{
    int nr = (rows > w) ? (((rows - 1 - w) >> 3) + 1) : 0;
    if (nr == 0) return;
    int c0 = lane * 4;
    float acc[8][4];
#pragma unroll
    for (int i = 0; i < 8; i++) { acc[i][0]=0.f; acc[i][1]=0.f; acc[i][2]=0.f; acc[i][3]=0.f; }

#pragma unroll 2
    for (int kk = 0; kk < CC; kk += 4) {
        float4 w0 = *(const float4*)(W + (kk + 0) * CC + c0);
        float4 w1 = *(const float4*)(W + (kk + 1) * CC + c0);
        float4 w2 = *(const float4*)(W + (kk + 2) * CC + c0);
        float4 w3 = *(const float4*)(W + (kk + 3) * CC + c0);
#pragma unroll
        for (int i = 0; i < 8; i++) {
            if (i < nr) {
                float4 xv = *(const float4*)(X + (w + 8 * i) * SR64 + kk);
                acc[i][0]=fmaf(xv.x,w0.x,acc[i][0]); acc[i][1]=fmaf(xv.x,w0.y,acc[i][1]);
                acc[i][2]=fmaf(xv.x,w0.z,acc[i][2]); acc[i][3]=fmaf(xv.x,w0.w,acc[i][3]);
                acc[i][0]=fmaf(xv.y,w1.x,acc[i][0]); acc[i][1]=fmaf(xv.y,w1.y,acc[i][1]);
                acc[i][2]=fmaf(xv.y,w1.z,acc[i][2]); acc[i][3]=fmaf(xv.y,w1.w,acc[i][3]);
                acc[i][0]=fmaf(xv.z,w2.x,acc[i][0]); acc[i][1]=fmaf(xv.z,w2.y,acc[i][1]);
                acc[i][2]=fmaf(xv.z,w2.z,acc[i][2]); acc[i][3]=fmaf(xv.z,w2.w,acc[i][3]);
                acc[i][0]=fmaf(xv.w,w3.x,acc[i][0]); acc[i][1]=fmaf(xv.w,w3.y,acc[i][1]);
                acc[i][2]=fmaf(xv.w,w3.z,acc[i][2]); acc[i][3]=fmaf(xv.w,w3.w,acc[i][3]);
            }
        }
    }
    float4 bv = *(const float4*)(bias + c0);
#pragma unroll
    for (int i = 0; i < 8; i++) {
        if (i < nr) {
            int r = w + 8 * i;
            float o0=acc[i][0]+bv.x, o1=acc[i][1]+bv.y, o2=acc[i][2]+bv.z, o3=acc[i][3]+bv.w;
            if (RELU) { o0=fmaxf(o0,0.f); o1=fmaxf(o1,0.f); o2=fmaxf(o2,0.f); o3=fmaxf(o3,0.f); }
            if (!TRANS) {
                *(float4*)(Y + r * SR64 + c0) = make_float4(o0, o1, o2, o3);
            } else {
                Y[(c0+0)*SKT64 + r]=o0; Y[(c0+1)*SKT64 + r]=o1;
                Y[(c0+2)*SKT64 + r]=o2; Y[(c0+3)*SKT64 + r]=o3;
            }
        }
    }
}

// ============================================================================
// single-gene attention (kv rows = KVR compile-time), window [0,len)
// ============================================================================
template <int KVR>
__device__ __forceinline__ void attn32s(const float* Q, const float* Kt, const float* V,
                                        float* outp, int outStride,
                                        int Lq, int len, int w, int lane)
{
    const float scale = 0.17677669529663687f;
    int ntask = Lq * 4;
    for (int t = w; t < ntask; t += 8) {
        int r = t >> 2, base = (t & 3) * 32;
        float s = 0.f;
#pragma unroll
        for (int d = 0; d < 32; d++)
            s = fmaf(Q[r * SRW + base + d], Kt[(base + d) * SKT32 + lane], s);
        s = (lane < len) ? s * scale : -1e30f;
        float m = warp_max(s);
        float p = __expf(s - m);
        float inv = 1.f / warp_sum(p);
        float a = p * inv;
        float acc = 0.f;
#pragma unroll
        for (int k = 0; k < KVR; k++)
            acc = fmaf(__shfl_sync(0xffffffffu, a, k), V[k * SRW + base + lane], acc);
        outp[r * outStride + base + lane] = acc;
    }
}

// paired encoder attention: rows 0-15 -> window [0,lenA); rows 16-31 -> [16,16+lenB)
__device__ __forceinline__ void attn_pair(float* QO, const float* Kt, const float* V,
                                          int lenA, int lenB, int w, int lane)
{
    const float scale = 0.17677669529663687f;
    for (int t = w; t < 128; t += 8) {
        int r = t >> 2, base = (t & 3) * 32;
        float s = 0.f;
#pragma unroll
        for (int d = 0; d < 32; d++)
            s = fmaf(QO[r * SRW + base + d], Kt[(base + d) * SKT32 + lane], s);
        int lo = (r >= 16) ? 16 : 0;
        int ln = (r >= 16) ? lenB : lenA;
        s = ((unsigned)(lane - lo) < (unsigned)ln) ? s * scale : -1e30f;
        float m = warp_max(s);
        float p = __expf(s - m);
        float inv = 1.f / warp_sum(p);
        float a = p * inv;
        float acc = 0.f;
#pragma unroll
        for (int k = 0; k < 32; k++)
            acc = fmaf(__shfl_sync(0xffffffffu, a, k), V[k * SRW + base + lane], acc);
        QO[r * SRW + base + lane] = acc;
    }
}

// paired PMA attention: 8 tasks = 2 genes x 4 heads; Q = SA row 0 (shared)
__device__ __forceinline__ void attn_pma_pair(const float* Q, const float* Kt, const float* V,
                                              int gA, int gB, int lenA, int lenB,
                                              int w, int lane)
{
    const float scale = 0.17677669529663687f;
    int gi   = w >> 2;                  // 0 = gene A, 1 = gene B
    int base = (w & 3) * 32;
    float s = 0.f;
#pragma unroll
    for (int d = 0; d < 32; d++)
        s = fmaf(Q[base + d], Kt[(base + d) * SKT32 + lane], s);
    int lo = gi ? 16 : 0;
    int ln = gi ? lenB : lenA;
    s = ((unsigned)(lane - lo) < (unsigned)ln) ? s * scale : -1e30f;
    float m = warp_max(s);
    float p = __expf(s - m);
    float inv = 1.f / warp_sum(p);
    float a = p * inv;
    float acc = 0.f;
#pragma unroll
    for (int k = 0; k < 32; k++)
        acc = fmaf(__shfl_sync(0xffffffffu, a, k), V[k * SRW + base + lane], acc);
    int gout = gi ? gB : gA;
    if (gout >= 0) g_pma[(size_t)gout * CC + base + lane] = acc;
}

// attention (kv <= 64) for the long kernel
__device__ void attn64(const float* Q, const float* Kt, const float* V,
                       float* outp, int outStride,
                       int Lq, int len, int kvr, int w, int lane)
{
    const float scale = 0.17677669529663687f;
    int ntask = Lq * 4;
    for (int t = w; t < ntask; t += 8) {
        int r = t >> 2, base = (t & 3) * 32;
        float s0 = 0.f, s1 = 0.f;
#pragma unroll
        for (int d = 0; d < 32; d++) {
            float qd = Q[r * SR64 + base + d];
            s0 = fmaf(qd, Kt[(base + d) * SKT64 + lane], s0);
            s1 = fmaf(qd, Kt[(base + d) * SKT64 + lane + 32], s1);
        }
        s0 = (lane < len)      ? s0 * scale : -1e30f;
        s1 = (lane + 32 < len) ? s1 * scale : -1e30f;
        float m = warp_max(fmaxf(s0, s1));
        float p0 = __expf(s0 - m), p1 = __expf(s1 - m);
        float inv = 1.f / warp_sum(p0 + p1);
        float a0 = p0 * inv, a1 = p1 * inv;
        float acc = 0.f;
        int k0 = kvr < 32 ? kvr : 32;
        for (int k = 0; k < k0; k++)
            acc = fmaf(__shfl_sync(0xffffffffu, a0, k), V[k * SR64 + base + lane], acc);
        for (int k = 32; k < kvr; k++)
            acc = fmaf(__shfl_sync(0xffffffffu, a1, k - 32), V[k * SR64 + base + lane], acc);
        outp[r * outStride + base + lane] = acc;
    }
}

// ============================================================================
// LN(residual + masked A). resStride==0 -> broadcast residual.
// ============================================================================
template <int SROW>
__device__ void lnres(const float* A, const float* Res, int resStride, float* Out,
                      int rows, int qmasklen,
                      const float* __restrict__ g, const float* __restrict__ b,
                      int w, int lane)
{
    for (int r = w; r < rows; r += 8) {
        float4 a = (r < qmasklen) ? *(const float4*)(A + r * SROW + lane * 4)
                                  : make_float4(0.f, 0.f, 0.f, 0.f);
        float4 s = *(const float4*)(Res + r * resStride + lane * 4);
        float t0 = a.x + s.x, t1 = a.y + s.y, t2 = a.z + s.z, t3 = a.w + s.w;
        float sum = warp_sum(t0 + t1 + t2 + t3);
        float sq  = warp_sum(t0*t0 + t1*t1 + t2*t2 + t3*t3);
        float mean = sum * (1.f / 128.f);
        float var  = sq * (1.f / 128.f) - mean * mean;
        float rstd = rsqrtf(var + 1e-5f);
        float4 gv = *(const float4*)(g + lane * 4);
        float4 bv = *(const float4*)(b + lane * 4);
        float4 o;
        o.x = (t0 - mean) * rstd * gv.x + bv.x;
        o.y = (t1 - mean) * rstd * gv.y + bv.y;
        o.z = (t2 - mean) * rstd * gv.z + bv.z;
        o.w = (t3 - mean) * rstd * gv.w + bv.w;
        *(float4*)(Out + r * SROW + lane * 4) = o;
    }
}

// paired version: row r valid if local index < its gene's len
__device__ void lnres_pair(const float* A, const float* Res, float* Out,
                           int lenA, int lenB,
                           const float* __restrict__ g, const float* __restrict__ b,
                           int w, int lane)
{
    for (int r = w; r < 32; r += 8) {
        int lo = (r >= 16) ? 16 : 0;
        int ln = (r >= 16) ? lenB : lenA;
        float4 a = ((r - lo) < ln) ? *(const float4*)(A + r * SRW + lane * 4)
                                   : make_float4(0.f, 0.f, 0.f, 0.f);
        float4 s = *(const float4*)(Res + r * SRW + lane * 4);
        float t0 = a.x + s.x, t1 = a.y + s.y, t2 = a.z + s.z, t3 = a.w + s.w;
        float sum = warp_sum(t0 + t1 + t2 + t3);
        float sq  = warp_sum(t0*t0 + t1*t1 + t2*t2 + t3*t3);
        float mean = sum * (1.f / 128.f);
        float var  = sq * (1.f / 128.f) - mean * mean;
        float rstd = rsqrtf(var + 1e-5f);
        float4 gv = *(const float4*)(g + lane * 4);
        float4 bv = *(const float4*)(b + lane * 4);
        float4 o;
        o.x = (t0 - mean) * rstd * gv.x + bv.x;
        o.y = (t1 - mean) * rstd * gv.y + bv.y;
        o.z = (t2 - mean) * rstd * gv.z + bv.z;
        o.w = (t3 - mean) * rstd * gv.w + bv.w;
        *(float4*)(Out + r * SRW + lane * 4) = o;
    }
}

// ============================================================================
// single-gene encoder(x2) + PMA attention, rows = NS*4
// ============================================================================
template <int NS>
__device__ __forceinline__ void enc_pma(
    float* Sst, float* SA, float* SB, float* SC,
    const float* __restrict__ Wq, const float* __restrict__ Wk,
    const float* __restrict__ Wv, const float* __restrict__ Wo,
    const float* __restrict__ bq, const float* __restrict__ bk,
    const float* __restrict__ bv, const float* __restrict__ bo,
    const float* __restrict__ Wlin, const float* __restrict__ blin,
    const float* __restrict__ g1, const float* __restrict__ b1,
    const float* __restrict__ g2, const float* __restrict__ b2,
    float* pma_out,
    int len, int w, int lane, int tid)
{
    constexpr int ROWS = NS * 4;
#pragma unroll 1
    for (int blk = 0; blk < 2; blk++) {
        const float* wq = Wq + blk * CC * CC;  const float* wk = Wk + blk * CC * CC;
        const float* wv = Wv + blk * CC * CC;  const float* wo = Wo + blk * CC * CC;
        const float* wl = Wlin + blk * CC * CC;
        mm32s<NS, false, false>(Sst, wq, bq + blk * CC, SA, w, lane);
        mm32s<NS, true,  false>(Sst, wk, bk + blk * CC, SB, w, lane);
        mm32s<NS, false, false>(Sst, wv, bv + blk * CC, SC, w, lane);
        __syncthreads();
        attn32s<ROWS>(SA, SB, SC, SA, SRW, ROWS, len, w, lane);
        __syncthreads();
        mm32s<NS, false, false>(SA, wo, bo + blk * CC, SB, w, lane);
        __syncthreads();
        lnres<SRW>(SB, Sst, SRW, Sst, ROWS, len, g1 + blk * CC, b1 + blk * CC, w, lane);
        __syncthreads();
        mm32s<NS, false, true>(Sst, wl, blin + blk * CC, SC, w, lane);
        __syncthreads();
        lnres<SRW>(SC, Sst, SRW, Sst, ROWS, ROWS, g2 + blk * CC, b2 + blk * CC, w, lane);
        __syncthreads();
    }
    if (tid < CC) SA[tid] = g_qpma[tid];
    mm32s<NS, true,  false>(Sst, Wk + 2 * CC * CC, bk + 2 * CC, SB, w, lane);
    mm32s<NS, false, false>(Sst, Wv + 2 * CC * CC, bv + 2 * CC, SC, w, lane);
    __syncthreads();
    attn32s<ROWS>(SA, SB, SC, pma_out, CC, 1, len, w, lane);
}

// ============================================================================
// paired encoder(x2) + PMA attention (2 genes, 32 rows)
// ============================================================================
__device__ __forceinline__ void enc_pma_pair(
    float* Sst, float* SA, float* SB, float* SC,
    const float* __restrict__ Wq, const float* __restrict__ Wk,
    const float* __restrict__ Wv, const float* __restrict__ Wo,
    const float* __restrict__ bq, const float* __restrict__ bk,
    const float* __restrict__ bv, const float* __restrict__ bo,
    const float* __restrict__ Wlin, const float* __restrict__ blin,
    const float* __restrict__ g1, const float* __restrict__ b1,
    const float* __restrict__ g2, const float* __restrict__ b2,
    int gA, int gB, int lenA, int lenB,
    int w, int lane, int tid)
{
#pragma unroll 1
    for (int blk = 0; blk < 2; blk++) {
        const float* wq = Wq + blk * CC * CC;  const float* wk = Wk + blk * CC * CC;
        const float* wv = Wv + blk * CC * CC;  const float* wo = Wo + blk * CC * CC;
        const float* wl = Wlin + blk * CC * CC;
        mm32s<8, false, false>(Sst, wq, bq + blk * CC, SA, w, lane);
        mm32s<8, true,  false>(Sst, wk, bk + blk * CC, SB, w, lane);
        mm32s<8, false, false>(Sst, wv, bv + blk * CC, SC, w, lane);
        __syncthreads();
        attn_pair(SA, SB, SC, lenA, lenB, w, lane);
        __syncthreads();
        mm32s<8, false, false>(SA, wo, bo + blk * CC, SB, w, lane);
        __syncthreads();
        lnres_pair(SB, Sst, Sst, lenA, lenB, g1 + blk * CC, b1 + blk * CC, w, lane);
        __syncthreads();
        mm32s<8, false, true>(Sst, wl, blin + blk * CC, SC, w, lane);
        __syncthreads();
        lnres<SRW>(SC, Sst, SRW, Sst, 32, 32, g2 + blk * CC, b2 + blk * CC, w, lane);
        __syncthreads();
    }
    if (tid < CC) SA[tid] = g_qpma[tid];
    mm32s<8, true,  false>(Sst, Wk + 2 * CC * CC, bk + 2 * CC, SB, w, lane);
    mm32s<8, false, false>(Sst, Wv + 2 * CC * CC, bv + 2 * CC, SC, w, lane);
    __syncthreads();
    attn_pma_pair(SA, SB, SC, gA, gB, lenA, lenB, w, lane);
}

// ============================================================================
// PACKED kernel: mid singles (16<len<=32) + pairs of small genes (len<=16)
// ============================================================================
__global__ __launch_bounds__(256, 3)
void gene_packed(const float* __restrict__ rf,
                 const float* __restrict__ Wq, const float* __restrict__ Wk,
                 const float* __restrict__ Wv, const float* __restrict__ Wo,
                 const float* __restrict__ bq, const float* __restrict__ bk,
                 const float* __restrict__ bv, const float* __restrict__ bo,
                 const float* __restrict__ Wlin, const float* __restrict__ blin,
                 const float* __restrict__ g1, const float* __restrict__ b1,
                 const float* __restrict__ g2, const float* __restrict__ b2,
                 const int* __restrict__ rxn_idx)
{
    extern __shared__ float sm[];
    float* Sst = sm;                    // [32][SRW]
    float* SA  = sm + B32;
    float* SB  = SA + B32;              // K^T [128][SKT32]
    float* SC  = SB + KT32;

    int i    = blockIdx.x;
    int tid  = threadIdx.x;
    int w    = tid >> 5;
    int lane = tid & 31;

    int nmid = g_nmid;

    if (i < nmid) {
        // ------- single mid gene -------
        int g     = g_midlist[i];
        int start = g_starts[g];
        int len   = g_starts[g + 1] - start;
        int lenr  = (len + 7) & ~7;     // 24 or 32

        for (int r = w; r < lenr; r += 8) {
            if (r < len) {
                int rx = rxn_idx[start + r];
                ((float4*)(Sst + r * SRW))[lane] = ((const float4*)(rf + (size_t)rx * CC))[lane];
            } else {
                ((float4*)(Sst + r * SRW))[lane] = make_float4(0.f, 0.f, 0.f, 0.f);
            }
        }
        __syncthreads();

        float* pma_out = g_pma + (size_t)g * CC;
        if (lenr == 24)
            enc_pma<6>(Sst, SA, SB, SC, Wq, Wk, Wv, Wo, bq, bk, bv, bo,
                       Wlin, blin, g1, b1, g2, b2, pma_out, len, w, lane, tid);
        else
            enc_pma<8>(Sst, SA, SB, SC, Wq, Wk, Wv, Wo, bq, bk, bv, bo,
                       Wlin, blin, g1, b1, g2, b2, pma_out, len, w, lane, tid);
    } else {
        // ------- pair of small genes -------
        int j = i - nmid;
        int nsmall = g_nsmall;
        if (2 * j >= nsmall) return;
        int gA = g_smalllist[2 * j];
        int gB = (2 * j + 1 < nsmall) ? g_smalllist[2 * j + 1] : -1;
        int sA = g_starts[gA], lenA = g_starts[gA + 1] - sA;
        int sB = 0, lenB = 0;
        if (gB >= 0) { sB = g_starts[gB]; lenB = g_starts[gB + 1] - sB; }

        for (int r = w; r < 32; r += 8) {
            int local = r & 15;
            bool isB  = r >= 16;
            int  ln   = isB ? lenB : lenA;
            int  st   = isB ? sB   : sA;
            if (local < ln) {
                int rx = rxn_idx[st + local];
                ((float4*)(Sst + r * SRW))[lane] = ((const float4*)(rf + (size_t)rx * CC))[lane];
            } else {
                ((float4*)(Sst + r * SRW))[lane] = make_float4(0.f, 0.f, 0.f, 0.f);
            }
        }
        __syncthreads();

        enc_pma_pair(Sst, SA, SB, SC, Wq, Wk, Wv, Wo, bq, bk, bv, bo,
                     Wlin, blin, g1, b1, g2, b2, gA, gB, lenA, lenB, w, lane, tid);
    }
}

// ============================================================================
// LONG kernel: genes with len > 32 (rare); ends after PMA attention
// ============================================================================
__global__ __launch_bounds__(256, 1)
void gene_long64(const float* __restrict__ rf,
                 const float* __restrict__ Wq, const float* __restrict__ Wk,
                 const float* __restrict__ Wv, const float* __restrict__ Wo,
                 const float* __restrict__ bq, const float* __restrict__ bk,
                 const float* __restrict__ bv, const float* __restrict__ bo,
                 const float* __restrict__ Wlin, const float* __restrict__ blin,
                 const float* __restrict__ g1, const float* __restrict__ b1,
                 const float* __restrict__ g2, const float* __restrict__ b2,
                 const int* __restrict__ rxn_idx)
{
    extern __shared__ float sm[];
    float* Sst = sm;                    // [64][SR64]
    float* SA  = sm + B64;
    float* SB  = SA + B64;
    float* SC  = SB + KT64;

    int tid  = threadIdx.x;
    int w    = tid >> 5;
    int lane = tid & 31;
    int nlong = g_longcount;

    for (int i = blockIdx.x; i < nlong; i += gridDim.x) {
        int g     = g_longlist[i];
        int start = g_starts[g];
        int cnt   = g_starts[g + 1] - start;
        int len   = cnt < 64 ? cnt : 64;
        int lenr  = (len + 7) & ~7;
        if (lenr > 64) lenr = 64;

        for (int r = w; r < lenr; r += 8) {
            if (r < len) {
                int rx = rxn_idx[start + r];
                ((float4*)(Sst + r * SR64))[lane] = ((const float4*)(rf + (size_t)rx * CC))[lane];
            } else {
                ((float4*)(Sst + r * SR64))[lane] = make_float4(0.f, 0.f, 0.f, 0.f);
            }
        }
        __syncthreads();

        for (int blk = 0; blk < 2; blk++) {
            const float* wq = Wq + blk * CC * CC;  const float* wk = Wk + blk * CC * CC;
            const float* wv = Wv + blk * CC * CC;  const float* wo = Wo + blk * CC * CC;
            const float* wl = Wlin + blk * CC * CC;
            mm64row<false, false>(Sst, wq, bq + blk * CC, SA, lenr, w, lane);
            mm64row<true,  false>(Sst, wk, bk + blk * CC, SB, lenr, w, lane);
            mm64row<false, false>(Sst, wv, bv + blk * CC, SC, lenr, w, lane);
            __syncthreads();
            attn64(SA, SB, SC, SA, SR64, lenr, len, lenr, w, lane);
            __syncthreads();
            mm64row<false, false>(SA, wo, bo + blk * CC, SB, lenr, w, lane);
            __syncthreads();
            lnres<SR64>(SB, Sst, SR64, Sst, lenr, len, g1 + blk * CC, b1 + blk * CC, w, lane);
            __syncthreads();
            mm64row<false, true>(Sst, wl, blin + blk * CC, SC, lenr, w, lane);
            __syncthreads();
            lnres<SR64>(SC, Sst, SR64, Sst, lenr, lenr, g2 + blk * CC, b2 + blk * CC, w, lane);
            __syncthreads();
        }
        if (tid < CC) SA[tid] = g_qpma[tid];
        mm64row<true,  false>(Sst, Wk + 2 * CC * CC, bk + 2 * CC, SB, lenr, w, lane);
        mm64row<false, false>(Sst, Wv + 2 * CC * CC, bv + 2 * CC, SC, lenr, w, lane);
        __syncthreads();
        attn64(SA, SB, SC, g_pma + (size_t)g * CC, CC, 1, len, lenr, w, lane);
        __syncthreads();
    }
}

// ============================================================================
// TAIL kernel: batched PMA-projection + decoder over 32 genes per CTA
// ============================================================================
__global__ __launch_bounds__(256)
void gene_tail(const float* __restrict__ Wv, const float* __restrict__ Wo,
               const float* __restrict__ bv, const float* __restrict__ bo,
               const float* __restrict__ Wlin, const float* __restrict__ blin,
               const float* __restrict__ g1, const float* __restrict__ b1,
               const float* __restrict__ g2, const float* __restrict__ b2,
               const float* __restrict__ seed,
               float* __restrict__ out)
{
    extern __shared__ float sm[];
    float* Sst = sm;                    // [32][SRW]
    float* SA  = sm + B32;
    float* SC  = SA + B32;

    int g0   = blockIdx.x * 32;
    int tid  = threadIdx.x;
    int w    = tid >> 5;
    int lane = tid & 31;

    for (int r = w; r < 32; r += 8)
        ((float4*)(Sst + r * SRW))[lane] = ((const float4*)(g_pma + (size_t)(g0 + r) * CC))[lane];
    __syncthreads();

    mm32s<8, false, false>(Sst, Wo + 2 * CC * CC, bo + 2 * CC, SA, w, lane);
    __syncthreads();
    lnres<SRW>(SA, seed, 0, Sst, 32, 32, g1 + 2 * CC, b1 + 2 * CC, w, lane);
    __syncthreads();
    mm32s<8, false, true>(Sst, Wlin + 2 * CC * CC, blin + 2 * CC, SC, w, lane);
    __syncthreads();
    lnres<SRW>(SC, Sst, SRW, Sst, 32, 32, g2 + 2 * CC, b2 + 2 * CC, w, lane);
    __syncthreads();

    mm32s<8, false, false>(Sst, Wv + 3 * CC * CC, bv + 3 * CC, SA, w, lane);
    __syncthreads();
    mm32s<8, false, false>(SA, Wo + 3 * CC * CC, bo + 3 * CC, SC, w, lane);
    __syncthreads();
    lnres<SRW>(SC, Sst, SRW, Sst, 32, 32, g1 + 3 * CC, b1 + 3 * CC, w, lane);
    __syncthreads();
    mm32s<8, false, true>(Sst, Wlin + 3 * CC * CC, blin + 3 * CC, SC, w, lane);
    __syncthreads();
    lnres<SRW>(SC, Sst, SRW, Sst, 32, 32, g2 + 3 * CC, b2 + 3 * CC, w, lane);
    __syncthreads();

    for (int r = w; r < 32; r += 8) {
        float4 v = ((const float4*)(Sst + r * SRW))[lane];
        float o[4] = {v.x, v.y, v.z, v.w};
#pragma unroll
        for (int j = 0; j < 4; j++) {
            float x = o[j];
            if (x != x) x = 0.f;
            x = fminf(fmaxf(x, -3.402823466e38f), 3.402823466e38f);
            o[j] = x;
        }
        ((float4*)(out + (size_t)(g0 + r) * CC))[lane] = make_float4(o[0], o[1], o[2], o[3]);
    }
}

extern "C" void kernel_launch(void* const* d_in, const int* in_sizes, int n_in,
                              void* d_out, int out_size)
{
    const float* rf   = (const float*)d_in[0];
    const float* Wq   = (const float*)d_in[1];
    const float* Wk   = (const float*)d_in[2];
    const float* Wv   = (const float*)d_in[3];
    const float* Wo   = (const float*)d_in[4];
    const float* bq   = (const float*)d_in[5];
    const float* bk   = (const float*)d_in[6];
    const float* bv   = (const float*)d_in[7];
    const float* bo   = (const float*)d_in[8];
    const float* Wlin = (const float*)d_in[9];
    const float* blin = (const float*)d_in[10];
    const float* g1   = (const float*)d_in[11];
    const float* b1   = (const float*)d_in[12];
    const float* g2   = (const float*)d_in[13];
    const float* b2   = (const float*)d_in[14];
    const float* seed = (const float*)d_in[15];
    const int*   rxn  = (const int*)d_in[16];
    const int*   gidx = (const int*)d_in[17];
    int E = in_sizes[16];

    cudaFuncSetAttribute(gene_packed, cudaFuncAttributeMaxDynamicSharedMemorySize, SM32_BYTES);
    cudaFuncSetAttribute(gene_long64, cudaFuncAttributeMaxDynamicSharedMemorySize, SM64_BYTES);
    cudaFuncSetAttribute(gene_tail,   cudaFuncAttributeMaxDynamicSharedMemorySize, SMT_BYTES);

    seg_bounds_kernel<<<(E + 255) / 256, 256>>>(gidx, E);
    classify_kernel<<<(GENES + 255) / 256, 256>>>();
    prep_qpma_kernel<<<1, 128>>>(Wq, bq, seed);
    gene_packed<<<GENES, 256, SM32_BYTES>>>(rf, Wq, Wk, Wv, Wo, bq, bk, bv, bo,
                                            Wlin, blin, g1, b1, g2, b2, rxn);
    gene_long64<<<128, 256, SM64_BYTES>>>(rf, Wq, Wk, Wv, Wo, bq, bk, bv, bo,
                                          Wlin, blin, g1, b1, g2, b2, rxn);
    gene_tail<<<GENES / 32, 256, SMT_BYTES>>>(Wv, Wo, bv, bo, Wlin, blin,
                                              g1, b1, g2, b2, seed, (float*)d_out);
}

// round 11
// speedup vs baseline: 1.1592x; 1.0703x over previous
#include <cuda_runtime.h>
#include <math.h>

#define CC    128
#define GENES 4096
#define SRW   132                 // row stride (floats)

// ---- 32-row packed kernel geometry ----
#define SKT32 33
#define B32   (32 * SRW)          // 4224 floats
#define KT32  (128 * SKT32)       // 4224 floats
#define SM32_BYTES ((3 * B32 + KT32) * 4)   // 67,584 B -> 3 CTAs/SM

// ---- long (len>32) kernel geometry ----
#define SR64  136
#define SKT64 69
#define B64   (64 * SR64)
#define KT64  (128 * SKT64)
#define SM64_BYTES ((3 * B64 + KT64) * 4)

// ---- tail kernel ----
#define SMT_BYTES (3 * B32 * 4)

__device__ int   g_starts[GENES + 1];
__device__ int   g_nsmall, g_nmid, g_longcount;
__device__ int   g_smalllist[GENES];
__device__ int   g_midlist[GENES];
__device__ int   g_longlist[GENES];
__device__ float g_qpma[CC];              // seed @ Wq[2] + bq[2]
__device__ float g_pma[GENES * CC];       // PMA attention output per gene

__device__ __forceinline__ float warp_sum(float v) {
#pragma unroll
    for (int o = 16; o; o >>= 1) v += __shfl_xor_sync(0xffffffffu, v, o);
    return v;
}
__device__ __forceinline__ float warp_max(float v) {
#pragma unroll
    for (int o = 16; o; o >>= 1) v = fmaxf(v, __shfl_xor_sync(0xffffffffu, v, o));
    return v;
}

// ============================================================================
// bounds + classify + PMA-Q precompute
// ============================================================================
__global__ void seg_bounds_kernel(const int* __restrict__ gene_idx, int E)
{
    int e = blockIdx.x * 256 + threadIdx.x;
    if (e == 0) { g_starts[GENES] = E; g_nsmall = 0; g_nmid = 0; g_longcount = 0; }
    if (e < E) {
        int gi = gene_idx[e];
        if (e == 0 || gene_idx[e - 1] != gi) g_starts[gi] = e;
    }
}

__global__ void classify_kernel()
{
    int g = blockIdx.x * 256 + threadIdx.x;
    if (g < GENES) {
        int len = g_starts[g + 1] - g_starts[g];
        if (len <= 16)      { int p = atomicAdd(&g_nsmall, 1);    g_smalllist[p] = g; }
        else if (len <= 32) { int p = atomicAdd(&g_nmid, 1);      g_midlist[p]   = g; }
        else                { int p = atomicAdd(&g_longcount, 1); g_longlist[p]  = g; }
    }
}

__global__ void prep_qpma_kernel(const float* __restrict__ Wq,
                                 const float* __restrict__ bq,
                                 const float* __restrict__ seed)
{
    int c = threadIdx.x;                       // 128 threads
    float acc = bq[2 * CC + c];
    const float* W2 = Wq + 2 * CC * CC;
#pragma unroll 8
    for (int k = 0; k < CC; k++) acc = fmaf(seed[k], W2[k * CC + c], acc);
    g_qpma[c] = acc;
}

// ============================================================================
// mm32s<NS>: X[NS*4 rows,128] @ W + b -> Y. 8 warps = 4 row-groups x 2 halves.
// ============================================================================
template <int NS, bool TRANS, bool RELU>
__device__ __forceinline__ void mm32s(const float* X, const float* __restrict__ W,
                                      const float* __restrict__ bias, float* Y,
                                      int w, int lane)
{
    int rg = w >> 1;
    int ch = w & 1;
    int c0 = ch * 64 + lane * 2;
    float acc[NS][2];
#pragma unroll
    for (int i = 0; i < NS; i++) { acc[i][0] = 0.f; acc[i][1] = 0.f; }

#pragma unroll 2
    for (int kk = 0; kk < CC; kk += 4) {
        float2 w0 = *(const float2*)(W + (kk + 0) * CC + c0);
        float2 w1 = *(const float2*)(W + (kk + 1) * CC + c0);
        float2 w2 = *(const float2*)(W + (kk + 2) * CC + c0);
        float2 w3 = *(const float2*)(W + (kk + 3) * CC + c0);
#pragma unroll
        for (int i = 0; i < NS; i++) {
            float4 xv = *(const float4*)(X + (rg + 4 * i) * SRW + kk);
            acc[i][0] = fmaf(xv.x, w0.x, acc[i][0]);
            acc[i][1] = fmaf(xv.x, w0.y, acc[i][1]);
            acc[i][0] = fmaf(xv.y, w1.x, acc[i][0]);
            acc[i][1] = fmaf(xv.y, w1.y, acc[i][1]);
            acc[i][0] = fmaf(xv.z, w2.x, acc[i][0]);
            acc[i][1] = fmaf(xv.z, w2.y, acc[i][1]);
            acc[i][0] = fmaf(xv.w, w3.x, acc[i][0]);
            acc[i][1] = fmaf(xv.w, w3.y, acc[i][1]);
        }
    }
    float2 bv = *(const float2*)(bias + c0);
#pragma unroll
    for (int i = 0; i < NS; i++) {
        int r = rg + 4 * i;
        float o0 = acc[i][0] + bv.x, o1 = acc[i][1] + bv.y;
        if (RELU) { o0 = fmaxf(o0, 0.f); o1 = fmaxf(o1, 0.f); }
        if (!TRANS) {
            *(float2*)(Y + r * SRW + c0) = make_float2(o0, o1);
        } else {
            Y[(c0 + 0) * SKT32 + r] = o0;
            Y[(c0 + 1) * SKT32 + r] = o1;
        }
    }
}

// ============================================================================
// mm64row: row-split matmul for the long (64-row) kernel
// ============================================================================
template <bool TRANS, bool RELU>
__device__ void mm64row(const float* X, const float* __restrict__ W,
                        const float* __restrict__ bias, float* Y,
                        int rows, int w, int lane)
{
    int nr = (rows > w) ? (((rows - 1 - w) >> 3) + 1) : 0;
    if (nr == 0) return;
    int c0 = lane * 4;
    float acc[8][4];
#pragma unroll
    for (int i = 0; i < 8; i++) { acc[i][0]=0.f; acc[i][1]=0.f; acc[i][2]=0.f; acc[i][3]=0.f; }

#pragma unroll 2
    for (int kk = 0; kk < CC; kk += 4) {
        float4 w0 = *(const float4*)(W + (kk + 0) * CC + c0);
        float4 w1 = *(const float4*)(W + (kk + 1) * CC + c0);
        float4 w2 = *(const float4*)(W + (kk + 2) * CC + c0);
        float4 w3 = *(const float4*)(W + (kk + 3) * CC + c0);
#pragma unroll
        for (int i = 0; i < 8; i++) {
            if (i < nr) {
                float4 xv = *(const float4*)(X + (w + 8 * i) * SR64 + kk);
                acc[i][0]=fmaf(xv.x,w0.x,acc[i][0]); acc[i][1]=fmaf(xv.x,w0.y,acc[i][1]);
                acc[i][2]=fmaf(xv.x,w0.z,acc[i][2]); acc[i][3]=fmaf(xv.x,w0.w,acc[i][3]);
                acc[i][0]=fmaf(xv.y,w1.x,acc[i][0]); acc[i][1]=fmaf(xv.y,w1.y,acc[i][1]);
                acc[i][2]=fmaf(xv.y,w1.z,acc[i][2]); acc[i][3]=fmaf(xv.y,w1.w,acc[i][3]);
                acc[i][0]=fmaf(xv.z,w2.x,acc[i][0]); acc[i][1]=fmaf(xv.z,w2.y,acc[i][1]);
                acc[i][2]=fmaf(xv.z,w2.z,acc[i][2]); acc[i][3]=fmaf(xv.z,w2.w,acc[i][3]);
                acc[i][0]=fmaf(xv.w,w3.x,acc[i][0]); acc[i][1]=fmaf(xv.w,w3.y,acc[i][1]);
                acc[i][2]=fmaf(xv.w,w3.z,acc[i][2]); acc[i][3]=fmaf(xv.w,w3.w,acc[i][3]);
            }
        }
    }
    float4 bv = *(const float4*)(bias + c0);
#pragma unroll
    for (int i = 0; i < 8; i++) {
        if (i < nr) {
            int r = w + 8 * i;
            float o0=acc[i][0]+bv.x, o1=acc[i][1]+bv.y, o2=acc[i][2]+bv.z, o3=acc[i][3]+bv.w;
            if (RELU) { o0=fmaxf(o0,0.f); o1=fmaxf(o1,0.f); o2=fmaxf(o2,0.f); o3=fmaxf(o3,0.f); }
            if (!TRANS) {
                *(float4*)(Y + r * SR64 + c0) = make_float4(o0, o1, o2, o3);
            } else {
                Y[(c0+0)*SKT64 + r]=o0; Y[(c0+1)*SKT64 + r]=o1;
                Y[(c0+2)*SKT64 + r]=o2; Y[(c0+3)*SKT64 + r]=o3;
            }
        }
    }
}

// ============================================================================
// paired encoder attention over KVR rows: row r window = A:[0,lenA) or B:[offB,offB+lenB)
// ============================================================================
template <int KVR>
__device__ __forceinline__ void attn_pair(float* QO, const float* Kt, const float* V,
                                          int offB, int lenA, int lenB, int w, int lane)
{
    const float scale = 0.17677669529663687f;
    for (int t = w; t < KVR * 4; t += 8) {
        int r = t >> 2, base = (t & 3) * 32;
        float s = 0.f;
#pragma unroll
        for (int d = 0; d < 32; d++)
            s = fmaf(QO[r * SRW + base + d], Kt[(base + d) * SKT32 + lane], s);
        int lo = (r >= offB) ? offB : 0;
        int ln = (r >= offB) ? lenB : lenA;
        s = ((unsigned)(lane - lo) < (unsigned)ln) ? s * scale : -1e30f;
        float m = warp_max(s);
        float p = __expf(s - m);
        float inv = 1.f / warp_sum(p);
        float a = p * inv;
        float acc = 0.f;
#pragma unroll
        for (int k = 0; k < KVR; k++)
            acc = fmaf(__shfl_sync(0xffffffffu, a, k), V[k * SRW + base + lane], acc);
        QO[r * SRW + base + lane] = acc;
    }
}

// paired PMA attention: warps 0-3 gene A heads, 4-7 gene B heads; Q = shared row
template <int KVR>
__device__ __forceinline__ void attn_pma_pair(const float* Q, const float* Kt, const float* V,
                                              int gA, int gB, int offB, int lenA, int lenB,
                                              int w, int lane)
{
    const float scale = 0.17677669529663687f;
    int gi   = w >> 2;                  // 0 = gene A, 1 = gene B
    int base = (w & 3) * 32;
    float s = 0.f;
#pragma unroll
    for (int d = 0; d < 32; d++)
        s = fmaf(Q[base + d], Kt[(base + d) * SKT32 + lane], s);
    int lo = gi ? offB : 0;
    int ln = gi ? lenB : lenA;
    s = ((unsigned)(lane - lo) < (unsigned)ln) ? s * scale : -1e30f;
    float m = warp_max(s);
    float p = __expf(s - m);
    float inv = 1.f / warp_sum(p);
    float a = p * inv;
    float acc = 0.f;
#pragma unroll
    for (int k = 0; k < KVR; k++)
        acc = fmaf(__shfl_sync(0xffffffffu, a, k), V[k * SRW + base + lane], acc);
    int gout = gi ? gB : gA;
    if (gout >= 0) g_pma[(size_t)gout * CC + base + lane] = acc;
}

// attention (kv <= 64) for the long kernel
__device__ void attn64(const float* Q, const float* Kt, const float* V,
                       float* outp, int outStride,
                       int Lq, int len, int kvr, int w, int lane)
{
    const float scale = 0.17677669529663687f;
    int ntask = Lq * 4;
    for (int t = w; t < ntask; t += 8) {
        int r = t >> 2, base = (t & 3) * 32;
        float s0 = 0.f, s1 = 0.f;
#pragma unroll
        for (int d = 0; d < 32; d++) {
            float qd = Q[r * SR64 + base + d];
            s0 = fmaf(qd, Kt[(base + d) * SKT64 + lane], s0);
            s1 = fmaf(qd, Kt[(base + d) * SKT64 + lane + 32], s1);
        }
        s0 = (lane < len)      ? s0 * scale : -1e30f;
        s1 = (lane + 32 < len) ? s1 * scale : -1e30f;
        float m = warp_max(fmaxf(s0, s1));
        float p0 = __expf(s0 - m), p1 = __expf(s1 - m);
        float inv = 1.f / warp_sum(p0 + p1);
        float a0 = p0 * inv, a1 = p1 * inv;
        float acc = 0.f;
        int k0 = kvr < 32 ? kvr : 32;
        for (int k = 0; k < k0; k++)
            acc = fmaf(__shfl_sync(0xffffffffu, a0, k), V[k * SR64 + base + lane], acc);
        for (int k = 32; k < kvr; k++)
            acc = fmaf(__shfl_sync(0xffffffffu, a1, k - 32), V[k * SR64 + base + lane], acc);
        outp[r * outStride + base + lane] = acc;
    }
}

// ============================================================================
// LN(residual + masked A). resStride==0 -> broadcast residual.
// ============================================================================
template <int SROW>
__device__ void lnres(const float* A, const float* Res, int resStride, float* Out,
                      int rows, int qmasklen,
                      const float* __restrict__ g, const float* __restrict__ b,
                      int w, int lane)
{
    for (int r = w; r < rows; r += 8) {
        float4 a = (r < qmasklen) ? *(const float4*)(A + r * SROW + lane * 4)
                                  : make_float4(0.f, 0.f, 0.f, 0.f);
        float4 s = *(const float4*)(Res + r * resStride + lane * 4);
        float t0 = a.x + s.x, t1 = a.y + s.y, t2 = a.z + s.z, t3 = a.w + s.w;
        float sum = warp_sum(t0 + t1 + t2 + t3);
        float sq  = warp_sum(t0*t0 + t1*t1 + t2*t2 + t3*t3);
        float mean = sum * (1.f / 128.f);
        float var  = sq * (1.f / 128.f) - mean * mean;
        float rstd = rsqrtf(var + 1e-5f);
        float4 gv = *(const float4*)(g + lane * 4);
        float4 bv = *(const float4*)(b + lane * 4);
        float4 o;
        o.x = (t0 - mean) * rstd * gv.x + bv.x;
        o.y = (t1 - mean) * rstd * gv.y + bv.y;
        o.z = (t2 - mean) * rstd * gv.z + bv.z;
        o.w = (t3 - mean) * rstd * gv.w + bv.w;
        *(float4*)(Out + r * SROW + lane * 4) = o;
    }
}

// paired version: row valid if local index (relative to its gene window) < len
__device__ void lnres_pair(const float* A, const float* Res, float* Out,
                           int rows, int offB, int lenA, int lenB,
                           const float* __restrict__ g, const float* __restrict__ b,
                           int w, int lane)
{
    for (int r = w; r < rows; r += 8) {
        int lo = (r >= offB) ? offB : 0;
        int ln = (r >= offB) ? lenB : lenA;
        float4 a = ((r - lo) < ln) ? *(const float4*)(A + r * SRW + lane * 4)
                                   : make_float4(0.f, 0.f, 0.f, 0.f);
        float4 s = *(const float4*)(Res + r * SRW + lane * 4);
        float t0 = a.x + s.x, t1 = a.y + s.y, t2 = a.z + s.z, t3 = a.w + s.w;
        float sum = warp_sum(t0 + t1 + t2 + t3);
        float sq  = warp_sum(t0*t0 + t1*t1 + t2*t2 + t3*t3);
        float mean = sum * (1.f / 128.f);
        float var  = sq * (1.f / 128.f) - mean * mean;
        float rstd = rsqrtf(var + 1e-5f);
        float4 gv = *(const float4*)(g + lane * 4);
        float4 bv = *(const float4*)(b + lane * 4);
        float4 o;
        o.x = (t0 - mean) * rstd * gv.x + bv.x;
        o.y = (t1 - mean) * rstd * gv.y + bv.y;
        o.z = (t2 - mean) * rstd * gv.z + bv.z;
        o.w = (t3 - mean) * rstd * gv.w + bv.w;
        *(float4*)(Out + r * SRW + lane * 4) = o;
    }
}

// ============================================================================
// unified encoder(x2) + PMA attention for 1 or 2 genes in NS*4 rows
// ============================================================================
template <int NS>
__device__ __forceinline__ void enc_pair(
    float* Sst, float* SA, float* SB, float* SC,
    const float* __restrict__ Wq, const float* __restrict__ Wk,
    const float* __restrict__ Wv, const float* __restrict__ Wo,
    const float* __restrict__ bq, const float* __restrict__ bk,
    const float* __restrict__ bv, const float* __restrict__ bo,
    const float* __restrict__ Wlin, const float* __restrict__ blin,
    const float* __restrict__ g1, const float* __restrict__ b1,
    const float* __restrict__ g2, const float* __restrict__ b2,
    int gA, int gB, int offB, int lenA, int lenB,
    int w, int lane, int tid)
{
    constexpr int ROWS = NS * 4;
#pragma unroll 1
    for (int blk = 0; blk < 2; blk++) {
        const float* wq = Wq + blk * CC * CC;  const float* wk = Wk + blk * CC * CC;
        const float* wv = Wv + blk * CC * CC;  const float* wo = Wo + blk * CC * CC;
        const float* wl = Wlin + blk * CC * CC;
        mm32s<NS, false, false>(Sst, wq, bq + blk * CC, SA, w, lane);
        mm32s<NS, true,  false>(Sst, wk, bk + blk * CC, SB, w, lane);
        mm32s<NS, false, false>(Sst, wv, bv + blk * CC, SC, w, lane);
        __syncthreads();
        attn_pair<ROWS>(SA, SB, SC, offB, lenA, lenB, w, lane);
        __syncthreads();
        mm32s<NS, false, false>(SA, wo, bo + blk * CC, SB, w, lane);
        __syncthreads();
        lnres_pair(SB, Sst, Sst, ROWS, offB, lenA, lenB,
                   g1 + blk * CC, b1 + blk * CC, w, lane);
        __syncthreads();
        mm32s<NS, false, true>(Sst, wl, blin + blk * CC, SC, w, lane);
        __syncthreads();
        lnres<SRW>(SC, Sst, SRW, Sst, ROWS, ROWS, g2 + blk * CC, b2 + blk * CC, w, lane);
        __syncthreads();
    }
    if (tid < CC) SA[tid] = g_qpma[tid];
    mm32s<NS, true,  false>(Sst, Wk + 2 * CC * CC, bk + 2 * CC, SB, w, lane);
    mm32s<NS, false, false>(Sst, Wv + 2 * CC * CC, bv + 2 * CC, SC, w, lane);
    __syncthreads();
    attn_pma_pair<ROWS>(SA, SB, SC, gA, gB, offB, lenA, lenB, w, lane);
}

// ============================================================================
// PACKED kernel: mid singles + pairs of small genes, 4-row granularity
// ============================================================================
__global__ __launch_bounds__(256, 3)
void gene_packed(const float* __restrict__ rf,
                 const float* __restrict__ Wq, const float* __restrict__ Wk,
                 const float* __restrict__ Wv, const float* __restrict__ Wo,
                 const float* __restrict__ bq, const float* __restrict__ bk,
                 const float* __restrict__ bv, const float* __restrict__ bo,
                 const float* __restrict__ Wlin, const float* __restrict__ blin,
                 const float* __restrict__ g1, const float* __restrict__ b1,
                 const float* __restrict__ g2, const float* __restrict__ b2,
                 const int* __restrict__ rxn_idx)
{
    extern __shared__ float sm[];
    float* Sst = sm;                    // [<=32][SRW]
    float* SA  = sm + B32;
    float* SB  = SA + B32;              // K^T [128][SKT32]
    float* SC  = SB + KT32;

    int i    = blockIdx.x;
    int tid  = threadIdx.x;
    int w    = tid >> 5;
    int lane = tid & 31;

    int nmid = g_nmid;
    int gA, gB, sA, sB, lenA, lenB;

    if (i < nmid) {
        gA = g_midlist[i];
        sA = g_starts[gA];  lenA = g_starts[gA + 1] - sA;
        gB = -1; sB = 0; lenB = 0;
    } else {
        int j = i - nmid;
        int nsmall = g_nsmall;
        if (2 * j >= nsmall) return;
        gA = g_smalllist[2 * j];
        sA = g_starts[gA];  lenA = g_starts[gA + 1] - sA;
        if (2 * j + 1 < nsmall) {
            gB = g_smalllist[2 * j + 1];
            sB = g_starts[gB];  lenB = g_starts[gB + 1] - sB;
        } else { gB = -1; sB = 0; lenB = 0; }
    }

    int offB = (lenA + 3) & ~3;
    int lenr = offB + ((lenB + 3) & ~3);     // multiple of 4, <= 32
    int NS   = lenr >> 2;                    // 1..8

    // gather
    for (int r = w; r < lenr; r += 8) {
        bool isB  = r >= offB;
        int local = isB ? (r - offB) : r;
        int ln    = isB ? lenB : lenA;
        int st    = isB ? sB   : sA;
        if (local < ln) {
            int rx = rxn_idx[st + local];
            ((float4*)(Sst + r * SRW))[lane] = ((const float4*)(rf + (size_t)rx * CC))[lane];
        } else {
            ((float4*)(Sst + r * SRW))[lane] = make_float4(0.f, 0.f, 0.f, 0.f);
        }
    }
    __syncthreads();

#define CALL_ENC(NSV) enc_pair<NSV>(Sst, SA, SB, SC, Wq, Wk, Wv, Wo, bq, bk, bv, bo, \
                                    Wlin, blin, g1, b1, g2, b2, gA, gB, offB, lenA, lenB, w, lane, tid)
    switch (NS) {
    case 1: CALL_ENC(1); break;
    case 2: CALL_ENC(2); break;
    case 3: CALL_ENC(3); break;
    case 4: CALL_ENC(4); break;
    case 5: CALL_ENC(5); break;
    case 6: CALL_ENC(6); break;
    case 7: CALL_ENC(7); break;
    default: CALL_ENC(8); break;
    }
#undef CALL_ENC
}

// ============================================================================
// LONG kernel: genes with len > 32 (rare); ends after PMA attention
// ============================================================================
__global__ __launch_bounds__(256, 1)
void gene_long64(const float* __restrict__ rf,
                 const float* __restrict__ Wq, const float* __restrict__ Wk,
                 const float* __restrict__ Wv, const float* __restrict__ Wo,
                 const float* __restrict__ bq, const float* __restrict__ bk,
                 const float* __restrict__ bv, const float* __restrict__ bo,
                 const float* __restrict__ Wlin, const float* __restrict__ blin,
                 const float* __restrict__ g1, const float* __restrict__ b1,
                 const float* __restrict__ g2, const float* __restrict__ b2,
                 const int* __restrict__ rxn_idx)
{
    extern __shared__ float sm[];
    float* Sst = sm;                    // [64][SR64]
    float* SA  = sm + B64;
    float* SB  = SA + B64;
    float* SC  = SB + KT64;

    int tid  = threadIdx.x;
    int w    = tid >> 5;
    int lane = tid & 31;
    int nlong = g_longcount;

    for (int i = blockIdx.x; i < nlong; i += gridDim.x) {
        int g     = g_longlist[i];
        int start = g_starts[g];
        int cnt   = g_starts[g + 1] - start;
        int len   = cnt < 64 ? cnt : 64;
        int lenr  = (len + 7) & ~7;
        if (lenr > 64) lenr = 64;

        for (int r = w; r < lenr; r += 8) {
            if (r < len) {
                int rx = rxn_idx[start + r];
                ((float4*)(Sst + r * SR64))[lane] = ((const float4*)(rf + (size_t)rx * CC))[lane];
            } else {
                ((float4*)(Sst + r * SR64))[lane] = make_float4(0.f, 0.f, 0.f, 0.f);
            }
        }
        __syncthreads();

        for (int blk = 0; blk < 2; blk++) {
            const float* wq = Wq + blk * CC * CC;  const float* wk = Wk + blk * CC * CC;
            const float* wv = Wv + blk * CC * CC;  const float* wo = Wo + blk * CC * CC;
            const float* wl = Wlin + blk * CC * CC;
            mm64row<false, false>(Sst, wq, bq + blk * CC, SA, lenr, w, lane);
            mm64row<true,  false>(Sst, wk, bk + blk * CC, SB, lenr, w, lane);
            mm64row<false, false>(Sst, wv, bv + blk * CC, SC, lenr, w, lane);
            __syncthreads();
            attn64(SA, SB, SC, SA, SR64, lenr, len, lenr, w, lane);
            __syncthreads();
            mm64row<false, false>(SA, wo, bo + blk * CC, SB, lenr, w, lane);
            __syncthreads();
            lnres<SR64>(SB, Sst, SR64, Sst, lenr, len, g1 + blk * CC, b1 + blk * CC, w, lane);
            __syncthreads();
            mm64row<false, true>(Sst, wl, blin + blk * CC, SC, lenr, w, lane);
            __syncthreads();
            lnres<SR64>(SC, Sst, SR64, Sst, lenr, lenr, g2 + blk * CC, b2 + blk * CC, w, lane);
            __syncthreads();
        }
        if (tid < CC) SA[tid] = g_qpma[tid];
        mm64row<true,  false>(Sst, Wk + 2 * CC * CC, bk + 2 * CC, SB, lenr, w, lane);
        mm64row<false, false>(Sst, Wv + 2 * CC * CC, bv + 2 * CC, SC, lenr, w, lane);
        __syncthreads();
        attn64(SA, SB, SC, g_pma + (size_t)g * CC, CC, 1, len, lenr, w, lane);
        __syncthreads();
    }
}

// ============================================================================
// TAIL kernel: batched PMA-projection + decoder over 32 genes per CTA
// ============================================================================
__global__ __launch_bounds__(256)
void gene_tail(const float* __restrict__ Wv, const float* __restrict__ Wo,
               const float* __restrict__ bv, const float* __restrict__ bo,
               const float* __restrict__ Wlin, const float* __restrict__ blin,
               const float* __restrict__ g1, const float* __restrict__ b1,
               const float* __restrict__ g2, const float* __restrict__ b2,
               const float* __restrict__ seed,
               float* __restrict__ out)
{
    extern __shared__ float sm[];
    float* Sst = sm;                    // [32][SRW]
    float* SA  = sm + B32;
    float* SC  = SA + B32;

    int g0   = blockIdx.x * 32;
    int tid  = threadIdx.x;
    int w    = tid >> 5;
    int lane = tid & 31;

    for (int r = w; r < 32; r += 8)
        ((float4*)(Sst + r * SRW))[lane] = ((const float4*)(g_pma + (size_t)(g0 + r) * CC))[lane];
    __syncthreads();

    mm32s<8, false, false>(Sst, Wo + 2 * CC * CC, bo + 2 * CC, SA, w, lane);
    __syncthreads();
    lnres<SRW>(SA, seed, 0, Sst, 32, 32, g1 + 2 * CC, b1 + 2 * CC, w, lane);
    __syncthreads();
    mm32s<8, false, true>(Sst, Wlin + 2 * CC * CC, blin + 2 * CC, SC, w, lane);
    __syncthreads();
    lnres<SRW>(SC, Sst, SRW, Sst, 32, 32, g2 + 2 * CC, b2 + 2 * CC, w, lane);
    __syncthreads();

    mm32s<8, false, false>(Sst, Wv + 3 * CC * CC, bv + 3 * CC, SA, w, lane);
    __syncthreads();
    mm32s<8, false, false>(SA, Wo + 3 * CC * CC, bo + 3 * CC, SC, w, lane);
    __syncthreads();
    lnres<SRW>(SC, Sst, SRW, Sst, 32, 32, g1 + 3 * CC, b1 + 3 * CC, w, lane);
    __syncthreads();
    mm32s<8, false, true>(Sst, Wlin + 3 * CC * CC, blin + 3 * CC, SC, w, lane);
    __syncthreads();
    lnres<SRW>(SC, Sst, SRW, Sst, 32, 32, g2 + 3 * CC, b2 + 3 * CC, w, lane);
    __syncthreads();

    for (int r = w; r < 32; r += 8) {
        float4 v = ((const float4*)(Sst + r * SRW))[lane];
        float o[4] = {v.x, v.y, v.z, v.w};
#pragma unroll
        for (int j = 0; j < 4; j++) {
            float x = o[j];
            if (x != x) x = 0.f;
            x = fminf(fmaxf(x, -3.402823466e38f), 3.402823466e38f);
            o[j] = x;
        }
        ((float4*)(out + (size_t)(g0 + r) * CC))[lane] = make_float4(o[0], o[1], o[2], o[3]);
    }
}

extern "C" void kernel_launch(void* const* d_in, const int* in_sizes, int n_in,
                              void* d_out, int out_size)
{
    const float* rf   = (const float*)d_in[0];
    const float* Wq   = (const float*)d_in[1];
    const float* Wk   = (const float*)d_in[2];
    const float* Wv   = (const float*)d_in[3];
    const float* Wo   = (const float*)d_in[4];
    const float* bq   = (const float*)d_in[5];
    const float* bk   = (const float*)d_in[6];
    const float* bv   = (const float*)d_in[7];
    const float* bo   = (const float*)d_in[8];
    const float* Wlin = (const float*)d_in[9];
    const float* blin = (const float*)d_in[10];
    const float* g1   = (const float*)d_in[11];
    const float* b1   = (const float*)d_in[12];
    const float* g2   = (const float*)d_in[13];
    const float* b2   = (const float*)d_in[14];
    const float* seed = (const float*)d_in[15];
    const int*   rxn  = (const int*)d_in[16];
    const int*   gidx = (const int*)d_in[17];
    int E = in_sizes[16];

    cudaFuncSetAttribute(gene_packed, cudaFuncAttributeMaxDynamicSharedMemorySize, SM32_BYTES);
    cudaFuncSetAttribute(gene_long64, cudaFuncAttributeMaxDynamicSharedMemorySize, SM64_BYTES);
    cudaFuncSetAttribute(gene_tail,   cudaFuncAttributeMaxDynamicSharedMemorySize, SMT_BYTES);

    seg_bounds_kernel<<<(E + 255) / 256, 256>>>(gidx, E);
    classify_kernel<<<(GENES + 255) / 256, 256>>>();
    prep_qpma_kernel<<<1, 128>>>(Wq, bq, seed);
    gene_packed<<<GENES, 256, SM32_BYTES>>>(rf, Wq, Wk, Wv, Wo, bq, bk, bv, bo,
                                            Wlin, blin, g1, b1, g2, b2, rxn);
    gene_long64<<<128, 256, SM64_BYTES>>>(rf, Wq, Wk, Wv, Wo, bq, bk, bv, bo,
                                          Wlin, blin, g1, b1, g2, b2, rxn);
    gene_tail<<<GENES / 32, 256, SMT_BYTES>>>(Wv, Wo, bv, bo, Wlin, blin,
                                              g1, b1, g2, b2, seed, (float*)d_out);
}

// round 12
// speedup vs baseline: 1.2459x; 1.0748x over previous
#include <cuda_runtime.h>
#include <math.h>

#define CC    128
#define GENES 4096
#define SRW   132                 // row stride (floats)

// ---- 32-row packed kernel geometry ----
#define SKT32 33
#define B32   (32 * SRW)          // 4224 floats
#define KT32  (128 * SKT32)       // 4224 floats
#define SM32_BYTES ((3 * B32 + KT32) * 4)   // 67,584 B -> 3 CTAs/SM

// ---- long (len>32) kernel geometry ----
#define SR64  136
#define SKT64 69
#define B64   (64 * SR64)
#define KT64  (128 * SKT64)
#define SM64_BYTES ((3 * B64 + KT64) * 4)

// ---- tail kernel ----
#define SMT_BYTES (3 * B32 * 4)

__device__ int   g_starts[GENES + 1];
__device__ int   g_nsmall, g_nmid, g_longcount;
__device__ int   g_smalllist[GENES];
__device__ int   g_midlist[GENES];
__device__ int   g_longlist[GENES];
__device__ float g_qpma[CC];              // seed @ Wq[2] + bq[2]
__device__ float g_pma[GENES * CC];       // PMA attention output per gene

__device__ __forceinline__ float warp_sum(float v) {
#pragma unroll
    for (int o = 16; o; o >>= 1) v += __shfl_xor_sync(0xffffffffu, v, o);
    return v;
}
__device__ __forceinline__ float warp_max(float v) {
#pragma unroll
    for (int o = 16; o; o >>= 1) v = fmaxf(v, __shfl_xor_sync(0xffffffffu, v, o));
    return v;
}

// ============================================================================
// bounds + classify + PMA-Q precompute
// ============================================================================
__global__ void seg_bounds_kernel(const int* __restrict__ gene_idx, int E)
{
    int e = blockIdx.x * 256 + threadIdx.x;
    if (e == 0) { g_starts[GENES] = E; g_nsmall = 0; g_nmid = 0; g_longcount = 0; }
    if (e < E) {
        int gi = gene_idx[e];
        if (e == 0 || gene_idx[e - 1] != gi) g_starts[gi] = e;
    }
}

__global__ void classify_kernel()
{
    int g = blockIdx.x * 256 + threadIdx.x;
    if (g < GENES) {
        int len = g_starts[g + 1] - g_starts[g];
        if (len <= 16)      { int p = atomicAdd(&g_nsmall, 1);    g_smalllist[p] = g; }
        else if (len <= 32) { int p = atomicAdd(&g_nmid, 1);      g_midlist[p]   = g; }
        else                { int p = atomicAdd(&g_longcount, 1); g_longlist[p]  = g; }
    }
}

__global__ void prep_qpma_kernel(const float* __restrict__ Wq,
                                 const float* __restrict__ bq,
                                 const float* __restrict__ seed)
{
    int c = threadIdx.x;                       // 128 threads
    float acc = bq[2 * CC + c];
    const float* W2 = Wq + 2 * CC * CC;
#pragma unroll 8
    for (int k = 0; k < CC; k++) acc = fmaf(seed[k], W2[k * CC + c], acc);
    g_qpma[c] = acc;
}

// ============================================================================
// mm32s<NS>: X[NS*4 rows,128] @ W + b -> Y. 8 warps = 4 row-groups x 2 halves.
// ============================================================================
template <int NS, bool TRANS, bool RELU>
__device__ __forceinline__ void mm32s(const float* X, const float* __restrict__ W,
                                      const float* __restrict__ bias, float* Y,
                                      int w, int lane)
{
    int rg = w >> 1;
    int ch = w & 1;
    int c0 = ch * 64 + lane * 2;
    float acc[NS][2];
#pragma unroll
    for (int i = 0; i < NS; i++) { acc[i][0] = 0.f; acc[i][1] = 0.f; }

#pragma unroll 2
    for (int kk = 0; kk < CC; kk += 4) {
        float2 w0 = *(const float2*)(W + (kk + 0) * CC + c0);
        float2 w1 = *(const float2*)(W + (kk + 1) * CC + c0);
        float2 w2 = *(const float2*)(W + (kk + 2) * CC + c0);
        float2 w3 = *(const float2*)(W + (kk + 3) * CC + c0);
#pragma unroll
        for (int i = 0; i < NS; i++) {
            float4 xv = *(const float4*)(X + (rg + 4 * i) * SRW + kk);
            acc[i][0] = fmaf(xv.x, w0.x, acc[i][0]);
            acc[i][1] = fmaf(xv.x, w0.y, acc[i][1]);
            acc[i][0] = fmaf(xv.y, w1.x, acc[i][0]);
            acc[i][1] = fmaf(xv.y, w1.y, acc[i][1]);
            acc[i][0] = fmaf(xv.z, w2.x, acc[i][0]);
            acc[i][1] = fmaf(xv.z, w2.y, acc[i][1]);
            acc[i][0] = fmaf(xv.w, w3.x, acc[i][0]);
            acc[i][1] = fmaf(xv.w, w3.y, acc[i][1]);
        }
    }
    float2 bv = *(const float2*)(bias + c0);
#pragma unroll
    for (int i = 0; i < NS; i++) {
        int r = rg + 4 * i;
        float o0 = acc[i][0] + bv.x, o1 = acc[i][1] + bv.y;
        if (RELU) { o0 = fmaxf(o0, 0.f); o1 = fmaxf(o1, 0.f); }
        if (!TRANS) {
            *(float2*)(Y + r * SRW + c0) = make_float2(o0, o1);
        } else {
            Y[(c0 + 0) * SKT32 + r] = o0;
            Y[(c0 + 1) * SKT32 + r] = o1;
        }
    }
}

// ============================================================================
// mm64row: row-split matmul for the long (64-row) kernel
// ============================================================================
template <bool TRANS, bool RELU>
__device__ void mm64row(const float* X, const float* __restrict__ W,
                        const float* __restrict__ bias, float* Y,
                        int rows, int w, int lane)
{
    int nr = (rows > w) ? (((rows - 1 - w) >> 3) + 1) : 0;
    if (nr == 0) return;
    int c0 = lane * 4;
    float acc[8][4];
#pragma unroll
    for (int i = 0; i < 8; i++) { acc[i][0]=0.f; acc[i][1]=0.f; acc[i][2]=0.f; acc[i][3]=0.f; }

#pragma unroll 2
    for (int kk = 0; kk < CC; kk += 4) {
        float4 w0 = *(const float4*)(W + (kk + 0) * CC + c0);
        float4 w1 = *(const float4*)(W + (kk + 1) * CC + c0);
        float4 w2 = *(const float4*)(W + (kk + 2) * CC + c0);
        float4 w3 = *(const float4*)(W + (kk + 3) * CC + c0);
#pragma unroll
        for (int i = 0; i < 8; i++) {
            if (i < nr) {
                float4 xv = *(const float4*)(X + (w + 8 * i) * SR64 + kk);
                acc[i][0]=fmaf(xv.x,w0.x,acc[i][0]); acc[i][1]=fmaf(xv.x,w0.y,acc[i][1]);
                acc[i][2]=fmaf(xv.x,w0.z,acc[i][2]); acc[i][3]=fmaf(xv.x,w0.w,acc[i][3]);
                acc[i][0]=fmaf(xv.y,w1.x,acc[i][0]); acc[i][1]=fmaf(xv.y,w1.y,acc[i][1]);
                acc[i][2]=fmaf(xv.y,w1.z,acc[i][2]); acc[i][3]=fmaf(xv.y,w1.w,acc[i][3]);
                acc[i][0]=fmaf(xv.z,w2.x,acc[i][0]); acc[i][1]=fmaf(xv.z,w2.y,acc[i][1]);
                acc[i][2]=fmaf(xv.z,w2.z,acc[i][2]); acc[i][3]=fmaf(xv.z,w2.w,acc[i][3]);
                acc[i][0]=fmaf(xv.w,w3.x,acc[i][0]); acc[i][1]=fmaf(xv.w,w3.y,acc[i][1]);
                acc[i][2]=fmaf(xv.w,w3.z,acc[i][2]); acc[i][3]=fmaf(xv.w,w3.w,acc[i][3]);
            }
        }
    }
    float4 bv = *(const float4*)(bias + c0);
#pragma unroll
    for (int i = 0; i < 8; i++) {
        if (i < nr) {
            int r = w + 8 * i;
            float o0=acc[i][0]+bv.x, o1=acc[i][1]+bv.y, o2=acc[i][2]+bv.z, o3=acc[i][3]+bv.w;
            if (RELU) { o0=fmaxf(o0,0.f); o1=fmaxf(o1,0.f); o2=fmaxf(o2,0.f); o3=fmaxf(o3,0.f); }
            if (!TRANS) {
                *(float4*)(Y + r * SR64 + c0) = make_float4(o0, o1, o2, o3);
            } else {
                Y[(c0+0)*SKT64 + r]=o0; Y[(c0+1)*SKT64 + r]=o1;
                Y[(c0+2)*SKT64 + r]=o2; Y[(c0+3)*SKT64 + r]=o3;
            }
        }
    }
}

// ============================================================================
// paired encoder attention, 4 query rows per task: task = (rowgroup, head).
// Kt and V loads shared across the 4 rows (4x fewer L1 wavefronts).
// Rowgroups are 4-aligned; offB is a multiple of 4 -> uniform window per task.
// ============================================================================
template <int KVR>
__device__ __forceinline__ void attn_pair(float* QO, const float* Kt, const float* V,
                                          int offB, int lenA, int lenB, int w, int lane)
{
    const float scale = 0.17677669529663687f;
    // tasks: KVR = (KVR/4 rowgroups) x 4 heads
    for (int t = w; t < KVR; t += 8) {
        int r0   = (t >> 2) * 4;
        int base = (t & 3) * 32;
        float s0 = 0.f, s1 = 0.f, s2 = 0.f, s3 = 0.f;
#pragma unroll
        for (int d = 0; d < 32; d += 4) {
            float k0 = Kt[(base + d + 0) * SKT32 + lane];
            float k1 = Kt[(base + d + 1) * SKT32 + lane];
            float k2 = Kt[(base + d + 2) * SKT32 + lane];
            float k3 = Kt[(base + d + 3) * SKT32 + lane];
            float4 qa = *(const float4*)(QO + (r0 + 0) * SRW + base + d);
            float4 qb = *(const float4*)(QO + (r0 + 1) * SRW + base + d);
            float4 qc = *(const float4*)(QO + (r0 + 2) * SRW + base + d);
            float4 qd = *(const float4*)(QO + (r0 + 3) * SRW + base + d);
            s0 = fmaf(qa.x,k0,fmaf(qa.y,k1,fmaf(qa.z,k2,fmaf(qa.w,k3,s0))));
            s1 = fmaf(qb.x,k0,fmaf(qb.y,k1,fmaf(qb.z,k2,fmaf(qb.w,k3,s1))));
            s2 = fmaf(qc.x,k0,fmaf(qc.y,k1,fmaf(qc.z,k2,fmaf(qc.w,k3,s2))));
            s3 = fmaf(qd.x,k0,fmaf(qd.y,k1,fmaf(qd.z,k2,fmaf(qd.w,k3,s3))));
        }
        int lo = (r0 >= offB) ? offB : 0;
        int ln = (r0 >= offB) ? lenB : lenA;
        bool valid = ((unsigned)(lane - lo) < (unsigned)ln);
        s0 = valid ? s0 * scale : -1e30f;
        s1 = valid ? s1 * scale : -1e30f;
        s2 = valid ? s2 * scale : -1e30f;
        s3 = valid ? s3 * scale : -1e30f;
        float a0, a1, a2, a3;
        { float m = warp_max(s0); float p = __expf(s0 - m); a0 = p * (1.f / warp_sum(p)); }
        { float m = warp_max(s1); float p = __expf(s1 - m); a1 = p * (1.f / warp_sum(p)); }
        { float m = warp_max(s2); float p = __expf(s2 - m); a2 = p * (1.f / warp_sum(p)); }
        { float m = warp_max(s3); float p = __expf(s3 - m); a3 = p * (1.f / warp_sum(p)); }

        float o0 = 0.f, o1 = 0.f, o2 = 0.f, o3 = 0.f;
#pragma unroll
        for (int k = 0; k < KVR; k++) {
            float v = V[k * SRW + base + lane];
            o0 = fmaf(__shfl_sync(0xffffffffu, a0, k), v, o0);
            o1 = fmaf(__shfl_sync(0xffffffffu, a1, k), v, o1);
            o2 = fmaf(__shfl_sync(0xffffffffu, a2, k), v, o2);
            o3 = fmaf(__shfl_sync(0xffffffffu, a3, k), v, o3);
        }
        QO[(r0 + 0) * SRW + base + lane] = o0;
        QO[(r0 + 1) * SRW + base + lane] = o1;
        QO[(r0 + 2) * SRW + base + lane] = o2;
        QO[(r0 + 3) * SRW + base + lane] = o3;
    }
}

// paired PMA attention: warps 0-3 gene A heads, 4-7 gene B heads; Q = shared row
template <int KVR>
__device__ __forceinline__ void attn_pma_pair(const float* Q, const float* Kt, const float* V,
                                              int gA, int gB, int offB, int lenA, int lenB,
                                              int w, int lane)
{
    const float scale = 0.17677669529663687f;
    int gi   = w >> 2;                  // 0 = gene A, 1 = gene B
    int base = (w & 3) * 32;
    float s = 0.f;
#pragma unroll
    for (int d = 0; d < 32; d += 4) {
        float4 q = *(const float4*)(Q + base + d);
        s = fmaf(q.x, Kt[(base + d + 0) * SKT32 + lane],
            fmaf(q.y, Kt[(base + d + 1) * SKT32 + lane],
            fmaf(q.z, Kt[(base + d + 2) * SKT32 + lane],
            fmaf(q.w, Kt[(base + d + 3) * SKT32 + lane], s))));
    }
    int lo = gi ? offB : 0;
    int ln = gi ? lenB : lenA;
    s = ((unsigned)(lane - lo) < (unsigned)ln) ? s * scale : -1e30f;
    float m = warp_max(s);
    float p = __expf(s - m);
    float a = p * (1.f / warp_sum(p));
    float acc = 0.f;
#pragma unroll
    for (int k = 0; k < KVR; k++)
        acc = fmaf(__shfl_sync(0xffffffffu, a, k), V[k * SRW + base + lane], acc);
    int gout = gi ? gB : gA;
    if (gout >= 0) g_pma[(size_t)gout * CC + base + lane] = acc;
}

// attention (kv <= 64) for the long kernel
__device__ void attn64(const float* Q, const float* Kt, const float* V,
                       float* outp, int outStride,
                       int Lq, int len, int kvr, int w, int lane)
{
    const float scale = 0.17677669529663687f;
    int ntask = Lq * 4;
    for (int t = w; t < ntask; t += 8) {
        int r = t >> 2, base = (t & 3) * 32;
        float s0 = 0.f, s1 = 0.f;
#pragma unroll
        for (int d = 0; d < 32; d++) {
            float qd = Q[r * SR64 + base + d];
            s0 = fmaf(qd, Kt[(base + d) * SKT64 + lane], s0);
            s1 = fmaf(qd, Kt[(base + d) * SKT64 + lane + 32], s1);
        }
        s0 = (lane < len)      ? s0 * scale : -1e30f;
        s1 = (lane + 32 < len) ? s1 * scale : -1e30f;
        float m = warp_max(fmaxf(s0, s1));
        float p0 = __expf(s0 - m), p1 = __expf(s1 - m);
        float inv = 1.f / warp_sum(p0 + p1);
        float a0 = p0 * inv, a1 = p1 * inv;
        float acc = 0.f;
        int k0 = kvr < 32 ? kvr : 32;
        for (int k = 0; k < k0; k++)
            acc = fmaf(__shfl_sync(0xffffffffu, a0, k), V[k * SR64 + base + lane], acc);
        for (int k = 32; k < kvr; k++)
            acc = fmaf(__shfl_sync(0xffffffffu, a1, k - 32), V[k * SR64 + base + lane], acc);
        outp[r * outStride + base + lane] = acc;
    }
}

// ============================================================================
// LN(residual + masked A). resStride==0 -> broadcast residual.
// ============================================================================
template <int SROW>
__device__ void lnres(const float* A, const float* Res, int resStride, float* Out,
                      int rows, int qmasklen,
                      const float* __restrict__ g, const float* __restrict__ b,
                      int w, int lane)
{
    for (int r = w; r < rows; r += 8) {
        float4 a = (r < qmasklen) ? *(const float4*)(A + r * SROW + lane * 4)
                                  : make_float4(0.f, 0.f, 0.f, 0.f);
        float4 s = *(const float4*)(Res + r * resStride + lane * 4);
        float t0 = a.x + s.x, t1 = a.y + s.y, t2 = a.z + s.z, t3 = a.w + s.w;
        float sum = warp_sum(t0 + t1 + t2 + t3);
        float sq  = warp_sum(t0*t0 + t1*t1 + t2*t2 + t3*t3);
        float mean = sum * (1.f / 128.f);
        float var  = sq * (1.f / 128.f) - mean * mean;
        float rstd = rsqrtf(var + 1e-5f);
        float4 gv = *(const float4*)(g + lane * 4);
        float4 bv = *(const float4*)(b + lane * 4);
        float4 o;
        o.x = (t0 - mean) * rstd * gv.x + bv.x;
        o.y = (t1 - mean) * rstd * gv.y + bv.y;
        o.z = (t2 - mean) * rstd * gv.z + bv.z;
        o.w = (t3 - mean) * rstd * gv.w + bv.w;
        *(float4*)(Out + r * SROW + lane * 4) = o;
    }
}

// paired version: row valid if local index (relative to its gene window) < len
__device__ void lnres_pair(const float* A, const float* Res, float* Out,
                           int rows, int offB, int lenA, int lenB,
                           const float* __restrict__ g, const float* __restrict__ b,
                           int w, int lane)
{
    for (int r = w; r < rows; r += 8) {
        int lo = (r >= offB) ? offB : 0;
        int ln = (r >= offB) ? lenB : lenA;
        float4 a = ((r - lo) < ln) ? *(const float4*)(A + r * SRW + lane * 4)
                                   : make_float4(0.f, 0.f, 0.f, 0.f);
        float4 s = *(const float4*)(Res + r * SRW + lane * 4);
        float t0 = a.x + s.x, t1 = a.y + s.y, t2 = a.z + s.z, t3 = a.w + s.w;
        float sum = warp_sum(t0 + t1 + t2 + t3);
        float sq  = warp_sum(t0*t0 + t1*t1 + t2*t2 + t3*t3);
        float mean = sum * (1.f / 128.f);
        float var  = sq * (1.f / 128.f) - mean * mean;
        float rstd = rsqrtf(var + 1e-5f);
        float4 gv = *(const float4*)(g + lane * 4);
        float4 bv = *(const float4*)(b + lane * 4);
        float4 o;
        o.x = (t0 - mean) * rstd * gv.x + bv.x;
        o.y = (t1 - mean) * rstd * gv.y + bv.y;
        o.z = (t2 - mean) * rstd * gv.z + bv.z;
        o.w = (t3 - mean) * rstd * gv.w + bv.w;
        *(float4*)(Out + r * SRW + lane * 4) = o;
    }
}

// ============================================================================
// unified encoder(x2) + PMA attention for 1 or 2 genes in NS*4 rows
// ============================================================================
template <int NS>
__device__ __forceinline__ void enc_pair(
    float* Sst, float* SA, float* SB, float* SC,
    const float* __restrict__ Wq, const float* __restrict__ Wk,
    const float* __restrict__ Wv, const float* __restrict__ Wo,
    const float* __restrict__ bq, const float* __restrict__ bk,
    const float* __restrict__ bv, const float* __restrict__ bo,
    const float* __restrict__ Wlin, const float* __restrict__ blin,
    const float* __restrict__ g1, const float* __restrict__ b1,
    const float* __restrict__ g2, const float* __restrict__ b2,
    int gA, int gB, int offB, int lenA, int lenB,
    int w, int lane, int tid)
{
    constexpr int ROWS = NS * 4;
#pragma unroll 1
    for (int blk = 0; blk < 2; blk++) {
        const float* wq = Wq + blk * CC * CC;  const float* wk = Wk + blk * CC * CC;
        const float* wv = Wv + blk * CC * CC;  const float* wo = Wo + blk * CC * CC;
        const float* wl = Wlin + blk * CC * CC;
        mm32s<NS, false, false>(Sst, wq, bq + blk * CC, SA, w, lane);
        mm32s<NS, true,  false>(Sst, wk, bk + blk * CC, SB, w, lane);
        mm32s<NS, false, false>(Sst, wv, bv + blk * CC, SC, w, lane);
        __syncthreads();
        attn_pair<ROWS>(SA, SB, SC, offB, lenA, lenB, w, lane);
        __syncthreads();
        mm32s<NS, false, false>(SA, wo, bo + blk * CC, SB, w, lane);
        __syncthreads();
        lnres_pair(SB, Sst, Sst, ROWS, offB, lenA, lenB,
                   g1 + blk * CC, b1 + blk * CC, w, lane);
        __syncthreads();
        mm32s<NS, false, true>(Sst, wl, blin + blk * CC, SC, w, lane);
        __syncthreads();
        lnres<SRW>(SC, Sst, SRW, Sst, ROWS, ROWS, g2 + blk * CC, b2 + blk * CC, w, lane);
        __syncthreads();
    }
    if (tid < CC) SA[tid] = g_qpma[tid];
    mm32s<NS, true,  false>(Sst, Wk + 2 * CC * CC, bk + 2 * CC, SB, w, lane);
    mm32s<NS, false, false>(Sst, Wv + 2 * CC * CC, bv + 2 * CC, SC, w, lane);
    __syncthreads();
    attn_pma_pair<ROWS>(SA, SB, SC, gA, gB, offB, lenA, lenB, w, lane);
}

// ============================================================================
// PACKED kernel: mid singles + pairs of small genes, 4-row granularity
// ============================================================================
__global__ __launch_bounds__(256, 3)
void gene_packed(const float* __restrict__ rf,
                 const float* __restrict__ Wq, const float* __restrict__ Wk,
                 const float* __restrict__ Wv, const float* __restrict__ Wo,
                 const float* __restrict__ bq, const float* __restrict__ bk,
                 const float* __restrict__ bv, const float* __restrict__ bo,
                 const float* __restrict__ Wlin, const float* __restrict__ blin,
                 const float* __restrict__ g1, const float* __restrict__ b1,
                 const float* __restrict__ g2, const float* __restrict__ b2,
                 const int* __restrict__ rxn_idx)
{
    extern __shared__ float sm[];
    float* Sst = sm;                    // [<=32][SRW]
    float* SA  = sm + B32;
    float* SB  = SA + B32;              // K^T [128][SKT32]
    float* SC  = SB + KT32;

    int i    = blockIdx.x;
    int tid  = threadIdx.x;
    int w    = tid >> 5;
    int lane = tid & 31;

    int nmid = g_nmid;
    int gA, gB, sA, sB, lenA, lenB;

    if (i < nmid) {
        gA = g_midlist[i];
        sA = g_starts[gA];  lenA = g_starts[gA + 1] - sA;
        gB = -1; sB = 0; lenB = 0;
    } else {
        int j = i - nmid;
        int nsmall = g_nsmall;
        if (2 * j >= nsmall) return;
        gA = g_smalllist[2 * j];
        sA = g_starts[gA];  lenA = g_starts[gA + 1] - sA;
        if (2 * j + 1 < nsmall) {
            gB = g_smalllist[2 * j + 1];
            sB = g_starts[gB];  lenB = g_starts[gB + 1] - sB;
        } else { gB = -1; sB = 0; lenB = 0; }
    }

    int offB = (lenA + 3) & ~3;
    int lenr = offB + ((lenB + 3) & ~3);     // multiple of 4, <= 32
    int NS   = lenr >> 2;                    // 1..8

    // gather
    for (int r = w; r < lenr; r += 8) {
        bool isB  = r >= offB;
        int local = isB ? (r - offB) : r;
        int ln    = isB ? lenB : lenA;
        int st    = isB ? sB   : sA;
        if (local < ln) {
            int rx = rxn_idx[st + local];
            ((float4*)(Sst + r * SRW))[lane] = ((const float4*)(rf + (size_t)rx * CC))[lane];
        } else {
            ((float4*)(Sst + r * SRW))[lane] = make_float4(0.f, 0.f, 0.f, 0.f);
        }
    }
    __syncthreads();

#define CALL_ENC(NSV) enc_pair<NSV>(Sst, SA, SB, SC, Wq, Wk, Wv, Wo, bq, bk, bv, bo, \
                                    Wlin, blin, g1, b1, g2, b2, gA, gB, offB, lenA, lenB, w, lane, tid)
    switch (NS) {
    case 1: CALL_ENC(1); break;
    case 2: CALL_ENC(2); break;
    case 3: CALL_ENC(3); break;
    case 4: CALL_ENC(4); break;
    case 5: CALL_ENC(5); break;
    case 6: CALL_ENC(6); break;
    case 7: CALL_ENC(7); break;
    default: CALL_ENC(8); break;
    }
#undef CALL_ENC
}

// ============================================================================
// LONG kernel: genes with len > 32 (rare); ends after PMA attention
// ============================================================================
__global__ __launch_bounds__(256, 1)
void gene_long64(const float* __restrict__ rf,
                 const float* __restrict__ Wq, const float* __restrict__ Wk,
                 const float* __restrict__ Wv, const float* __restrict__ Wo,
                 const float* __restrict__ bq, const float* __restrict__ bk,
                 const float* __restrict__ bv, const float* __restrict__ bo,
                 const float* __restrict__ Wlin, const float* __restrict__ blin,
                 const float* __restrict__ g1, const float* __restrict__ b1,
                 const float* __restrict__ g2, const float* __restrict__ b2,
                 const int* __restrict__ rxn_idx)
{
    extern __shared__ float sm[];
    float* Sst = sm;                    // [64][SR64]
    float* SA  = sm + B64;
    float* SB  = SA + B64;
    float* SC  = SB + KT64;

    int tid  = threadIdx.x;
    int w    = tid >> 5;
    int lane = tid & 31;
    int nlong = g_longcount;

    for (int i = blockIdx.x; i < nlong; i += gridDim.x) {
        int g     = g_longlist[i];
        int start = g_starts[g];
        int cnt   = g_starts[g + 1] - start;
        int len   = cnt < 64 ? cnt : 64;
        int lenr  = (len + 7) & ~7;
        if (lenr > 64) lenr = 64;

        for (int r = w; r < lenr; r += 8) {
            if (r < len) {
                int rx = rxn_idx[start + r];
                ((float4*)(Sst + r * SR64))[lane] = ((const float4*)(rf + (size_t)rx * CC))[lane];
            } else {
                ((float4*)(Sst + r * SR64))[lane] = make_float4(0.f, 0.f, 0.f, 0.f);
            }
        }
        __syncthreads();

        for (int blk = 0; blk < 2; blk++) {
            const float* wq = Wq + blk * CC * CC;  const float* wk = Wk + blk * CC * CC;
            const float* wv = Wv + blk * CC * CC;  const float* wo = Wo + blk * CC * CC;
            const float* wl = Wlin + blk * CC * CC;
            mm64row<false, false>(Sst, wq, bq + blk * CC, SA, lenr, w, lane);
            mm64row<true,  false>(Sst, wk, bk + blk * CC, SB, lenr, w, lane);
            mm64row<false, false>(Sst, wv, bv + blk * CC, SC, lenr, w, lane);
            __syncthreads();
            attn64(SA, SB, SC, SA, SR64, lenr, len, lenr, w, lane);
            __syncthreads();
            mm64row<false, false>(SA, wo, bo + blk * CC, SB, lenr, w, lane);
            __syncthreads();
            lnres<SR64>(SB, Sst, SR64, Sst, lenr, len, g1 + blk * CC, b1 + blk * CC, w, lane);
            __syncthreads();
            mm64row<false, true>(Sst, wl, blin + blk * CC, SC, lenr, w, lane);
            __syncthreads();
            lnres<SR64>(SC, Sst, SR64, Sst, lenr, lenr, g2 + blk * CC, b2 + blk * CC, w, lane);
            __syncthreads();
        }
        if (tid < CC) SA[tid] = g_qpma[tid];
        mm64row<true,  false>(Sst, Wk + 2 * CC * CC, bk + 2 * CC, SB, lenr, w, lane);
        mm64row<false, false>(Sst, Wv + 2 * CC * CC, bv + 2 * CC, SC, lenr, w, lane);
        __syncthreads();
        attn64(SA, SB, SC, g_pma + (size_t)g * CC, CC, 1, len, lenr, w, lane);
        __syncthreads();
    }
}

// ============================================================================
// TAIL kernel: batched PMA-projection + decoder over 32 genes per CTA
// ============================================================================
__global__ __launch_bounds__(256)
void gene_tail(const float* __restrict__ Wv, const float* __restrict__ Wo,
               const float* __restrict__ bv, const float* __restrict__ bo,
               const float* __restrict__ Wlin, const float* __restrict__ blin,
               const float* __restrict__ g1, const float* __restrict__ b1,
               const float* __restrict__ g2, const float* __restrict__ b2,
               const float* __restrict__ seed,
               float* __restrict__ out)
{
    extern __shared__ float sm[];
    float* Sst = sm;                    // [32][SRW]
    float* SA  = sm + B32;
    float* SC  = SA + B32;

    int g0   = blockIdx.x * 32;
    int tid  = threadIdx.x;
    int w    = tid >> 5;
    int lane = tid & 31;

    for (int r = w; r < 32; r += 8)
        ((float4*)(Sst + r * SRW))[lane] = ((const float4*)(g_pma + (size_t)(g0 + r) * CC))[lane];
    __syncthreads();

    mm32s<8, false, false>(Sst, Wo + 2 * CC * CC, bo + 2 * CC, SA, w, lane);
    __syncthreads();
    lnres<SRW>(SA, seed, 0, Sst, 32, 32, g1 + 2 * CC, b1 + 2 * CC, w, lane);
    __syncthreads();
    mm32s<8, false, true>(Sst, Wlin + 2 * CC * CC, blin + 2 * CC, SC, w, lane);
    __syncthreads();
    lnres<SRW>(SC, Sst, SRW, Sst, 32, 32, g2 + 2 * CC, b2 + 2 * CC, w, lane);
    __syncthreads();

    mm32s<8, false, false>(Sst, Wv + 3 * CC * CC, bv + 3 * CC, SA, w, lane);
    __syncthreads();
    mm32s<8, false, false>(SA, Wo + 3 * CC * CC, bo + 3 * CC, SC, w, lane);
    __syncthreads();
    lnres<SRW>(SC, Sst, SRW, Sst, 32, 32, g1 + 3 * CC, b1 + 3 * CC, w, lane);
    __syncthreads();
    mm32s<8, false, true>(Sst, Wlin + 3 * CC * CC, blin + 3 * CC, SC, w, lane);
    __syncthreads();
    lnres<SRW>(SC, Sst, SRW, Sst, 32, 32, g2 + 3 * CC, b2 + 3 * CC, w, lane);
    __syncthreads();

    for (int r = w; r < 32; r += 8) {
        float4 v = ((const float4*)(Sst + r * SRW))[lane];
        float o[4] = {v.x, v.y, v.z, v.w};
#pragma unroll
        for (int j = 0; j < 4; j++) {
            float x = o[j];
            if (x != x) x = 0.f;
            x = fminf(fmaxf(x, -3.402823466e38f), 3.402823466e38f);
            o[j] = x;
        }
        ((float4*)(out + (size_t)(g0 + r) * CC))[lane] = make_float4(o[0], o[1], o[2], o[3]);
    }
}

extern "C" void kernel_launch(void* const* d_in, const int* in_sizes, int n_in,
                              void* d_out, int out_size)
{
    const float* rf   = (const float*)d_in[0];
    const float* Wq   = (const float*)d_in[1];
    const float* Wk   = (const float*)d_in[2];
    const float* Wv   = (const float*)d_in[3];
    const float* Wo   = (const float*)d_in[4];
    const float* bq   = (const float*)d_in[5];
    const float* bk   = (const float*)d_in[6];
    const float* bv   = (const float*)d_in[7];
    const float* bo   = (const float*)d_in[8];
    const float* Wlin = (const float*)d_in[9];
    const float* blin = (const float*)d_in[10];
    const float* g1   = (const float*)d_in[11];
    const float* b1   = (const float*)d_in[12];
    const float* g2   = (const float*)d_in[13];
    const float* b2   = (const float*)d_in[14];
    const float* seed = (const float*)d_in[15];
    const int*   rxn  = (const int*)d_in[16];
    const int*   gidx = (const int*)d_in[17];
    int E = in_sizes[16];

    cudaFuncSetAttribute(gene_packed, cudaFuncAttributeMaxDynamicSharedMemorySize, SM32_BYTES);
    cudaFuncSetAttribute(gene_long64, cudaFuncAttributeMaxDynamicSharedMemorySize, SM64_BYTES);
    cudaFuncSetAttribute(gene_tail,   cudaFuncAttributeMaxDynamicSharedMemorySize, SMT_BYTES);

    seg_bounds_kernel<<<(E + 255) / 256, 256>>>(gidx, E);
    classify_kernel<<<(GENES + 255) / 256, 256>>>();
    prep_qpma_kernel<<<1, 128>>>(Wq, bq, seed);
    gene_packed<<<GENES, 256, SM32_BYTES>>>(rf, Wq, Wk, Wv, Wo, bq, bk, bv, bo,
                                            Wlin, blin, g1, b1, g2, b2, rxn);
    gene_long64<<<128, 256, SM64_BYTES>>>(rf, Wq, Wk, Wv, Wo, bq, bk, bv, bo,
                                          Wlin, blin, g1, b1, g2, b2, rxn);
    gene_tail<<<GENES / 32, 256, SMT_BYTES>>>(Wv, Wo, bv, bo, Wlin, blin,
                                              g1, b1, g2, b2, seed, (float*)d_out);
}

// round 13
// speedup vs baseline: 1.2491x; 1.0026x over previous
#include <cuda_runtime.h>
#include <math.h>

#define CC    128
#define GENES 4096
#define SRW   132                 // row stride (floats)

// ---- 32-row packed kernel geometry ----
#define SKT32 33
#define B32   (32 * SRW)          // 4224 floats
#define KT32  (128 * SKT32)       // 4224 floats
#define SM32_BYTES ((3 * B32 + KT32) * 4)   // 67,584 B -> 3 CTAs/SM

// ---- long (len>32) kernel geometry ----
#define SR64  136
#define SKT64 69
#define B64   (64 * SR64)
#define KT64  (128 * SKT64)
#define SM64_BYTES ((3 * B64 + KT64) * 4)

// ---- tail kernel ----
#define SMT_BYTES (3 * B32 * 4)

__device__ int   g_starts[GENES + 1];
__device__ int   g_nsmall, g_nmid, g_longcount;
__device__ int   g_smalllist[GENES];
__device__ int   g_midlist[GENES];
__device__ int   g_longlist[GENES];
__device__ float g_qpma[CC];              // seed @ Wq[2] + bq[2]
__device__ float g_pma[GENES * CC];       // PMA attention output per gene

__device__ __forceinline__ float warp_sum(float v) {
#pragma unroll
    for (int o = 16; o; o >>= 1) v += __shfl_xor_sync(0xffffffffu, v, o);
    return v;
}
__device__ __forceinline__ float warp_max(float v) {
#pragma unroll
    for (int o = 16; o; o >>= 1) v = fmaxf(v, __shfl_xor_sync(0xffffffffu, v, o));
    return v;
}

// ============================================================================
// bounds + classify + PMA-Q precompute
// ============================================================================
__global__ void seg_bounds_kernel(const int* __restrict__ gene_idx, int E)
{
    int e = blockIdx.x * 256 + threadIdx.x;
    if (e == 0) { g_starts[GENES] = E; g_nsmall = 0; g_nmid = 0; g_longcount = 0; }
    if (e < E) {
        int gi = gene_idx[e];
        if (e == 0 || gene_idx[e - 1] != gi) g_starts[gi] = e;
    }
}

__global__ void classify_kernel()
{
    int g = blockIdx.x * 256 + threadIdx.x;
    if (g < GENES) {
        int len = g_starts[g + 1] - g_starts[g];
        if (len <= 16)      { int p = atomicAdd(&g_nsmall, 1);    g_smalllist[p] = g; }
        else if (len <= 32) { int p = atomicAdd(&g_nmid, 1);      g_midlist[p]   = g; }
        else                { int p = atomicAdd(&g_longcount, 1); g_longlist[p]  = g; }
    }
}

__global__ void prep_qpma_kernel(const float* __restrict__ Wq,
                                 const float* __restrict__ bq,
                                 const float* __restrict__ seed)
{
    int c = threadIdx.x;                       // 128 threads
    float acc = bq[2 * CC + c];
    const float* W2 = Wq + 2 * CC * CC;
#pragma unroll 8
    for (int k = 0; k < CC; k++) acc = fmaf(seed[k], W2[k * CC + c], acc);
    g_qpma[c] = acc;
}

// ============================================================================
// mm32s<NS>: X[NS*4 rows,128] @ W + b -> Y. 8 warps = 4 row-groups x 2 halves.
// ============================================================================
template <int NS, bool TRANS, bool RELU>
__device__ __forceinline__ void mm32s(const float* X, const float* __restrict__ W,
                                      const float* __restrict__ bias, float* Y,
                                      int w, int lane)
{
    int rg = w >> 1;
    int ch = w & 1;
    int c0 = ch * 64 + lane * 2;
    float acc[NS][2];
#pragma unroll
    for (int i = 0; i < NS; i++) { acc[i][0] = 0.f; acc[i][1] = 0.f; }

#pragma unroll 2
    for (int kk = 0; kk < CC; kk += 4) {
        float2 w0 = *(const float2*)(W + (kk + 0) * CC + c0);
        float2 w1 = *(const float2*)(W + (kk + 1) * CC + c0);
        float2 w2 = *(const float2*)(W + (kk + 2) * CC + c0);
        float2 w3 = *(const float2*)(W + (kk + 3) * CC + c0);
#pragma unroll
        for (int i = 0; i < NS; i++) {
            float4 xv = *(const float4*)(X + (rg + 4 * i) * SRW + kk);
            acc[i][0] = fmaf(xv.x, w0.x, acc[i][0]);
            acc[i][1] = fmaf(xv.x, w0.y, acc[i][1]);
            acc[i][0] = fmaf(xv.y, w1.x, acc[i][0]);
            acc[i][1] = fmaf(xv.y, w1.y, acc[i][1]);
            acc[i][0] = fmaf(xv.z, w2.x, acc[i][0]);
            acc[i][1] = fmaf(xv.z, w2.y, acc[i][1]);
            acc[i][0] = fmaf(xv.w, w3.x, acc[i][0]);
            acc[i][1] = fmaf(xv.w, w3.y, acc[i][1]);
        }
    }
    float2 bv = *(const float2*)(bias + c0);
#pragma unroll
    for (int i = 0; i < NS; i++) {
        int r = rg + 4 * i;
        float o0 = acc[i][0] + bv.x, o1 = acc[i][1] + bv.y;
        if (RELU) { o0 = fmaxf(o0, 0.f); o1 = fmaxf(o1, 0.f); }
        if (!TRANS) {
            *(float2*)(Y + r * SRW + c0) = make_float2(o0, o1);
        } else {
            Y[(c0 + 0) * SKT32 + r] = o0;
            Y[(c0 + 1) * SKT32 + r] = o1;
        }
    }
}

// ============================================================================
// mm64row: row-split matmul for the long (64-row) kernel
// ============================================================================
template <bool TRANS, bool RELU>
__device__ void mm64row(const float* X, const float* __restrict__ W,
                        const float* __restrict__ bias, float* Y,
                        int rows, int w, int lane)
{
    int nr = (rows > w) ? (((rows - 1 - w) >> 3) + 1) : 0;
    if (nr == 0) return;
    int c0 = lane * 4;
    float acc[8][4];
#pragma unroll
    for (int i = 0; i < 8; i++) { acc[i][0]=0.f; acc[i][1]=0.f; acc[i][2]=0.f; acc[i][3]=0.f; }

#pragma unroll 2
    for (int kk = 0; kk < CC; kk += 4) {
        float4 w0 = *(const float4*)(W + (kk + 0) * CC + c0);
        float4 w1 = *(const float4*)(W + (kk + 1) * CC + c0);
        float4 w2 = *(const float4*)(W + (kk + 2) * CC + c0);
        float4 w3 = *(const float4*)(W + (kk + 3) * CC + c0);
#pragma unroll
        for (int i = 0; i < 8; i++) {
            if (i < nr) {
                float4 xv = *(const float4*)(X + (w + 8 * i) * SR64 + kk);
                acc[i][0]=fmaf(xv.x,w0.x,acc[i][0]); acc[i][1]=fmaf(xv.x,w0.y,acc[i][1]);
                acc[i][2]=fmaf(xv.x,w0.z,acc[i][2]); acc[i][3]=fmaf(xv.x,w0.w,acc[i][3]);
                acc[i][0]=fmaf(xv.y,w1.x,acc[i][0]); acc[i][1]=fmaf(xv.y,w1.y,acc[i][1]);
                acc[i][2]=fmaf(xv.y,w1.z,acc[i][2]); acc[i][3]=fmaf(xv.y,w1.w,acc[i][3]);
                acc[i][0]=fmaf(xv.z,w2.x,acc[i][0]); acc[i][1]=fmaf(xv.z,w2.y,acc[i][1]);
                acc[i][2]=fmaf(xv.z,w2.z,acc[i][2]); acc[i][3]=fmaf(xv.z,w2.w,acc[i][3]);
                acc[i][0]=fmaf(xv.w,w3.x,acc[i][0]); acc[i][1]=fmaf(xv.w,w3.y,acc[i][1]);
                acc[i][2]=fmaf(xv.w,w3.z,acc[i][2]); acc[i][3]=fmaf(xv.w,w3.w,acc[i][3]);
            }
        }
    }
    float4 bv = *(const float4*)(bias + c0);
#pragma unroll
    for (int i = 0; i < 8; i++) {
        if (i < nr) {
            int r = w + 8 * i;
            float o0=acc[i][0]+bv.x, o1=acc[i][1]+bv.y, o2=acc[i][2]+bv.z, o3=acc[i][3]+bv.w;
            if (RELU) { o0=fmaxf(o0,0.f); o1=fmaxf(o1,0.f); o2=fmaxf(o2,0.f); o3=fmaxf(o3,0.f); }
            if (!TRANS) {
                *(float4*)(Y + r * SR64 + c0) = make_float4(o0, o1, o2, o3);
            } else {
                Y[(c0+0)*SKT64 + r]=o0; Y[(c0+1)*SKT64 + r]=o1;
                Y[(c0+2)*SKT64 + r]=o2; Y[(c0+3)*SKT64 + r]=o3;
            }
        }
    }
}

// ============================================================================
// paired encoder attention: task = (head, row-block of RB rows).
// RB = 8 (or 4 if KVR%8 != 0) -> Kt and V register-reused across RB rows.
// Per-row mask windows handle the A/B gene split exactly.
// ============================================================================
template <int KVR>
__device__ __forceinline__ void attn_pair(float* QO, const float* Kt, const float* V,
                                          int offB, int lenA, int lenB, int w, int lane)
{
    constexpr int RB     = (KVR % 8 == 0) ? 8 : 4;   // rows per task
    constexpr int NTASK  = 4 * (KVR / RB);           // heads x row-blocks
    const float scale = 0.17677669529663687f;

    for (int t = w; t < NTASK; t += 8) {
        int h    = t & 3;
        int blk  = t >> 2;
        int base = h * 32;
        int r0   = blk * RB;

        float s[RB];
#pragma unroll
        for (int i = 0; i < RB; i++) s[i] = 0.f;

#pragma unroll
        for (int d = 0; d < 32; d += 4) {
            float k0 = Kt[(base + d + 0) * SKT32 + lane];
            float k1 = Kt[(base + d + 1) * SKT32 + lane];
            float k2 = Kt[(base + d + 2) * SKT32 + lane];
            float k3 = Kt[(base + d + 3) * SKT32 + lane];
#pragma unroll
            for (int i = 0; i < RB; i++) {
                float4 q = *(const float4*)(QO + (r0 + i) * SRW + base + d);
                s[i] = fmaf(q.x, k0, fmaf(q.y, k1, fmaf(q.z, k2, fmaf(q.w, k3, s[i]))));
            }
        }

        // mask + softmax per row (window depends on which gene owns the row)
#pragma unroll
        for (int i = 0; i < RB; i++) {
            int r  = r0 + i;
            int lo = (r >= offB) ? offB : 0;
            int ln = (r >= offB) ? lenB : lenA;
            float sv = ((unsigned)(lane - lo) < (unsigned)ln) ? s[i] * scale : -1e30f;
            float m = warp_max(sv);
            float p = __expf(sv - m);
            s[i] = p * (1.f / warp_sum(p));
        }

        float acc[RB];
#pragma unroll
        for (int i = 0; i < RB; i++) acc[i] = 0.f;
#pragma unroll
        for (int k = 0; k < KVR; k++) {
            float v = V[k * SRW + base + lane];
#pragma unroll
            for (int i = 0; i < RB; i++)
                acc[i] = fmaf(__shfl_sync(0xffffffffu, s[i], k), v, acc[i]);
        }
#pragma unroll
        for (int i = 0; i < RB; i++)
            QO[(r0 + i) * SRW + base + lane] = acc[i];
    }
}

// paired PMA attention: warps 0-3 gene A heads, 4-7 gene B heads; Q = shared row
template <int KVR>
__device__ __forceinline__ void attn_pma_pair(const float* Q, const float* Kt, const float* V,
                                              int gA, int gB, int offB, int lenA, int lenB,
                                              int w, int lane)
{
    const float scale = 0.17677669529663687f;
    int gi   = w >> 2;                  // 0 = gene A, 1 = gene B
    int base = (w & 3) * 32;
    float s = 0.f;
#pragma unroll
    for (int d = 0; d < 32; d += 4) {
        float4 q = *(const float4*)(Q + base + d);
        s = fmaf(q.x, Kt[(base + d + 0) * SKT32 + lane],
            fmaf(q.y, Kt[(base + d + 1) * SKT32 + lane],
            fmaf(q.z, Kt[(base + d + 2) * SKT32 + lane],
            fmaf(q.w, Kt[(base + d + 3) * SKT32 + lane], s))));
    }
    int lo = gi ? offB : 0;
    int ln = gi ? lenB : lenA;
    s = ((unsigned)(lane - lo) < (unsigned)ln) ? s * scale : -1e30f;
    float m = warp_max(s);
    float p = __expf(s - m);
    float a = p * (1.f / warp_sum(p));
    float acc = 0.f;
#pragma unroll
    for (int k = 0; k < KVR; k++)
        acc = fmaf(__shfl_sync(0xffffffffu, a, k), V[k * SRW + base + lane], acc);
    int gout = gi ? gB : gA;
    if (gout >= 0) g_pma[(size_t)gout * CC + base + lane] = acc;
}

// attention (kv <= 64) for the long kernel
__device__ void attn64(const float* Q, const float* Kt, const float* V,
                       float* outp, int outStride,
                       int Lq, int len, int kvr, int w, int lane)
{
    const float scale = 0.17677669529663687f;
    int ntask = Lq * 4;
    for (int t = w; t < ntask; t += 8) {
        int r = t >> 2, base = (t & 3) * 32;
        float s0 = 0.f, s1 = 0.f;
#pragma unroll
        for (int d = 0; d < 32; d++) {
            float qd = Q[r * SR64 + base + d];
            s0 = fmaf(qd, Kt[(base + d) * SKT64 + lane], s0);
            s1 = fmaf(qd, Kt[(base + d) * SKT64 + lane + 32], s1);
        }
        s0 = (lane < len)      ? s0 * scale : -1e30f;
        s1 = (lane + 32 < len) ? s1 * scale : -1e30f;
        float m = warp_max(fmaxf(s0, s1));
        float p0 = __expf(s0 - m), p1 = __expf(s1 - m);
        float inv = 1.f / warp_sum(p0 + p1);
        float a0 = p0 * inv, a1 = p1 * inv;
        float acc = 0.f;
        int k0 = kvr < 32 ? kvr : 32;
        for (int k = 0; k < k0; k++)
            acc = fmaf(__shfl_sync(0xffffffffu, a0, k), V[k * SR64 + base + lane], acc);
        for (int k = 32; k < kvr; k++)
            acc = fmaf(__shfl_sync(0xffffffffu, a1, k - 32), V[k * SR64 + base + lane], acc);
        outp[r * outStride + base + lane] = acc;
    }
}

// ============================================================================
// LN(residual + masked A). resStride==0 -> broadcast residual.
// ============================================================================
template <int SROW>
__device__ void lnres(const float* A, const float* Res, int resStride, float* Out,
                      int rows, int qmasklen,
                      const float* __restrict__ g, const float* __restrict__ b,
                      int w, int lane)
{
    for (int r = w; r < rows; r += 8) {
        float4 a = (r < qmasklen) ? *(const float4*)(A + r * SROW + lane * 4)
                                  : make_float4(0.f, 0.f, 0.f, 0.f);
        float4 s = *(const float4*)(Res + r * resStride + lane * 4);
        float t0 = a.x + s.x, t1 = a.y + s.y, t2 = a.z + s.z, t3 = a.w + s.w;
        float sum = warp_sum(t0 + t1 + t2 + t3);
        float sq  = warp_sum(t0*t0 + t1*t1 + t2*t2 + t3*t3);
        float mean = sum * (1.f / 128.f);
        float var  = sq * (1.f / 128.f) - mean * mean;
        float rstd = rsqrtf(var + 1e-5f);
        float4 gv = *(const float4*)(g + lane * 4);
        float4 bv = *(const float4*)(b + lane * 4);
        float4 o;
        o.x = (t0 - mean) * rstd * gv.x + bv.x;
        o.y = (t1 - mean) * rstd * gv.y + bv.y;
        o.z = (t2 - mean) * rstd * gv.z + bv.z;
        o.w = (t3 - mean) * rstd * gv.w + bv.w;
        *(float4*)(Out + r * SROW + lane * 4) = o;
    }
}

// paired version: row valid if local index (relative to its gene window) < len
__device__ void lnres_pair(const float* A, const float* Res, float* Out,
                           int rows, int offB, int lenA, int lenB,
                           const float* __restrict__ g, const float* __restrict__ b,
                           int w, int lane)
{
    for (int r = w; r < rows; r += 8) {
        int lo = (r >= offB) ? offB : 0;
        int ln = (r >= offB) ? lenB : lenA;
        float4 a = ((r - lo) < ln) ? *(const float4*)(A + r * SRW + lane * 4)
                                   : make_float4(0.f, 0.f, 0.f, 0.f);
        float4 s = *(const float4*)(Res + r * SRW + lane * 4);
        float t0 = a.x + s.x, t1 = a.y + s.y, t2 = a.z + s.z, t3 = a.w + s.w;
        float sum = warp_sum(t0 + t1 + t2 + t3);
        float sq  = warp_sum(t0*t0 + t1*t1 + t2*t2 + t3*t3);
        float mean = sum * (1.f / 128.f);
        float var  = sq * (1.f / 128.f) - mean * mean;
        float rstd = rsqrtf(var + 1e-5f);
        float4 gv = *(const float4*)(g + lane * 4);
        float4 bv = *(const float4*)(b + lane * 4);
        float4 o;
        o.x = (t0 - mean) * rstd * gv.x + bv.x;
        o.y = (t1 - mean) * rstd * gv.y + bv.y;
        o.z = (t2 - mean) * rstd * gv.z + bv.z;
        o.w = (t3 - mean) * rstd * gv.w + bv.w;
        *(float4*)(Out + r * SRW + lane * 4) = o;
    }
}

// ============================================================================
// unified encoder(x2) + PMA attention for 1 or 2 genes in NS*4 rows
// ============================================================================
template <int NS>
__device__ __forceinline__ void enc_pair(
    float* Sst, float* SA, float* SB, float* SC,
    const float* __restrict__ Wq, const float* __restrict__ Wk,
    const float* __restrict__ Wv, const float* __restrict__ Wo,
    const float* __restrict__ bq, const float* __restrict__ bk,
    const float* __restrict__ bv, const float* __restrict__ bo,
    const float* __restrict__ Wlin, const float* __restrict__ blin,
    const float* __restrict__ g1, const float* __restrict__ b1,
    const float* __restrict__ g2, const float* __restrict__ b2,
    int gA, int gB, int offB, int lenA, int lenB,
    int w, int lane, int tid)
{
    constexpr int ROWS = NS * 4;
#pragma unroll 1
    for (int blk = 0; blk < 2; blk++) {
        const float* wq = Wq + blk * CC * CC;  const float* wk = Wk + blk * CC * CC;
        const float* wv = Wv + blk * CC * CC;  const float* wo = Wo + blk * CC * CC;
        const float* wl = Wlin + blk * CC * CC;
        mm32s<NS, false, false>(Sst, wq, bq + blk * CC, SA, w, lane);
        mm32s<NS, true,  false>(Sst, wk, bk + blk * CC, SB, w, lane);
        mm32s<NS, false, false>(Sst, wv, bv + blk * CC, SC, w, lane);
        __syncthreads();
        attn_pair<ROWS>(SA, SB, SC, offB, lenA, lenB, w, lane);
        __syncthreads();
        mm32s<NS, false, false>(SA, wo, bo + blk * CC, SB, w, lane);
        __syncthreads();
        lnres_pair(SB, Sst, Sst, ROWS, offB, lenA, lenB,
                   g1 + blk * CC, b1 + blk * CC, w, lane);
        __syncthreads();
        mm32s<NS, false, true>(Sst, wl, blin + blk * CC, SC, w, lane);
        __syncthreads();
        lnres<SRW>(SC, Sst, SRW, Sst, ROWS, ROWS, g2 + blk * CC, b2 + blk * CC, w, lane);
        __syncthreads();
    }
    if (tid < CC) SA[tid] = g_qpma[tid];
    mm32s<NS, true,  false>(Sst, Wk + 2 * CC * CC, bk + 2 * CC, SB, w, lane);
    mm32s<NS, false, false>(Sst, Wv + 2 * CC * CC, bv + 2 * CC, SC, w, lane);
    __syncthreads();
    attn_pma_pair<ROWS>(SA, SB, SC, gA, gB, offB, lenA, lenB, w, lane);
}

// ============================================================================
// PACKED kernel: mid singles + pairs of small genes, 4-row granularity
// ============================================================================
__global__ __launch_bounds__(256, 3)
void gene_packed(const float* __restrict__ rf,
                 const float* __restrict__ Wq, const float* __restrict__ Wk,
                 const float* __restrict__ Wv, const float* __restrict__ Wo,
                 const float* __restrict__ bq, const float* __restrict__ bk,
                 const float* __restrict__ bv, const float* __restrict__ bo,
                 const float* __restrict__ Wlin, const float* __restrict__ blin,
                 const float* __restrict__ g1, const float* __restrict__ b1,
                 const float* __restrict__ g2, const float* __restrict__ b2,
                 const int* __restrict__ rxn_idx)
{
    extern __shared__ float sm[];
    float* Sst = sm;                    // [<=32][SRW]
    float* SA  = sm + B32;
    float* SB  = SA + B32;              // K^T [128][SKT32]
    float* SC  = SB + KT32;

    int i    = blockIdx.x;
    int tid  = threadIdx.x;
    int w    = tid >> 5;
    int lane = tid & 31;

    int nmid = g_nmid;
    int gA, gB, sA, sB, lenA, lenB;

    if (i < nmid) {
        gA = g_midlist[i];
        sA = g_starts[gA];  lenA = g_starts[gA + 1] - sA;
        gB = -1; sB = 0; lenB = 0;
    } else {
        int j = i - nmid;
        int nsmall = g_nsmall;
        if (2 * j >= nsmall) return;
        gA = g_smalllist[2 * j];
        sA = g_starts[gA];  lenA = g_starts[gA + 1] - sA;
        if (2 * j + 1 < nsmall) {
            gB = g_smalllist[2 * j + 1];
            sB = g_starts[gB];  lenB = g_starts[gB + 1] - sB;
        } else { gB = -1; sB = 0; lenB = 0; }
    }

    int offB = (lenA + 3) & ~3;
    int lenr = offB + ((lenB + 3) & ~3);     // multiple of 4, <= 32
    int NS   = lenr >> 2;                    // 1..8

    // gather
    for (int r = w; r < lenr; r += 8) {
        bool isB  = r >= offB;
        int local = isB ? (r - offB) : r;
        int ln    = isB ? lenB : lenA;
        int st    = isB ? sB   : sA;
        if (local < ln) {
            int rx = rxn_idx[st + local];
            ((float4*)(Sst + r * SRW))[lane] = ((const float4*)(rf + (size_t)rx * CC))[lane];
        } else {
            ((float4*)(Sst + r * SRW))[lane] = make_float4(0.f, 0.f, 0.f, 0.f);
        }
    }
    __syncthreads();

#define CALL_ENC(NSV) enc_pair<NSV>(Sst, SA, SB, SC, Wq, Wk, Wv, Wo, bq, bk, bv, bo, \
                                    Wlin, blin, g1, b1, g2, b2, gA, gB, offB, lenA, lenB, w, lane, tid)
    switch (NS) {
    case 1: CALL_ENC(1); break;
    case 2: CALL_ENC(2); break;
    case 3: CALL_ENC(3); break;
    case 4: CALL_ENC(4); break;
    case 5: CALL_ENC(5); break;
    case 6: CALL_ENC(6); break;
    case 7: CALL_ENC(7); break;
    default: CALL_ENC(8); break;
    }
#undef CALL_ENC
}

// ============================================================================
// LONG kernel: genes with len > 32 (rare); ends after PMA attention
// ============================================================================
__global__ __launch_bounds__(256, 1)
void gene_long64(const float* __restrict__ rf,
                 const float* __restrict__ Wq, const float* __restrict__ Wk,
                 const float* __restrict__ Wv, const float* __restrict__ Wo,
                 const float* __restrict__ bq, const float* __restrict__ bk,
                 const float* __restrict__ bv, const float* __restrict__ bo,
                 const float* __restrict__ Wlin, const float* __restrict__ blin,
                 const float* __restrict__ g1, const float* __restrict__ b1,
                 const float* __restrict__ g2, const float* __restrict__ b2,
                 const int* __restrict__ rxn_idx)
{
    extern __shared__ float sm[];
    float* Sst = sm;                    // [64][SR64]
    float* SA  = sm + B64;
    float* SB  = SA + B64;
    float* SC  = SB + KT64;

    int tid  = threadIdx.x;
    int w    = tid >> 5;
    int lane = tid & 31;
    int nlong = g_longcount;

    for (int i = blockIdx.x; i < nlong; i += gridDim.x) {
        int g     = g_longlist[i];
        int start = g_starts[g];
        int cnt   = g_starts[g + 1] - start;
        int len   = cnt < 64 ? cnt : 64;
        int lenr  = (len + 7) & ~7;
        if (lenr > 64) lenr = 64;

        for (int r = w; r < lenr; r += 8) {
            if (r < len) {
                int rx = rxn_idx[start + r];
                ((float4*)(Sst + r * SR64))[lane] = ((const float4*)(rf + (size_t)rx * CC))[lane];
            } else {
                ((float4*)(Sst + r * SR64))[lane] = make_float4(0.f, 0.f, 0.f, 0.f);
            }
        }
        __syncthreads();

        for (int blk = 0; blk < 2; blk++) {
            const float* wq = Wq + blk * CC * CC;  const float* wk = Wk + blk * CC * CC;
            const float* wv = Wv + blk * CC * CC;  const float* wo = Wo + blk * CC * CC;
            const float* wl = Wlin + blk * CC * CC;
            mm64row<false, false>(Sst, wq, bq + blk * CC, SA, lenr, w, lane);
            mm64row<true,  false>(Sst, wk, bk + blk * CC, SB, lenr, w, lane);
            mm64row<false, false>(Sst, wv, bv + blk * CC, SC, lenr, w, lane);
            __syncthreads();
            attn64(SA, SB, SC, SA, SR64, lenr, len, lenr, w, lane);
            __syncthreads();
            mm64row<false, false>(SA, wo, bo + blk * CC, SB, lenr, w, lane);
            __syncthreads();
            lnres<SR64>(SB, Sst, SR64, Sst, lenr, len, g1 + blk * CC, b1 + blk * CC, w, lane);
            __syncthreads();
            mm64row<false, true>(Sst, wl, blin + blk * CC, SC, lenr, w, lane);
            __syncthreads();
            lnres<SR64>(SC, Sst, SR64, Sst, lenr, lenr, g2 + blk * CC, b2 + blk * CC, w, lane);
            __syncthreads();
        }
        if (tid < CC) SA[tid] = g_qpma[tid];
        mm64row<true,  false>(Sst, Wk + 2 * CC * CC, bk + 2 * CC, SB, lenr, w, lane);
        mm64row<false, false>(Sst, Wv + 2 * CC * CC, bv + 2 * CC, SC, lenr, w, lane);
        __syncthreads();
        attn64(SA, SB, SC, g_pma + (size_t)g * CC, CC, 1, len, lenr, w, lane);
        __syncthreads();
    }
}

// ============================================================================
// TAIL kernel: batched PMA-projection + decoder over 32 genes per CTA
// ============================================================================
__global__ __launch_bounds__(256)
void gene_tail(const float* __restrict__ Wv, const float* __restrict__ Wo,
               const float* __restrict__ bv, const float* __restrict__ bo,
               const float* __restrict__ Wlin, const float* __restrict__ blin,
               const float* __restrict__ g1, const float* __restrict__ b1,
               const float* __restrict__ g2, const float* __restrict__ b2,
               const float* __restrict__ seed,
               float* __restrict__ out)
{
    extern __shared__ float sm[];
    float* Sst = sm;                    // [32][SRW]
    float* SA  = sm + B32;
    float* SC  = SA + B32;

    int g0   = blockIdx.x * 32;
    int tid  = threadIdx.x;
    int w    = tid >> 5;
    int lane = tid & 31;

    for (int r = w; r < 32; r += 8)
        ((float4*)(Sst + r * SRW))[lane] = ((const float4*)(g_pma + (size_t)(g0 + r) * CC))[lane];
    __syncthreads();

    mm32s<8, false, false>(Sst, Wo + 2 * CC * CC, bo + 2 * CC, SA, w, lane);
    __syncthreads();
    lnres<SRW>(SA, seed, 0, Sst, 32, 32, g1 + 2 * CC, b1 + 2 * CC, w, lane);
    __syncthreads();
    mm32s<8, false, true>(Sst, Wlin + 2 * CC * CC, blin + 2 * CC, SC, w, lane);
    __syncthreads();
    lnres<SRW>(SC, Sst, SRW, Sst, 32, 32, g2 + 2 * CC, b2 + 2 * CC, w, lane);
    __syncthreads();

    mm32s<8, false, false>(Sst, Wv + 3 * CC * CC, bv + 3 * CC, SA, w, lane);
    __syncthreads();
    mm32s<8, false, false>(SA, Wo + 3 * CC * CC, bo + 3 * CC, SC, w, lane);
    __syncthreads();
    lnres<SRW>(SC, Sst, SRW, Sst, 32, 32, g1 + 3 * CC, b1 + 3 * CC, w, lane);
    __syncthreads();
    mm32s<8, false, true>(Sst, Wlin + 3 * CC * CC, blin + 3 * CC, SC, w, lane);
    __syncthreads();
    lnres<SRW>(SC, Sst, SRW, Sst, 32, 32, g2 + 3 * CC, b2 + 3 * CC, w, lane);
    __syncthreads();

    for (int r = w; r < 32; r += 8) {
        float4 v = ((const float4*)(Sst + r * SRW))[lane];
        float o[4] = {v.x, v.y, v.z, v.w};
#pragma unroll
        for (int j = 0; j < 4; j++) {
            float x = o[j];
            if (x != x) x = 0.f;
            x = fminf(fmaxf(x, -3.402823466e38f), 3.402823466e38f);
            o[j] = x;
        }
        ((float4*)(out + (size_t)(g0 + r) * CC))[lane] = make_float4(o[0], o[1], o[2], o[3]);
    }
}

extern "C" void kernel_launch(void* const* d_in, const int* in_sizes, int n_in,
                              void* d_out, int out_size)
{
    const float* rf   = (const float*)d_in[0];
    const float* Wq   = (const float*)d_in[1];
    const float* Wk   = (const float*)d_in[2];
    const float* Wv   = (const float*)d_in[3];
    const float* Wo   = (const float*)d_in[4];
    const float* bq   = (const float*)d_in[5];
    const float* bk   = (const float*)d_in[6];
    const float* bv   = (const float*)d_in[7];
    const float* bo   = (const float*)d_in[8];
    const float* Wlin = (const float*)d_in[9];
    const float* blin = (const float*)d_in[10];
    const float* g1   = (const float*)d_in[11];
    const float* b1   = (const float*)d_in[12];
    const float* g2   = (const float*)d_in[13];
    const float* b2   = (const float*)d_in[14];
    const float* seed = (const float*)d_in[15];
    const int*   rxn  = (const int*)d_in[16];
    const int*   gidx = (const int*)d_in[17];
    int E = in_sizes[16];

    cudaFuncSetAttribute(gene_packed, cudaFuncAttributeMaxDynamicSharedMemorySize, SM32_BYTES);
    cudaFuncSetAttribute(gene_long64, cudaFuncAttributeMaxDynamicSharedMemorySize, SM64_BYTES);
    cudaFuncSetAttribute(gene_tail,   cudaFuncAttributeMaxDynamicSharedMemorySize, SMT_BYTES);

    seg_bounds_kernel<<<(E + 255) / 256, 256>>>(gidx, E);
    classify_kernel<<<(GENES + 255) / 256, 256>>>();
    prep_qpma_kernel<<<1, 128>>>(Wq, bq, seed);
    gene_packed<<<GENES, 256, SM32_BYTES>>>(rf, Wq, Wk, Wv, Wo, bq, bk, bv, bo,
                                            Wlin, blin, g1, b1, g2, b2, rxn);
    gene_long64<<<128, 256, SM64_BYTES>>>(rf, Wq, Wk, Wv, Wo, bq, bk, bv, bo,
                                          Wlin, blin, g1, b1, g2, b2, rxn);
    gene_tail<<<GENES / 32, 256, SMT_BYTES>>>(Wv, Wo, bv, bo, Wlin, blin,
                                              g1, b1, g2, b2, seed, (float*)d_out);
}

// round 14
// speedup vs baseline: 1.2723x; 1.0185x over previous
#include <cuda_runtime.h>
#include <math.h>

#define CC    128
#define GENES 4096
#define SRW   132                 // row stride (floats)

// ---- 32-row packed kernel geometry ----
#define SKT32 33
#define B32   (32 * SRW)          // 4224 floats
#define KT32  (128 * SKT32)       // 4224 floats
#define SM32_BYTES ((3 * B32 + KT32) * 4)   // 67,584 B -> 3 CTAs/SM

// ---- long (len>32) kernel geometry ----
#define SR64  136
#define SKT64 69
#define B64   (64 * SR64)
#define KT64  (128 * SKT64)
#define SM64_BYTES ((3 * B64 + KT64) * 4)

// ---- tail kernel ----
#define SMT_BYTES (3 * B32 * 4)

__device__ int   g_starts[GENES + 1];
__device__ int   g_nsmall, g_nmid, g_longcount;
__device__ int   g_smalllist[GENES];
__device__ int   g_midlist[GENES];
__device__ int   g_longlist[GENES];
__device__ float g_qpma[CC];              // seed @ Wq[2] + bq[2]
__device__ float g_pma[GENES * CC];       // PMA attention output per gene

__device__ __forceinline__ float warp_sum(float v) {
#pragma unroll
    for (int o = 16; o; o >>= 1) v += __shfl_xor_sync(0xffffffffu, v, o);
    return v;
}
__device__ __forceinline__ float warp_max(float v) {
#pragma unroll
    for (int o = 16; o; o >>= 1) v = fmaxf(v, __shfl_xor_sync(0xffffffffu, v, o));
    return v;
}

// ============================================================================
// bounds + classify + PMA-Q precompute
// ============================================================================
__global__ void seg_bounds_kernel(const int* __restrict__ gene_idx, int E)
{
    int e = blockIdx.x * 256 + threadIdx.x;
    if (e == 0) { g_starts[GENES] = E; g_nsmall = 0; g_nmid = 0; g_longcount = 0; }
    if (e < E) {
        int gi = gene_idx[e];
        if (e == 0 || gene_idx[e - 1] != gi) g_starts[gi] = e;
    }
}

__global__ void classify_kernel()
{
    int g = blockIdx.x * 256 + threadIdx.x;
    if (g < GENES) {
        int len = g_starts[g + 1] - g_starts[g];
        if (len <= 16)      { int p = atomicAdd(&g_nsmall, 1);    g_smalllist[p] = g; }
        else if (len <= 32) { int p = atomicAdd(&g_nmid, 1);      g_midlist[p]   = g; }
        else                { int p = atomicAdd(&g_longcount, 1); g_longlist[p]  = g; }
    }
}

__global__ void prep_qpma_kernel(const float* __restrict__ Wq,
                                 const float* __restrict__ bq,
                                 const float* __restrict__ seed)
{
    int c = threadIdx.x;                       // 128 threads
    float acc = bq[2 * CC + c];
    const float* W2 = Wq + 2 * CC * CC;
#pragma unroll 8
    for (int k = 0; k < CC; k++) acc = fmaf(seed[k], W2[k * CC + c], acc);
    g_qpma[c] = acc;
}

// ============================================================================
// mm32s<NS>: X[NS*4 rows,128] @ W + b -> Y. 8 warps = 4 row-groups x 2 halves.
// ============================================================================
template <int NS, bool TRANS, bool RELU>
__device__ __forceinline__ void mm32s(const float* X, const float* __restrict__ W,
                                      const float* __restrict__ bias, float* Y,
                                      int w, int lane)
{
    int rg = w >> 1;
    int ch = w & 1;
    int c0 = ch * 64 + lane * 2;
    float acc[NS][2];
#pragma unroll
    for (int i = 0; i < NS; i++) { acc[i][0] = 0.f; acc[i][1] = 0.f; }

#pragma unroll 2
    for (int kk = 0; kk < CC; kk += 4) {
        float2 w0 = *(const float2*)(W + (kk + 0) * CC + c0);
        float2 w1 = *(const float2*)(W + (kk + 1) * CC + c0);
        float2 w2 = *(const float2*)(W + (kk + 2) * CC + c0);
        float2 w3 = *(const float2*)(W + (kk + 3) * CC + c0);
#pragma unroll
        for (int i = 0; i < NS; i++) {
            float4 xv = *(const float4*)(X + (rg + 4 * i) * SRW + kk);
            acc[i][0] = fmaf(xv.x, w0.x, acc[i][0]);
            acc[i][1] = fmaf(xv.x, w0.y, acc[i][1]);
            acc[i][0] = fmaf(xv.y, w1.x, acc[i][0]);
            acc[i][1] = fmaf(xv.y, w1.y, acc[i][1]);
            acc[i][0] = fmaf(xv.z, w2.x, acc[i][0]);
            acc[i][1] = fmaf(xv.z, w2.y, acc[i][1]);
            acc[i][0] = fmaf(xv.w, w3.x, acc[i][0]);
            acc[i][1] = fmaf(xv.w, w3.y, acc[i][1]);
        }
    }
    float2 bv = *(const float2*)(bias + c0);
#pragma unroll
    for (int i = 0; i < NS; i++) {
        int r = rg + 4 * i;
        float o0 = acc[i][0] + bv.x, o1 = acc[i][1] + bv.y;
        if (RELU) { o0 = fmaxf(o0, 0.f); o1 = fmaxf(o1, 0.f); }
        if (!TRANS) {
            *(float2*)(Y + r * SRW + c0) = make_float2(o0, o1);
        } else {
            Y[(c0 + 0) * SKT32 + r] = o0;
            Y[(c0 + 1) * SKT32 + r] = o1;
        }
    }
}

// ============================================================================
// mmKV<NS>: fused K^T + V projection, single X pass (for NS <= 5)
// ============================================================================
template <int NS>
__device__ __forceinline__ void mmKV(const float* X,
                                     const float* __restrict__ Wk_,
                                     const float* __restrict__ bk_,
                                     const float* __restrict__ Wv_,
                                     const float* __restrict__ bv_,
                                     float* Kt, float* V, int w, int lane)
{
    int rg = w >> 1;
    int ch = w & 1;
    int c0 = ch * 64 + lane * 2;
    float aK[NS][2], aV[NS][2];
#pragma unroll
    for (int i = 0; i < NS; i++) { aK[i][0]=0.f; aK[i][1]=0.f; aV[i][0]=0.f; aV[i][1]=0.f; }

#pragma unroll 2
    for (int kk = 0; kk < CC; kk += 4) {
        float2 k0 = *(const float2*)(Wk_ + (kk + 0) * CC + c0);
        float2 k1 = *(const float2*)(Wk_ + (kk + 1) * CC + c0);
        float2 k2 = *(const float2*)(Wk_ + (kk + 2) * CC + c0);
        float2 k3 = *(const float2*)(Wk_ + (kk + 3) * CC + c0);
        float2 v0 = *(const float2*)(Wv_ + (kk + 0) * CC + c0);
        float2 v1 = *(const float2*)(Wv_ + (kk + 1) * CC + c0);
        float2 v2 = *(const float2*)(Wv_ + (kk + 2) * CC + c0);
        float2 v3 = *(const float2*)(Wv_ + (kk + 3) * CC + c0);
#pragma unroll
        for (int i = 0; i < NS; i++) {
            float4 xv = *(const float4*)(X + (rg + 4 * i) * SRW + kk);
            aK[i][0] = fmaf(xv.x, k0.x, aK[i][0]);
            aK[i][1] = fmaf(xv.x, k0.y, aK[i][1]);
            aV[i][0] = fmaf(xv.x, v0.x, aV[i][0]);
            aV[i][1] = fmaf(xv.x, v0.y, aV[i][1]);
            aK[i][0] = fmaf(xv.y, k1.x, aK[i][0]);
            aK[i][1] = fmaf(xv.y, k1.y, aK[i][1]);
            aV[i][0] = fmaf(xv.y, v1.x, aV[i][0]);
            aV[i][1] = fmaf(xv.y, v1.y, aV[i][1]);
            aK[i][0] = fmaf(xv.z, k2.x, aK[i][0]);
            aK[i][1] = fmaf(xv.z, k2.y, aK[i][1]);
            aV[i][0] = fmaf(xv.z, v2.x, aV[i][0]);
            aV[i][1] = fmaf(xv.z, v2.y, aV[i][1]);
            aK[i][0] = fmaf(xv.w, k3.x, aK[i][0]);
            aK[i][1] = fmaf(xv.w, k3.y, aK[i][1]);
            aV[i][0] = fmaf(xv.w, v3.x, aV[i][0]);
            aV[i][1] = fmaf(xv.w, v3.y, aV[i][1]);
        }
    }
    float2 bk2 = *(const float2*)(bk_ + c0);
    float2 bv2 = *(const float2*)(bv_ + c0);
#pragma unroll
    for (int i = 0; i < NS; i++) {
        int r = rg + 4 * i;
        Kt[(c0 + 0) * SKT32 + r] = aK[i][0] + bk2.x;
        Kt[(c0 + 1) * SKT32 + r] = aK[i][1] + bk2.y;
        *(float2*)(V + r * SRW + c0) = make_float2(aV[i][0] + bv2.x, aV[i][1] + bv2.y);
    }
}

// ============================================================================
// mm64row: row-split matmul for the long (64-row) kernel
// ============================================================================
template <bool TRANS, bool RELU>
__device__ void mm64row(const float* X, const float* __restrict__ W,
                        const float* __restrict__ bias, float* Y,
                        int rows, int w, int lane)
{
    int nr = (rows > w) ? (((rows - 1 - w) >> 3) + 1) : 0;
    if (nr == 0) return;
    int c0 = lane * 4;
    float acc[8][4];
#pragma unroll
    for (int i = 0; i < 8; i++) { acc[i][0]=0.f; acc[i][1]=0.f; acc[i][2]=0.f; acc[i][3]=0.f; }

#pragma unroll 2
    for (int kk = 0; kk < CC; kk += 4) {
        float4 w0 = *(const float4*)(W + (kk + 0) * CC + c0);
        float4 w1 = *(const float4*)(W + (kk + 1) * CC + c0);
        float4 w2 = *(const float4*)(W + (kk + 2) * CC + c0);
        float4 w3 = *(const float4*)(W + (kk + 3) * CC + c0);
#pragma unroll
        for (int i = 0; i < 8; i++) {
            if (i < nr) {
                float4 xv = *(const float4*)(X + (w + 8 * i) * SR64 + kk);
                acc[i][0]=fmaf(xv.x,w0.x,acc[i][0]); acc[i][1]=fmaf(xv.x,w0.y,acc[i][1]);
                acc[i][2]=fmaf(xv.x,w0.z,acc[i][2]); acc[i][3]=fmaf(xv.x,w0.w,acc[i][3]);
                acc[i][0]=fmaf(xv.y,w1.x,acc[i][0]); acc[i][1]=fmaf(xv.y,w1.y,acc[i][1]);
                acc[i][2]=fmaf(xv.y,w1.z,acc[i][2]); acc[i][3]=fmaf(xv.y,w1.w,acc[i][3]);
                acc[i][0]=fmaf(xv.z,w2.x,acc[i][0]); acc[i][1]=fmaf(xv.z,w2.y,acc[i][1]);
                acc[i][2]=fmaf(xv.z,w2.z,acc[i][2]); acc[i][3]=fmaf(xv.z,w2.w,acc[i][3]);
                acc[i][0]=fmaf(xv.w,w3.x,acc[i][0]); acc[i][1]=fmaf(xv.w,w3.y,acc[i][1]);
                acc[i][2]=fmaf(xv.w,w3.z,acc[i][2]); acc[i][3]=fmaf(xv.w,w3.w,acc[i][3]);
            }
        }
    }
    float4 bv = *(const float4*)(bias + c0);
#pragma unroll
    for (int i = 0; i < 8; i++) {
        if (i < nr) {
            int r = w + 8 * i;
            float o0=acc[i][0]+bv.x, o1=acc[i][1]+bv.y, o2=acc[i][2]+bv.z, o3=acc[i][3]+bv.w;
            if (RELU) { o0=fmaxf(o0,0.f); o1=fmaxf(o1,0.f); o2=fmaxf(o2,0.f); o3=fmaxf(o3,0.f); }
            if (!TRANS) {
                *(float4*)(Y + r * SR64 + c0) = make_float4(o0, o1, o2, o3);
            } else {
                Y[(c0+0)*SKT64 + r]=o0; Y[(c0+1)*SKT64 + r]=o1;
                Y[(c0+2)*SKT64 + r]=o2; Y[(c0+3)*SKT64 + r]=o3;
            }
        }
    }
}

// ============================================================================
// paired encoder attention: task = (rowgroup of 4, head); windowed AV loop.
// offB is a multiple of 4 -> every task's 4 rows belong to one gene.
// Masked lanes give exactly a=0, so AV only iterates the gene's own window.
// ============================================================================
template <int KVR>
__device__ __forceinline__ void attn_pair(float* QO, const float* Kt, const float* V,
                                          int offB, int lenA, int lenB, int w, int lane)
{
    const float scale = 0.17677669529663687f;
    int lnA4 = (lenA + 3) & ~3;
    int lnB4 = (lenB + 3) & ~3;
    for (int t = w; t < KVR; t += 8) {
        int r0   = (t >> 2) * 4;
        int base = (t & 3) * 32;
        float s0 = 0.f, s1 = 0.f, s2 = 0.f, s3 = 0.f;
#pragma unroll
        for (int d = 0; d < 32; d += 4) {
            float k0 = Kt[(base + d + 0) * SKT32 + lane];
            float k1 = Kt[(base + d + 1) * SKT32 + lane];
            float k2 = Kt[(base + d + 2) * SKT32 + lane];
            float k3 = Kt[(base + d + 3) * SKT32 + lane];
            float4 qa = *(const float4*)(QO + (r0 + 0) * SRW + base + d);
            float4 qb = *(const float4*)(QO + (r0 + 1) * SRW + base + d);
            float4 qc = *(const float4*)(QO + (r0 + 2) * SRW + base + d);
            float4 qd = *(const float4*)(QO + (r0 + 3) * SRW + base + d);
            s0 = fmaf(qa.x,k0,fmaf(qa.y,k1,fmaf(qa.z,k2,fmaf(qa.w,k3,s0))));
            s1 = fmaf(qb.x,k0,fmaf(qb.y,k1,fmaf(qb.z,k2,fmaf(qb.w,k3,s1))));
            s2 = fmaf(qc.x,k0,fmaf(qc.y,k1,fmaf(qc.z,k2,fmaf(qc.w,k3,s2))));
            s3 = fmaf(qd.x,k0,fmaf(qd.y,k1,fmaf(qd.z,k2,fmaf(qd.w,k3,s3))));
        }
        bool isB = (r0 >= offB);
        int lo  = isB ? offB : 0;
        int ln  = isB ? lenB : lenA;
        int kln = isB ? lnB4 : lnA4;
        bool valid = ((unsigned)(lane - lo) < (unsigned)ln);
        s0 = valid ? s0 * scale : -1e30f;
        s1 = valid ? s1 * scale : -1e30f;
        s2 = valid ? s2 * scale : -1e30f;
        s3 = valid ? s3 * scale : -1e30f;
        float a0, a1, a2, a3;
        { float m = warp_max(s0); float p = __expf(s0 - m); a0 = p * (1.f / warp_sum(p)); }
        { float m = warp_max(s1); float p = __expf(s1 - m); a1 = p * (1.f / warp_sum(p)); }
        { float m = warp_max(s2); float p = __expf(s2 - m); a2 = p * (1.f / warp_sum(p)); }
        { float m = warp_max(s3); float p = __expf(s3 - m); a3 = p * (1.f / warp_sum(p)); }

        float o0 = 0.f, o1 = 0.f, o2 = 0.f, o3 = 0.f;
        for (int k = lo; k < lo + kln; k++) {
            float v = V[k * SRW + base + lane];
            o0 = fmaf(__shfl_sync(0xffffffffu, a0, k), v, o0);
            o1 = fmaf(__shfl_sync(0xffffffffu, a1, k), v, o1);
            o2 = fmaf(__shfl_sync(0xffffffffu, a2, k), v, o2);
            o3 = fmaf(__shfl_sync(0xffffffffu, a3, k), v, o3);
        }
        QO[(r0 + 0) * SRW + base + lane] = o0;
        QO[(r0 + 1) * SRW + base + lane] = o1;
        QO[(r0 + 2) * SRW + base + lane] = o2;
        QO[(r0 + 3) * SRW + base + lane] = o3;
    }
}

// paired PMA attention: warps 0-3 gene A heads, 4-7 gene B heads; windowed AV
__device__ __forceinline__ void attn_pma_pair(const float* Q, const float* Kt, const float* V,
                                              int gA, int gB, int offB, int lenA, int lenB,
                                              int w, int lane)
{
    const float scale = 0.17677669529663687f;
    int gi   = w >> 2;                  // 0 = gene A, 1 = gene B
    int base = (w & 3) * 32;
    float s = 0.f;
#pragma unroll
    for (int d = 0; d < 32; d += 4) {
        float4 q = *(const float4*)(Q + base + d);
        s = fmaf(q.x, Kt[(base + d + 0) * SKT32 + lane],
            fmaf(q.y, Kt[(base + d + 1) * SKT32 + lane],
            fmaf(q.z, Kt[(base + d + 2) * SKT32 + lane],
            fmaf(q.w, Kt[(base + d + 3) * SKT32 + lane], s))));
    }
    int lo  = gi ? offB : 0;
    int ln  = gi ? lenB : lenA;
    int kln = gi ? ((lenB + 3) & ~3) : ((lenA + 3) & ~3);
    s = ((unsigned)(lane - lo) < (unsigned)ln) ? s * scale : -1e30f;
    float m = warp_max(s);
    float p = __expf(s - m);
    float a = p * (1.f / warp_sum(p));
    float acc = 0.f;
    for (int k = lo; k < lo + kln; k++)
        acc = fmaf(__shfl_sync(0xffffffffu, a, k), V[k * SRW + base + lane], acc);
    int gout = gi ? gB : gA;
    if (gout >= 0) g_pma[(size_t)gout * CC + base + lane] = acc;
}

// attention (kv <= 64) for the long kernel
__device__ void attn64(const float* Q, const float* Kt, const float* V,
                       float* outp, int outStride,
                       int Lq, int len, int kvr, int w, int lane)
{
    const float scale = 0.17677669529663687f;
    int ntask = Lq * 4;
    for (int t = w; t < ntask; t += 8) {
        int r = t >> 2, base = (t & 3) * 32;
        float s0 = 0.f, s1 = 0.f;
#pragma unroll
        for (int d = 0; d < 32; d++) {
            float qd = Q[r * SR64 + base + d];
            s0 = fmaf(qd, Kt[(base + d) * SKT64 + lane], s0);
            s1 = fmaf(qd, Kt[(base + d) * SKT64 + lane + 32], s1);
        }
        s0 = (lane < len)      ? s0 * scale : -1e30f;
        s1 = (lane + 32 < len) ? s1 * scale : -1e30f;
        float m = warp_max(fmaxf(s0, s1));
        float p0 = __expf(s0 - m), p1 = __expf(s1 - m);
        float inv = 1.f / warp_sum(p0 + p1);
        float a0 = p0 * inv, a1 = p1 * inv;
        float acc = 0.f;
        int k0 = kvr < 32 ? kvr : 32;
        for (int k = 0; k < k0; k++)
            acc = fmaf(__shfl_sync(0xffffffffu, a0, k), V[k * SR64 + base + lane], acc);
        for (int k = 32; k < kvr; k++)
            acc = fmaf(__shfl_sync(0xffffffffu, a1, k - 32), V[k * SR64 + base + lane], acc);
        outp[r * outStride + base + lane] = acc;
    }
}

// ============================================================================
// LN(residual + masked A). resStride==0 -> broadcast residual.
// ============================================================================
template <int SROW>
__device__ void lnres(const float* A, const float* Res, int resStride, float* Out,
                      int rows, int qmasklen,
                      const float* __restrict__ g, const float* __restrict__ b,
                      int w, int lane)
{
    for (int r = w; r < rows; r += 8) {
        float4 a = (r < qmasklen) ? *(const float4*)(A + r * SROW + lane * 4)
                                  : make_float4(0.f, 0.f, 0.f, 0.f);
        float4 s = *(const float4*)(Res + r * resStride + lane * 4);
        float t0 = a.x + s.x, t1 = a.y + s.y, t2 = a.z + s.z, t3 = a.w + s.w;
        float sum = warp_sum(t0 + t1 + t2 + t3);
        float sq  = warp_sum(t0*t0 + t1*t1 + t2*t2 + t3*t3);
        float mean = sum * (1.f / 128.f);
        float var  = sq * (1.f / 128.f) - mean * mean;
        float rstd = rsqrtf(var + 1e-5f);
        float4 gv = *(const float4*)(g + lane * 4);
        float4 bv = *(const float4*)(b + lane * 4);
        float4 o;
        o.x = (t0 - mean) * rstd * gv.x + bv.x;
        o.y = (t1 - mean) * rstd * gv.y + bv.y;
        o.z = (t2 - mean) * rstd * gv.z + bv.z;
        o.w = (t3 - mean) * rstd * gv.w + bv.w;
        *(float4*)(Out + r * SROW + lane * 4) = o;
    }
}

// paired version: row valid if local index (relative to its gene window) < len
__device__ void lnres_pair(const float* A, const float* Res, float* Out,
                           int rows, int offB, int lenA, int lenB,
                           const float* __restrict__ g, const float* __restrict__ b,
                           int w, int lane)
{
    for (int r = w; r < rows; r += 8) {
        int lo = (r >= offB) ? offB : 0;
        int ln = (r >= offB) ? lenB : lenA;
        float4 a = ((r - lo) < ln) ? *(const float4*)(A + r * SRW + lane * 4)
                                   : make_float4(0.f, 0.f, 0.f, 0.f);
        float4 s = *(const float4*)(Res + r * SRW + lane * 4);
        float t0 = a.x + s.x, t1 = a.y + s.y, t2 = a.z + s.z, t3 = a.w + s.w;
        float sum = warp_sum(t0 + t1 + t2 + t3);
        float sq  = warp_sum(t0*t0 + t1*t1 + t2*t2 + t3*t3);
        float mean = sum * (1.f / 128.f);
        float var  = sq * (1.f / 128.f) - mean * mean;
        float rstd = rsqrtf(var + 1e-5f);
        float4 gv = *(const float4*)(g + lane * 4);
        float4 bv = *(const float4*)(b + lane * 4);
        float4 o;
        o.x = (t0 - mean) * rstd * gv.x + bv.x;
        o.y = (t1 - mean) * rstd * gv.y + bv.y;
        o.z = (t2 - mean) * rstd * gv.z + bv.z;
        o.w = (t3 - mean) * rstd * gv.w + bv.w;
        *(float4*)(Out + r * SRW + lane * 4) = o;
    }
}

// ============================================================================
// unified encoder(x2) + PMA attention for 1 or 2 genes in NS*4 rows
// ============================================================================
template <int NS>
__device__ __forceinline__ void enc_pair(
    float* Sst, float* SA, float* SB, float* SC,
    const float* __restrict__ Wq, const float* __restrict__ Wk,
    const float* __restrict__ Wv, const float* __restrict__ Wo,
    const float* __restrict__ bq, const float* __restrict__ bk,
    const float* __restrict__ bv, const float* __restrict__ bo,
    const float* __restrict__ Wlin, const float* __restrict__ blin,
    const float* __restrict__ g1, const float* __restrict__ b1,
    const float* __restrict__ g2, const float* __restrict__ b2,
    int gA, int gB, int offB, int lenA, int lenB,
    int w, int lane, int tid)
{
    constexpr int ROWS = NS * 4;
#pragma unroll 1
    for (int blk = 0; blk < 2; blk++) {
        const float* wq = Wq + blk * CC * CC;  const float* wk = Wk + blk * CC * CC;
        const float* wv = Wv + blk * CC * CC;  const float* wo = Wo + blk * CC * CC;
        const float* wl = Wlin + blk * CC * CC;
        mm32s<NS, false, false>(Sst, wq, bq + blk * CC, SA, w, lane);
        if constexpr (NS <= 5) {
            mmKV<NS>(Sst, wk, bk + blk * CC, wv, bv + blk * CC, SB, SC, w, lane);
        } else {
            mm32s<NS, true,  false>(Sst, wk, bk + blk * CC, SB, w, lane);
            mm32s<NS, false, false>(Sst, wv, bv + blk * CC, SC, w, lane);
        }
        __syncthreads();
        attn_pair<ROWS>(SA, SB, SC, offB, lenA, lenB, w, lane);
        __syncthreads();
        mm32s<NS, false, false>(SA, wo, bo + blk * CC, SB, w, lane);
        __syncthreads();
        lnres_pair(SB, Sst, Sst, ROWS, offB, lenA, lenB,
                   g1 + blk * CC, b1 + blk * CC, w, lane);
        __syncthreads();
        mm32s<NS, false, true>(Sst, wl, blin + blk * CC, SC, w, lane);
        __syncthreads();
        lnres<SRW>(SC, Sst, SRW, Sst, ROWS, ROWS, g2 + blk * CC, b2 + blk * CC, w, lane);
        __syncthreads();
    }
    if (tid < CC) SA[tid] = g_qpma[tid];
    if constexpr (NS <= 5) {
        mmKV<NS>(Sst, Wk + 2 * CC * CC, bk + 2 * CC, Wv + 2 * CC * CC, bv + 2 * CC,
                 SB, SC, w, lane);
    } else {
        mm32s<NS, true,  false>(Sst, Wk + 2 * CC * CC, bk + 2 * CC, SB, w, lane);
        mm32s<NS, false, false>(Sst, Wv + 2 * CC * CC, bv + 2 * CC, SC, w, lane);
    }
    __syncthreads();
    attn_pma_pair(SA, SB, SC, gA, gB, offB, lenA, lenB, w, lane);
}

// ============================================================================
// PACKED kernel: mid singles + pairs of small genes, 4-row granularity
// ============================================================================
__global__ __launch_bounds__(256, 3)
void gene_packed(const float* __restrict__ rf,
                 const float* __restrict__ Wq, const float* __restrict__ Wk,
                 const float* __restrict__ Wv, const float* __restrict__ Wo,
                 const float* __restrict__ bq, const float* __restrict__ bk,
                 const float* __restrict__ bv, const float* __restrict__ bo,
                 const float* __restrict__ Wlin, const float* __restrict__ blin,
                 const float* __restrict__ g1, const float* __restrict__ b1,
                 const float* __restrict__ g2, const float* __restrict__ b2,
                 const int* __restrict__ rxn_idx)
{
    extern __shared__ float sm[];
    float* Sst = sm;                    // [<=32][SRW]
    float* SA  = sm + B32;
    float* SB  = SA + B32;              // K^T [128][SKT32]
    float* SC  = SB + KT32;

    int i    = blockIdx.x;
    int tid  = threadIdx.x;
    int w    = tid >> 5;
    int lane = tid & 31;

    int nmid = g_nmid;
    int gA, gB, sA, sB, lenA, lenB;

    if (i < nmid) {
        gA = g_midlist[i];
        sA = g_starts[gA];  lenA = g_starts[gA + 1] - sA;
        gB = -1; sB = 0; lenB = 0;
    } else {
        int j = i - nmid;
        int nsmall = g_nsmall;
        if (2 * j >= nsmall) return;
        gA = g_smalllist[2 * j];
        sA = g_starts[gA];  lenA = g_starts[gA + 1] - sA;
        if (2 * j + 1 < nsmall) {
            gB = g_smalllist[2 * j + 1];
            sB = g_starts[gB];  lenB = g_starts[gB + 1] - sB;
        } else { gB = -1; sB = 0; lenB = 0; }
    }

    int offB = (lenA + 3) & ~3;
    int lenr = offB + ((lenB + 3) & ~3);     // multiple of 4, <= 32
    int NS   = lenr >> 2;                    // 1..8

    // gather
    for (int r = w; r < lenr; r += 8) {
        bool isB  = r >= offB;
        int local = isB ? (r - offB) : r;
        int ln    = isB ? lenB : lenA;
        int st    = isB ? sB   : sA;
        if (local < ln) {
            int rx = rxn_idx[st + local];
            ((float4*)(Sst + r * SRW))[lane] = ((const float4*)(rf + (size_t)rx * CC))[lane];
        } else {
            ((float4*)(Sst + r * SRW))[lane] = make_float4(0.f, 0.f, 0.f, 0.f);
        }
    }
    __syncthreads();

#define CALL_ENC(NSV) enc_pair<NSV>(Sst, SA, SB, SC, Wq, Wk, Wv, Wo, bq, bk, bv, bo, \
                                    Wlin, blin, g1, b1, g2, b2, gA, gB, offB, lenA, lenB, w, lane, tid)
    switch (NS) {
    case 1: CALL_ENC(1); break;
    case 2: CALL_ENC(2); break;
    case 3: CALL_ENC(3); break;
    case 4: CALL_ENC(4); break;
    case 5: CALL_ENC(5); break;
    case 6: CALL_ENC(6); break;
    case 7: CALL_ENC(7); break;
    default: CALL_ENC(8); break;
    }
#undef CALL_ENC
}

// ============================================================================
// LONG kernel: genes with len > 32 (rare); ends after PMA attention
// ============================================================================
__global__ __launch_bounds__(256, 1)
void gene_long64(const float* __restrict__ rf,
                 const float* __restrict__ Wq, const float* __restrict__ Wk,
                 const float* __restrict__ Wv, const float* __restrict__ Wo,
                 const float* __restrict__ bq, const float* __restrict__ bk,
                 const float* __restrict__ bv, const float* __restrict__ bo,
                 const float* __restrict__ Wlin, const float* __restrict__ blin,
                 const float* __restrict__ g1, const float* __restrict__ b1,
                 const float* __restrict__ g2, const float* __restrict__ b2,
                 const int* __restrict__ rxn_idx)
{
    extern __shared__ float sm[];
    float* Sst = sm;                    // [64][SR64]
    float* SA  = sm + B64;
    float* SB  = SA + B64;
    float* SC  = SB + KT64;

    int tid  = threadIdx.x;
    int w    = tid >> 5;
    int lane = tid & 31;
    int nlong = g_longcount;

    for (int i = blockIdx.x; i < nlong; i += gridDim.x) {
        int g     = g_longlist[i];
        int start = g_starts[g];
        int cnt   = g_starts[g + 1] - start;
        int len   = cnt < 64 ? cnt : 64;
        int lenr  = (len + 7) & ~7;
        if (lenr > 64) lenr = 64;

        for (int r = w; r < lenr; r += 8) {
            if (r < len) {
                int rx = rxn_idx[start + r];
                ((float4*)(Sst + r * SR64))[lane] = ((const float4*)(rf + (size_t)rx * CC))[lane];
            } else {
                ((float4*)(Sst + r * SR64))[lane] = make_float4(0.f, 0.f, 0.f, 0.f);
            }
        }
        __syncthreads();

        for (int blk = 0; blk < 2; blk++) {
            const float* wq = Wq + blk * CC * CC;  const float* wk = Wk + blk * CC * CC;
            const float* wv = Wv + blk * CC * CC;  const float* wo = Wo + blk * CC * CC;
            const float* wl = Wlin + blk * CC * CC;
            mm64row<false, false>(Sst, wq, bq + blk * CC, SA, lenr, w, lane);
            mm64row<true,  false>(Sst, wk, bk + blk * CC, SB, lenr, w, lane);
            mm64row<false, false>(Sst, wv, bv + blk * CC, SC, lenr, w, lane);
            __syncthreads();
            attn64(SA, SB, SC, SA, SR64, lenr, len, lenr, w, lane);
            __syncthreads();
            mm64row<false, false>(SA, wo, bo + blk * CC, SB, lenr, w, lane);
            __syncthreads();
            lnres<SR64>(SB, Sst, SR64, Sst, lenr, len, g1 + blk * CC, b1 + blk * CC, w, lane);
            __syncthreads();
            mm64row<false, true>(Sst, wl, blin + blk * CC, SC, lenr, w, lane);
            __syncthreads();
            lnres<SR64>(SC, Sst, SR64, Sst, lenr, lenr, g2 + blk * CC, b2 + blk * CC, w, lane);
            __syncthreads();
        }
        if (tid < CC) SA[tid] = g_qpma[tid];
        mm64row<true,  false>(Sst, Wk + 2 * CC * CC, bk + 2 * CC, SB, lenr, w, lane);
        mm64row<false, false>(Sst, Wv + 2 * CC * CC, bv + 2 * CC, SC, lenr, w, lane);
        __syncthreads();
        attn64(SA, SB, SC, g_pma + (size_t)g * CC, CC, 1, len, lenr, w, lane);
        __syncthreads();
    }
}

// ============================================================================
// TAIL kernel: batched PMA-projection + decoder over 32 genes per CTA
// ============================================================================
__global__ __launch_bounds__(256)
void gene_tail(const float* __restrict__ Wv, const float* __restrict__ Wo,
               const float* __restrict__ bv, const float* __restrict__ bo,
               const float* __restrict__ Wlin, const float* __restrict__ blin,
               const float* __restrict__ g1, const float* __restrict__ b1,
               const float* __restrict__ g2, const float* __restrict__ b2,
               const float* __restrict__ seed,
               float* __restrict__ out)
{
    extern __shared__ float sm[];
    float* Sst = sm;                    // [32][SRW]
    float* SA  = sm + B32;
    float* SC  = SA + B32;

    int g0   = blockIdx.x * 32;
    int tid  = threadIdx.x;
    int w    = tid >> 5;
    int lane = tid & 31;

    for (int r = w; r < 32; r += 8)
        ((float4*)(Sst + r * SRW))[lane] = ((const float4*)(g_pma + (size_t)(g0 + r) * CC))[lane];
    __syncthreads();

    mm32s<8, false, false>(Sst, Wo + 2 * CC * CC, bo + 2 * CC, SA, w, lane);
    __syncthreads();
    lnres<SRW>(SA, seed, 0, Sst, 32, 32, g1 + 2 * CC, b1 + 2 * CC, w, lane);
    __syncthreads();
    mm32s<8, false, true>(Sst, Wlin + 2 * CC * CC, blin + 2 * CC, SC, w, lane);
    __syncthreads();
    lnres<SRW>(SC, Sst, SRW, Sst, 32, 32, g2 + 2 * CC, b2 + 2 * CC, w, lane);
    __syncthreads();

    mm32s<8, false, false>(Sst, Wv + 3 * CC * CC, bv + 3 * CC, SA, w, lane);
    __syncthreads();
    mm32s<8, false, false>(SA, Wo + 3 * CC * CC, bo + 3 * CC, SC, w, lane);
    __syncthreads();
    lnres<SRW>(SC, Sst, SRW, Sst, 32, 32, g1 + 3 * CC, b1 + 3 * CC, w, lane);
    __syncthreads();
    mm32s<8, false, true>(Sst, Wlin + 3 * CC * CC, blin + 3 * CC, SC, w, lane);
    __syncthreads();
    lnres<SRW>(SC, Sst, SRW, Sst, 32, 32, g2 + 3 * CC, b2 + 3 * CC, w, lane);
    __syncthreads();

    for (int r = w; r < 32; r += 8) {
        float4 v = ((const float4*)(Sst + r * SRW))[lane];
        float o[4] = {v.x, v.y, v.z, v.w};
#pragma unroll
        for (int j = 0; j < 4; j++) {
            float x = o[j];
            if (x != x) x = 0.f;
            x = fminf(fmaxf(x, -3.402823466e38f), 3.402823466e38f);
            o[j] = x;
        }
        ((float4*)(out + (size_t)(g0 + r) * CC))[lane] = make_float4(o[0], o[1], o[2], o[3]);
    }
}

extern "C" void kernel_launch(void* const* d_in, const int* in_sizes, int n_in,
                              void* d_out, int out_size)
{
    const float* rf   = (const float*)d_in[0];
    const float* Wq   = (const float*)d_in[1];
    const float* Wk   = (const float*)d_in[2];
    const float* Wv   = (const float*)d_in[3];
    const float* Wo   = (const float*)d_in[4];
    const float* bq   = (const float*)d_in[5];
    const float* bk   = (const float*)d_in[6];
    const float* bv   = (const float*)d_in[7];
    const float* bo   = (const float*)d_in[8];
    const float* Wlin = (const float*)d_in[9];
    const float* blin = (const float*)d_in[10];
    const float* g1   = (const float*)d_in[11];
    const float* b1   = (const float*)d_in[12];
    const float* g2   = (const float*)d_in[13];
    const float* b2   = (const float*)d_in[14];
    const float* seed = (const float*)d_in[15];
    const int*   rxn  = (const int*)d_in[16];
    const int*   gidx = (const int*)d_in[17];
    int E = in_sizes[16];

    cudaFuncSetAttribute(gene_packed, cudaFuncAttributeMaxDynamicSharedMemorySize, SM32_BYTES);
    cudaFuncSetAttribute(gene_long64, cudaFuncAttributeMaxDynamicSharedMemorySize, SM64_BYTES);
    cudaFuncSetAttribute(gene_tail,   cudaFuncAttributeMaxDynamicSharedMemorySize, SMT_BYTES);

    seg_bounds_kernel<<<(E + 255) / 256, 256>>>(gidx, E);
    classify_kernel<<<(GENES + 255) / 256, 256>>>();
    prep_qpma_kernel<<<1, 128>>>(Wq, bq, seed);
    gene_packed<<<GENES, 256, SM32_BYTES>>>(rf, Wq, Wk, Wv, Wo, bq, bk, bv, bo,
                                            Wlin, blin, g1, b1, g2, b2, rxn);
    gene_long64<<<128, 256, SM64_BYTES>>>(rf, Wq, Wk, Wv, Wo, bq, bk, bv, bo,
                                          Wlin, blin, g1, b1, g2, b2, rxn);
    gene_tail<<<GENES / 32, 256, SMT_BYTES>>>(Wv, Wo, bv, bo, Wlin, blin,
                                              g1, b1, g2, b2, seed, (float*)d_out);
}

// round 15
// speedup vs baseline: 1.3035x; 1.0246x over previous
#include <cuda_runtime.h>
#include <math.h>

#define CC    128
#define GENES 4096
#define SRW   132                 // row stride (floats)

// ---- 32-row packed kernel geometry ----
#define SKT32 33
#define B32   (32 * SRW)          // 4224 floats
#define KT32  (128 * SKT32)       // 4224 floats
#define SM32_BYTES ((3 * B32 + KT32) * 4)   // 67,584 B -> 3 CTAs/SM

// ---- long (len>32) kernel geometry ----
#define SR64  136
#define SKT64 69
#define B64   (64 * SR64)
#define KT64  (128 * SKT64)
#define SM64_BYTES ((3 * B64 + KT64) * 4)

// ---- tail kernel ----
#define SMT_BYTES (3 * B32 * 4)

#define MAXPLAN 64

__device__ int   g_starts[GENES + 1];
__device__ int   g_longcount;
__device__ int   g_longlist[GENES];
__device__ int   g_bcnt[9];               // bucket counts, b = 1..8 (r4 = 4b)
__device__ int   g_bucketbuf[9 * GENES];
__device__ int   g_ncta;
__device__ int   g_ctaA[GENES];
__device__ int   g_ctaB[GENES];
__device__ float g_qpma[CC];              // seed @ Wq[2] + bq[2]
__device__ float g_pma[GENES * CC];       // PMA attention output per gene

__device__ __forceinline__ float warp_sum(float v) {
#pragma unroll
    for (int o = 16; o; o >>= 1) v += __shfl_xor_sync(0xffffffffu, v, o);
    return v;
}
__device__ __forceinline__ float warp_max(float v) {
#pragma unroll
    for (int o = 16; o; o >>= 1) v = fmaxf(v, __shfl_xor_sync(0xffffffffu, v, o));
    return v;
}

// ============================================================================
// bounds + classify + pack + PMA-Q precompute
// ============================================================================
__global__ void seg_bounds_kernel(const int* __restrict__ gene_idx, int E)
{
    int e = blockIdx.x * 256 + threadIdx.x;
    if (e == 0) {
        g_starts[GENES] = E; g_longcount = 0;
        for (int b = 0; b < 9; b++) g_bcnt[b] = 0;
    }
    if (e < E) {
        int gi = gene_idx[e];
        if (e == 0 || gene_idx[e - 1] != gi) g_starts[gi] = e;
    }
}

__global__ void classify_kernel()
{
    int g = blockIdx.x * 256 + threadIdx.x;
    if (g < GENES) {
        int len = g_starts[g + 1] - g_starts[g];
        if (len > 32) {
            int p = atomicAdd(&g_longcount, 1); g_longlist[p] = g;
        } else {
            int b = (len + 3) >> 2;             // 1..8
            int p = atomicAdd(&g_bcnt[b], 1);
            g_bucketbuf[b * GENES + p] = g;
        }
    }
}

// single block: thread 0 builds a pairing plan over bucket counts, all threads emit
__global__ void pack_kernel()
{
    __shared__ int pAb[MAXPLAN], pAo[MAXPLAN], pBb[MAXPLAN], pBo[MAXPLAN];
    __shared__ int pCnt[MAXPLAN], pBase[MAXPLAN];
    __shared__ int s_nplan;

    int tid = threadIdx.x;
    if (tid == 0) {
        int rem[9], used[9];
        for (int b = 0; b < 9; b++) { rem[b] = g_bcnt[b]; used[b] = 0; }
        int np = 0, ncta = 0;
        for (int b = 8; b >= 1; b--) {
            while (rem[b] > 0) {
                int cap = 8 - b;
                int b2 = -1;
                int chi = cap < 8 ? cap : 8;
                for (int c = chi; c >= 1; c--) {
                    if (c == b) { if (rem[b] >= 2) { b2 = c; break; } }
                    else        { if (rem[c] > 0)  { b2 = c; break; } }
                }
                if (b2 < 0) {                       // emit alone
                    pAb[np] = b; pAo[np] = used[b]; pBb[np] = -1; pBo[np] = 0;
                    pCnt[np] = rem[b]; pBase[np] = ncta;
                    ncta += rem[b]; used[b] += rem[b]; rem[b] = 0; np++;
                } else if (b2 == b) {               // self-pair
                    int m = rem[b] >> 1;
                    pAb[np] = b; pAo[np] = used[b];
                    pBb[np] = b; pBo[np] = used[b] + m;
                    pCnt[np] = m; pBase[np] = ncta;
                    ncta += m; used[b] += 2 * m; rem[b] -= 2 * m; np++;
                    if (rem[b] == 1) {
                        pAb[np] = b; pAo[np] = used[b]; pBb[np] = -1; pBo[np] = 0;
                        pCnt[np] = 1; pBase[np] = ncta;
                        ncta += 1; used[b] += 1; rem[b] = 0; np++;
                    }
                } else {                            // cross-bucket pair
                    int m = rem[b] < rem[b2] ? rem[b] : rem[b2];
                    pAb[np] = b;  pAo[np] = used[b];
                    pBb[np] = b2; pBo[np] = used[b2];
                    pCnt[np] = m; pBase[np] = ncta;
                    ncta += m; used[b] += m; used[b2] += m;
                    rem[b] -= m; rem[b2] -= m; np++;
                }
            }
        }
        s_nplan = np;
        g_ncta = ncta;
    }
    __syncthreads();
    int np = s_nplan;
    for (int e = 0; e < np; e++) {
        int cnt = pCnt[e];
        for (int k = tid; k < cnt; k += 256) {
            g_ctaA[pBase[e] + k] = g_bucketbuf[pAb[e] * GENES + pAo[e] + k];
            g_ctaB[pBase[e] + k] = (pBb[e] >= 0)
                ? g_bucketbuf[pBb[e] * GENES + pBo[e] + k] : -1;
        }
    }
}

__global__ void prep_qpma_kernel(const float* __restrict__ Wq,
                                 const float* __restrict__ bq,
                                 const float* __restrict__ seed)
{
    int c = threadIdx.x;                       // 128 threads
    float acc = bq[2 * CC + c];
    const float* W2 = Wq + 2 * CC * CC;
#pragma unroll 8
    for (int k = 0; k < CC; k++) acc = fmaf(seed[k], W2[k * CC + c], acc);
    g_qpma[c] = acc;
}

// ============================================================================
// mm32s<NS>: X[NS*4 rows,128] @ W + b -> Y. 8 warps = 4 row-groups x 2 halves.
// ============================================================================
template <int NS, bool TRANS, bool RELU>
__device__ __forceinline__ void mm32s(const float* X, const float* __restrict__ W,
                                      const float* __restrict__ bias, float* Y,
                                      int w, int lane)
{
    int rg = w >> 1;
    int ch = w & 1;
    int c0 = ch * 64 + lane * 2;
    float acc[NS][2];
#pragma unroll
    for (int i = 0; i < NS; i++) { acc[i][0] = 0.f; acc[i][1] = 0.f; }

#pragma unroll 2
    for (int kk = 0; kk < CC; kk += 4) {
        float2 w0 = *(const float2*)(W + (kk + 0) * CC + c0);
        float2 w1 = *(const float2*)(W + (kk + 1) * CC + c0);
        float2 w2 = *(const float2*)(W + (kk + 2) * CC + c0);
        float2 w3 = *(const float2*)(W + (kk + 3) * CC + c0);
#pragma unroll
        for (int i = 0; i < NS; i++) {
            float4 xv = *(const float4*)(X + (rg + 4 * i) * SRW + kk);
            acc[i][0] = fmaf(xv.x, w0.x, acc[i][0]);
            acc[i][1] = fmaf(xv.x, w0.y, acc[i][1]);
            acc[i][0] = fmaf(xv.y, w1.x, acc[i][0]);
            acc[i][1] = fmaf(xv.y, w1.y, acc[i][1]);
            acc[i][0] = fmaf(xv.z, w2.x, acc[i][0]);
            acc[i][1] = fmaf(xv.z, w2.y, acc[i][1]);
            acc[i][0] = fmaf(xv.w, w3.x, acc[i][0]);
            acc[i][1] = fmaf(xv.w, w3.y, acc[i][1]);
        }
    }
    float2 bv = *(const float2*)(bias + c0);
#pragma unroll
    for (int i = 0; i < NS; i++) {
        int r = rg + 4 * i;
        float o0 = acc[i][0] + bv.x, o1 = acc[i][1] + bv.y;
        if (RELU) { o0 = fmaxf(o0, 0.f); o1 = fmaxf(o1, 0.f); }
        if (!TRANS) {
            *(float2*)(Y + r * SRW + c0) = make_float2(o0, o1);
        } else {
            Y[(c0 + 0) * SKT32 + r] = o0;
            Y[(c0 + 1) * SKT32 + r] = o1;
        }
    }
}

// ============================================================================
// mmKV<NS>: fused K^T + V projection, single X pass (for NS <= 5)
// ============================================================================
template <int NS>
__device__ __forceinline__ void mmKV(const float* X,
                                     const float* __restrict__ Wk_,
                                     const float* __restrict__ bk_,
                                     const float* __restrict__ Wv_,
                                     const float* __restrict__ bv_,
                                     float* Kt, float* V, int w, int lane)
{
    int rg = w >> 1;
    int ch = w & 1;
    int c0 = ch * 64 + lane * 2;
    float aK[NS][2], aV[NS][2];
#pragma unroll
    for (int i = 0; i < NS; i++) { aK[i][0]=0.f; aK[i][1]=0.f; aV[i][0]=0.f; aV[i][1]=0.f; }

#pragma unroll 2
    for (int kk = 0; kk < CC; kk += 4) {
        float2 k0 = *(const float2*)(Wk_ + (kk + 0) * CC + c0);
        float2 k1 = *(const float2*)(Wk_ + (kk + 1) * CC + c0);
        float2 k2 = *(const float2*)(Wk_ + (kk + 2) * CC + c0);
        float2 k3 = *(const float2*)(Wk_ + (kk + 3) * CC + c0);
        float2 v0 = *(const float2*)(Wv_ + (kk + 0) * CC + c0);
        float2 v1 = *(const float2*)(Wv_ + (kk + 1) * CC + c0);
        float2 v2 = *(const float2*)(Wv_ + (kk + 2) * CC + c0);
        float2 v3 = *(const float2*)(Wv_ + (kk + 3) * CC + c0);
#pragma unroll
        for (int i = 0; i < NS; i++) {
            float4 xv = *(const float4*)(X + (rg + 4 * i) * SRW + kk);
            aK[i][0] = fmaf(xv.x, k0.x, aK[i][0]);
            aK[i][1] = fmaf(xv.x, k0.y, aK[i][1]);
            aV[i][0] = fmaf(xv.x, v0.x, aV[i][0]);
            aV[i][1] = fmaf(xv.x, v0.y, aV[i][1]);
            aK[i][0] = fmaf(xv.y, k1.x, aK[i][0]);
            aK[i][1] = fmaf(xv.y, k1.y, aK[i][1]);
            aV[i][0] = fmaf(xv.y, v1.x, aV[i][0]);
            aV[i][1] = fmaf(xv.y, v1.y, aV[i][1]);
            aK[i][0] = fmaf(xv.z, k2.x, aK[i][0]);
            aK[i][1] = fmaf(xv.z, k2.y, aK[i][1]);
            aV[i][0] = fmaf(xv.z, v2.x, aV[i][0]);
            aV[i][1] = fmaf(xv.z, v2.y, aV[i][1]);
            aK[i][0] = fmaf(xv.w, k3.x, aK[i][0]);
            aK[i][1] = fmaf(xv.w, k3.y, aK[i][1]);
            aV[i][0] = fmaf(xv.w, v3.x, aV[i][0]);
            aV[i][1] = fmaf(xv.w, v3.y, aV[i][1]);
        }
    }
    float2 bk2 = *(const float2*)(bk_ + c0);
    float2 bv2 = *(const float2*)(bv_ + c0);
#pragma unroll
    for (int i = 0; i < NS; i++) {
        int r = rg + 4 * i;
        Kt[(c0 + 0) * SKT32 + r] = aK[i][0] + bk2.x;
        Kt[(c0 + 1) * SKT32 + r] = aK[i][1] + bk2.y;
        *(float2*)(V + r * SRW + c0) = make_float2(aV[i][0] + bv2.x, aV[i][1] + bv2.y);
    }
}

// ============================================================================
// mm64row: row-split matmul for the long (64-row) kernel
// ============================================================================
template <bool TRANS, bool RELU>
__device__ void mm64row(const float* X, const float* __restrict__ W,
                        const float* __restrict__ bias, float* Y,
                        int rows, int w, int lane)
{
    int nr = (rows > w) ? (((rows - 1 - w) >> 3) + 1) : 0;
    if (nr == 0) return;
    int c0 = lane * 4;
    float acc[8][4];
#pragma unroll
    for (int i = 0; i < 8; i++) { acc[i][0]=0.f; acc[i][1]=0.f; acc[i][2]=0.f; acc[i][3]=0.f; }

#pragma unroll 2
    for (int kk = 0; kk < CC; kk += 4) {
        float4 w0 = *(const float4*)(W + (kk + 0) * CC + c0);
        float4 w1 = *(const float4*)(W + (kk + 1) * CC + c0);
        float4 w2 = *(const float4*)(W + (kk + 2) * CC + c0);
        float4 w3 = *(const float4*)(W + (kk + 3) * CC + c0);
#pragma unroll
        for (int i = 0; i < 8; i++) {
            if (i < nr) {
                float4 xv = *(const float4*)(X + (w + 8 * i) * SR64 + kk);
                acc[i][0]=fmaf(xv.x,w0.x,acc[i][0]); acc[i][1]=fmaf(xv.x,w0.y,acc[i][1]);
                acc[i][2]=fmaf(xv.x,w0.z,acc[i][2]); acc[i][3]=fmaf(xv.x,w0.w,acc[i][3]);
                acc[i][0]=fmaf(xv.y,w1.x,acc[i][0]); acc[i][1]=fmaf(xv.y,w1.y,acc[i][1]);
                acc[i][2]=fmaf(xv.y,w1.z,acc[i][2]); acc[i][3]=fmaf(xv.y,w1.w,acc[i][3]);
                acc[i][0]=fmaf(xv.z,w2.x,acc[i][0]); acc[i][1]=fmaf(xv.z,w2.y,acc[i][1]);
                acc[i][2]=fmaf(xv.z,w2.z,acc[i][2]); acc[i][3]=fmaf(xv.z,w2.w,acc[i][3]);
                acc[i][0]=fmaf(xv.w,w3.x,acc[i][0]); acc[i][1]=fmaf(xv.w,w3.y,acc[i][1]);
                acc[i][2]=fmaf(xv.w,w3.z,acc[i][2]); acc[i][3]=fmaf(xv.w,w3.w,acc[i][3]);
            }
        }
    }
    float4 bv = *(const float4*)(bias + c0);
#pragma unroll
    for (int i = 0; i < 8; i++) {
        if (i < nr) {
            int r = w + 8 * i;
            float o0=acc[i][0]+bv.x, o1=acc[i][1]+bv.y, o2=acc[i][2]+bv.z, o3=acc[i][3]+bv.w;
            if (RELU) { o0=fmaxf(o0,0.f); o1=fmaxf(o1,0.f); o2=fmaxf(o2,0.f); o3=fmaxf(o3,0.f); }
            if (!TRANS) {
                *(float4*)(Y + r * SR64 + c0) = make_float4(o0, o1, o2, o3);
            } else {
                Y[(c0+0)*SKT64 + r]=o0; Y[(c0+1)*SKT64 + r]=o1;
                Y[(c0+2)*SKT64 + r]=o2; Y[(c0+3)*SKT64 + r]=o3;
            }
        }
    }
}

// ============================================================================
// paired encoder attention: task = (rowgroup of 4, head); windowed AV loop.
// ============================================================================
template <int KVR>
__device__ __forceinline__ void attn_pair(float* QO, const float* Kt, const float* V,
                                          int offB, int lenA, int lenB, int w, int lane)
{
    const float scale = 0.17677669529663687f;
    int lnA4 = (lenA + 3) & ~3;
    int lnB4 = (lenB + 3) & ~3;
    for (int t = w; t < KVR; t += 8) {
        int r0   = (t >> 2) * 4;
        int base = (t & 3) * 32;
        float s0 = 0.f, s1 = 0.f, s2 = 0.f, s3 = 0.f;
#pragma unroll
        for (int d = 0; d < 32; d += 4) {
            float k0 = Kt[(base + d + 0) * SKT32 + lane];
            float k1 = Kt[(base + d + 1) * SKT32 + lane];
            float k2 = Kt[(base + d + 2) * SKT32 + lane];
            float k3 = Kt[(base + d + 3) * SKT32 + lane];
            float4 qa = *(const float4*)(QO + (r0 + 0) * SRW + base + d);
            float4 qb = *(const float4*)(QO + (r0 + 1) * SRW + base + d);
            float4 qc = *(const float4*)(QO + (r0 + 2) * SRW + base + d);
            float4 qd = *(const float4*)(QO + (r0 + 3) * SRW + base + d);
            s0 = fmaf(qa.x,k0,fmaf(qa.y,k1,fmaf(qa.z,k2,fmaf(qa.w,k3,s0))));
            s1 = fmaf(qb.x,k0,fmaf(qb.y,k1,fmaf(qb.z,k2,fmaf(qb.w,k3,s1))));
            s2 = fmaf(qc.x,k0,fmaf(qc.y,k1,fmaf(qc.z,k2,fmaf(qc.w,k3,s2))));
            s3 = fmaf(qd.x,k0,fmaf(qd.y,k1,fmaf(qd.z,k2,fmaf(qd.w,k3,s3))));
        }
        bool isB = (r0 >= offB);
        int lo  = isB ? offB : 0;
        int ln  = isB ? lenB : lenA;
        int kln = isB ? lnB4 : lnA4;
        bool valid = ((unsigned)(lane - lo) < (unsigned)ln);
        s0 = valid ? s0 * scale : -1e30f;
        s1 = valid ? s1 * scale : -1e30f;
        s2 = valid ? s2 * scale : -1e30f;
        s3 = valid ? s3 * scale : -1e30f;
        float a0, a1, a2, a3;
        { float m = warp_max(s0); float p = __expf(s0 - m); a0 = p * (1.f / warp_sum(p)); }
        { float m = warp_max(s1); float p = __expf(s1 - m); a1 = p * (1.f / warp_sum(p)); }
        { float m = warp_max(s2); float p = __expf(s2 - m); a2 = p * (1.f / warp_sum(p)); }
        { float m = warp_max(s3); float p = __expf(s3 - m); a3 = p * (1.f / warp_sum(p)); }

        float o0 = 0.f, o1 = 0.f, o2 = 0.f, o3 = 0.f;
        for (int k = lo; k < lo + kln; k++) {
            float v = V[k * SRW + base + lane];
            o0 = fmaf(__shfl_sync(0xffffffffu, a0, k), v, o0);
            o1 = fmaf(__shfl_sync(0xffffffffu, a1, k), v, o1);
            o2 = fmaf(__shfl_sync(0xffffffffu, a2, k), v, o2);
            o3 = fmaf(__shfl_sync(0xffffffffu, a3, k), v, o3);
        }
        QO[(r0 + 0) * SRW + base + lane] = o0;
        QO[(r0 + 1) * SRW + base + lane] = o1;
        QO[(r0 + 2) * SRW + base + lane] = o2;
        QO[(r0 + 3) * SRW + base + lane] = o3;
    }
}

// paired PMA attention: warps 0-3 gene A heads, 4-7 gene B heads; windowed AV
__device__ __forceinline__ void attn_pma_pair(const float* Q, const float* Kt, const float* V,
                                              int gA, int gB, int offB, int lenA, int lenB,
                                              int w, int lane)
{
    const float scale = 0.17677669529663687f;
    int gi   = w >> 2;                  // 0 = gene A, 1 = gene B
    int base = (w & 3) * 32;
    float s = 0.f;
#pragma unroll
    for (int d = 0; d < 32; d += 4) {
        float4 q = *(const float4*)(Q + base + d);
        s = fmaf(q.x, Kt[(base + d + 0) * SKT32 + lane],
            fmaf(q.y, Kt[(base + d + 1) * SKT32 + lane],
            fmaf(q.z, Kt[(base + d + 2) * SKT32 + lane],
            fmaf(q.w, Kt[(base + d + 3) * SKT32 + lane], s))));
    }
    int lo  = gi ? offB : 0;
    int ln  = gi ? lenB : lenA;
    int kln = gi ? ((lenB + 3) & ~3) : ((lenA + 3) & ~3);
    s = ((unsigned)(lane - lo) < (unsigned)ln) ? s * scale : -1e30f;
    float m = warp_max(s);
    float p = __expf(s - m);
    float a = p * (1.f / warp_sum(p));
    float acc = 0.f;
    for (int k = lo; k < lo + kln; k++)
        acc = fmaf(__shfl_sync(0xffffffffu, a, k), V[k * SRW + base + lane], acc);
    int gout = gi ? gB : gA;
    if (gout >= 0) g_pma[(size_t)gout * CC + base + lane] = acc;
}

// attention (kv <= 64) for the long kernel
__device__ void attn64(const float* Q, const float* Kt, const float* V,
                       float* outp, int outStride,
                       int Lq, int len, int kvr, int w, int lane)
{
    const float scale = 0.17677669529663687f;
    int ntask = Lq * 4;
    for (int t = w; t < ntask; t += 8) {
        int r = t >> 2, base = (t & 3) * 32;
        float s0 = 0.f, s1 = 0.f;
#pragma unroll
        for (int d = 0; d < 32; d++) {
            float qd = Q[r * SR64 + base + d];
            s0 = fmaf(qd, Kt[(base + d) * SKT64 + lane], s0);
            s1 = fmaf(qd, Kt[(base + d) * SKT64 + lane + 32], s1);
        }
        s0 = (lane < len)      ? s0 * scale : -1e30f;
        s1 = (lane + 32 < len) ? s1 * scale : -1e30f;
        float m = warp_max(fmaxf(s0, s1));
        float p0 = __expf(s0 - m), p1 = __expf(s1 - m);
        float inv = 1.f / warp_sum(p0 + p1);
        float a0 = p0 * inv, a1 = p1 * inv;
        float acc = 0.f;
        int k0 = kvr < 32 ? kvr : 32;
        for (int k = 0; k < k0; k++)
            acc = fmaf(__shfl_sync(0xffffffffu, a0, k), V[k * SR64 + base + lane], acc);
        for (int k = 32; k < kvr; k++)
            acc = fmaf(__shfl_sync(0xffffffffu, a1, k - 32), V[k * SR64 + base + lane], acc);
        outp[r * outStride + base + lane] = acc;
    }
}

// ============================================================================
// LN(residual + masked A). resStride==0 -> broadcast residual.
// ============================================================================
template <int SROW>
__device__ void lnres(const float* A, const float* Res, int resStride, float* Out,
                      int rows, int qmasklen,
                      const float* __restrict__ g, const float* __restrict__ b,
                      int w, int lane)
{
    for (int r = w; r < rows; r += 8) {
        float4 a = (r < qmasklen) ? *(const float4*)(A + r * SROW + lane * 4)
                                  : make_float4(0.f, 0.f, 0.f, 0.f);
        float4 s = *(const float4*)(Res + r * resStride + lane * 4);
        float t0 = a.x + s.x, t1 = a.y + s.y, t2 = a.z + s.z, t3 = a.w + s.w;
        float sum = warp_sum(t0 + t1 + t2 + t3);
        float sq  = warp_sum(t0*t0 + t1*t1 + t2*t2 + t3*t3);
        float mean = sum * (1.f / 128.f);
        float var  = sq * (1.f / 128.f) - mean * mean;
        float rstd = rsqrtf(var + 1e-5f);
        float4 gv = *(const float4*)(g + lane * 4);
        float4 bv = *(const float4*)(b + lane * 4);
        float4 o;
        o.x = (t0 - mean) * rstd * gv.x + bv.x;
        o.y = (t1 - mean) * rstd * gv.y + bv.y;
        o.z = (t2 - mean) * rstd * gv.z + bv.z;
        o.w = (t3 - mean) * rstd * gv.w + bv.w;
        *(float4*)(Out + r * SROW + lane * 4) = o;
    }
}

// paired version: row valid if local index (relative to its gene window) < len
__device__ void lnres_pair(const float* A, const float* Res, float* Out,
                           int rows, int offB, int lenA, int lenB,
                           const float* __restrict__ g, const float* __restrict__ b,
                           int w, int lane)
{
    for (int r = w; r < rows; r += 8) {
        int lo = (r >= offB) ? offB : 0;
        int ln = (r >= offB) ? lenB : lenA;
        float4 a = ((r - lo) < ln) ? *(const float4*)(A + r * SRW + lane * 4)
                                   : make_float4(0.f, 0.f, 0.f, 0.f);
        float4 s = *(const float4*)(Res + r * SRW + lane * 4);
        float t0 = a.x + s.x, t1 = a.y + s.y, t2 = a.z + s.z, t3 = a.w + s.w;
        float sum = warp_sum(t0 + t1 + t2 + t3);
        float sq  = warp_sum(t0*t0 + t1*t1 + t2*t2 + t3*t3);
        float mean = sum * (1.f / 128.f);
        float var  = sq * (1.f / 128.f) - mean * mean;
        float rstd = rsqrtf(var + 1e-5f);
        float4 gv = *(const float4*)(g + lane * 4);
        float4 bv = *(const float4*)(b + lane * 4);
        float4 o;
        o.x = (t0 - mean) * rstd * gv.x + bv.x;
        o.y = (t1 - mean) * rstd * gv.y + bv.y;
        o.z = (t2 - mean) * rstd * gv.z + bv.z;
        o.w = (t3 - mean) * rstd * gv.w + bv.w;
        *(float4*)(Out + r * SRW + lane * 4) = o;
    }
}

// ============================================================================
// unified encoder(x2) + PMA attention for 1 or 2 genes in NS*4 rows
// ============================================================================
template <int NS>
__device__ __forceinline__ void enc_pair(
    float* Sst, float* SA, float* SB, float* SC,
    const float* __restrict__ Wq, const float* __restrict__ Wk,
    const float* __restrict__ Wv, const float* __restrict__ Wo,
    const float* __restrict__ bq, const float* __restrict__ bk,
    const float* __restrict__ bv, const float* __restrict__ bo,
    const float* __restrict__ Wlin, const float* __restrict__ blin,
    const float* __restrict__ g1, const float* __restrict__ b1,
    const float* __restrict__ g2, const float* __restrict__ b2,
    int gA, int gB, int offB, int lenA, int lenB,
    int w, int lane, int tid)
{
    constexpr int ROWS = NS * 4;
#pragma unroll 1
    for (int blk = 0; blk < 2; blk++) {
        const float* wq = Wq + blk * CC * CC;  const float* wk = Wk + blk * CC * CC;
        const float* wv = Wv + blk * CC * CC;  const float* wo = Wo + blk * CC * CC;
        const float* wl = Wlin + blk * CC * CC;
        mm32s<NS, false, false>(Sst, wq, bq + blk * CC, SA, w, lane);
        if constexpr (NS <= 5) {
            mmKV<NS>(Sst, wk, bk + blk * CC, wv, bv + blk * CC, SB, SC, w, lane);
        } else {
            mm32s<NS, true,  false>(Sst, wk, bk + blk * CC, SB, w, lane);
            mm32s<NS, false, false>(Sst, wv, bv + blk * CC, SC, w, lane);
        }
        __syncthreads();
        attn_pair<ROWS>(SA, SB, SC, offB, lenA, lenB, w, lane);
        __syncthreads();
        mm32s<NS, false, false>(SA, wo, bo + blk * CC, SB, w, lane);
        __syncthreads();
        lnres_pair(SB, Sst, Sst, ROWS, offB, lenA, lenB,
                   g1 + blk * CC, b1 + blk * CC, w, lane);
        __syncthreads();
        mm32s<NS, false, true>(Sst, wl, blin + blk * CC, SC, w, lane);
        __syncthreads();
        lnres<SRW>(SC, Sst, SRW, Sst, ROWS, ROWS, g2 + blk * CC, b2 + blk * CC, w, lane);
        __syncthreads();
    }
    if (tid < CC) SA[tid] = g_qpma[tid];
    if constexpr (NS <= 5) {
        mmKV<NS>(Sst, Wk + 2 * CC * CC, bk + 2 * CC, Wv + 2 * CC * CC, bv + 2 * CC,
                 SB, SC, w, lane);
    } else {
        mm32s<NS, true,  false>(Sst, Wk + 2 * CC * CC, bk + 2 * CC, SB, w, lane);
        mm32s<NS, false, false>(Sst, Wv + 2 * CC * CC, bv + 2 * CC, SC, w, lane);
    }
    __syncthreads();
    attn_pma_pair(SA, SB, SC, gA, gB, offB, lenA, lenB, w, lane);
}

// ============================================================================
// PACKED kernel: bin-packed 1-2 genes per CTA (worklist from pack_kernel)
// ============================================================================
__global__ __launch_bounds__(256, 3)
void gene_packed(const float* __restrict__ rf,
                 const float* __restrict__ Wq, const float* __restrict__ Wk,
                 const float* __restrict__ Wv, const float* __restrict__ Wo,
                 const float* __restrict__ bq, const float* __restrict__ bk,
                 const float* __restrict__ bv, const float* __restrict__ bo,
                 const float* __restrict__ Wlin, const float* __restrict__ blin,
                 const float* __restrict__ g1, const float* __restrict__ b1,
                 const float* __restrict__ g2, const float* __restrict__ b2,
                 const int* __restrict__ rxn_idx)
{
    extern __shared__ float sm[];
    float* Sst = sm;                    // [<=32][SRW]
    float* SA  = sm + B32;
    float* SB  = SA + B32;              // K^T [128][SKT32]
    float* SC  = SB + KT32;

    int i    = blockIdx.x;
    if (i >= g_ncta) return;
    int tid  = threadIdx.x;
    int w    = tid >> 5;
    int lane = tid & 31;

    int gA = g_ctaA[i];
    int gB = g_ctaB[i];
    int sA = g_starts[gA];
    int lenA = g_starts[gA + 1] - sA;
    int sB = 0, lenB = 0;
    if (gB >= 0) { sB = g_starts[gB]; lenB = g_starts[gB + 1] - sB; }

    int offB = (lenA + 3) & ~3;
    int lenr = offB + ((lenB + 3) & ~3);     // multiple of 4, <= 32
    int NS   = lenr >> 2;                    // 1..8

    // gather
    for (int r = w; r < lenr; r += 8) {
        bool isB  = r >= offB;
        int local = isB ? (r - offB) : r;
        int ln    = isB ? lenB : lenA;
        int st    = isB ? sB   : sA;
        if (local < ln) {
            int rx = rxn_idx[st + local];
            ((float4*)(Sst + r * SRW))[lane] = ((const float4*)(rf + (size_t)rx * CC))[lane];
        } else {
            ((float4*)(Sst + r * SRW))[lane] = make_float4(0.f, 0.f, 0.f, 0.f);
        }
    }
    __syncthreads();

#define CALL_ENC(NSV) enc_pair<NSV>(Sst, SA, SB, SC, Wq, Wk, Wv, Wo, bq, bk, bv, bo, \
                                    Wlin, blin, g1, b1, g2, b2, gA, gB, offB, lenA, lenB, w, lane, tid)
    switch (NS) {
    case 1: CALL_ENC(1); break;
    case 2: CALL_ENC(2); break;
    case 3: CALL_ENC(3); break;
    case 4: CALL_ENC(4); break;
    case 5: CALL_ENC(5); break;
    case 6: CALL_ENC(6); break;
    case 7: CALL_ENC(7); break;
    default: CALL_ENC(8); break;
    }
#undef CALL_ENC
}

// ============================================================================
// LONG kernel: genes with len > 32 (rare); ends after PMA attention
// ============================================================================
__global__ __launch_bounds__(256, 1)
void gene_long64(const float* __restrict__ rf,
                 const float* __restrict__ Wq, const float* __restrict__ Wk,
                 const float* __restrict__ Wv, const float* __restrict__ Wo,
                 const float* __restrict__ bq, const float* __restrict__ bk,
                 const float* __restrict__ bv, const float* __restrict__ bo,
                 const float* __restrict__ Wlin, const float* __restrict__ blin,
                 const float* __restrict__ g1, const float* __restrict__ b1,
                 const float* __restrict__ g2, const float* __restrict__ b2,
                 const int* __restrict__ rxn_idx)
{
    extern __shared__ float sm[];
    float* Sst = sm;                    // [64][SR64]
    float* SA  = sm + B64;
    float* SB  = SA + B64;
    float* SC  = SB + KT64;

    int tid  = threadIdx.x;
    int w    = tid >> 5;
    int lane = tid & 31;
    int nlong = g_longcount;

    for (int i = blockIdx.x; i < nlong; i += gridDim.x) {
        int g     = g_longlist[i];
        int start = g_starts[g];
        int cnt   = g_starts[g + 1] - start;
        int len   = cnt < 64 ? cnt : 64;
        int lenr  = (len + 7) & ~7;
        if (lenr > 64) lenr = 64;

        for (int r = w; r < lenr; r += 8) {
            if (r < len) {
                int rx = rxn_idx[start + r];
                ((float4*)(Sst + r * SR64))[lane] = ((const float4*)(rf + (size_t)rx * CC))[lane];
            } else {
                ((float4*)(Sst + r * SR64))[lane] = make_float4(0.f, 0.f, 0.f, 0.f);
            }
        }
        __syncthreads();

        for (int blk = 0; blk < 2; blk++) {
            const float* wq = Wq + blk * CC * CC;  const float* wk = Wk + blk * CC * CC;
            const float* wv = Wv + blk * CC * CC;  const float* wo = Wo + blk * CC * CC;
            const float* wl = Wlin + blk * CC * CC;
            mm64row<false, false>(Sst, wq, bq + blk * CC, SA, lenr, w, lane);
            mm64row<true,  false>(Sst, wk, bk + blk * CC, SB, lenr, w, lane);
            mm64row<false, false>(Sst, wv, bv + blk * CC, SC, lenr, w, lane);
            __syncthreads();
            attn64(SA, SB, SC, SA, SR64, lenr, len, lenr, w, lane);
            __syncthreads();
            mm64row<false, false>(SA, wo, bo + blk * CC, SB, lenr, w, lane);
            __syncthreads();
            lnres<SR64>(SB, Sst, SR64, Sst, lenr, len, g1 + blk * CC, b1 + blk * CC, w, lane);
            __syncthreads();
            mm64row<false, true>(Sst, wl, blin + blk * CC, SC, lenr, w, lane);
            __syncthreads();
            lnres<SR64>(SC, Sst, SR64, Sst, lenr, lenr, g2 + blk * CC, b2 + blk * CC, w, lane);
            __syncthreads();
        }
        if (tid < CC) SA[tid] = g_qpma[tid];
        mm64row<true,  false>(Sst, Wk + 2 * CC * CC, bk + 2 * CC, SB, lenr, w, lane);
        mm64row<false, false>(Sst, Wv + 2 * CC * CC, bv + 2 * CC, SC, lenr, w, lane);
        __syncthreads();
        attn64(SA, SB, SC, g_pma + (size_t)g * CC, CC, 1, len, lenr, w, lane);
        __syncthreads();
    }
}

// ============================================================================
// TAIL kernel: batched PMA-projection + decoder over 32 genes per CTA
// ============================================================================
__global__ __launch_bounds__(256)
void gene_tail(const float* __restrict__ Wv, const float* __restrict__ Wo,
               const float* __restrict__ bv, const float* __restrict__ bo,
               const float* __restrict__ Wlin, const float* __restrict__ blin,
               const float* __restrict__ g1, const float* __restrict__ b1,
               const float* __restrict__ g2, const float* __restrict__ b2,
               const float* __restrict__ seed,
               float* __restrict__ out)
{
    extern __shared__ float sm[];
    float* Sst = sm;                    // [32][SRW]
    float* SA  = sm + B32;
    float* SC  = SA + B32;

    int g0   = blockIdx.x * 32;
    int tid  = threadIdx.x;
    int w    = tid >> 5;
    int lane = tid & 31;

    for (int r = w; r < 32; r += 8)
        ((float4*)(Sst + r * SRW))[lane] = ((const float4*)(g_pma + (size_t)(g0 + r) * CC))[lane];
    __syncthreads();

    mm32s<8, false, false>(Sst, Wo + 2 * CC * CC, bo + 2 * CC, SA, w, lane);
    __syncthreads();
    lnres<SRW>(SA, seed, 0, Sst, 32, 32, g1 + 2 * CC, b1 + 2 * CC, w, lane);
    __syncthreads();
    mm32s<8, false, true>(Sst, Wlin + 2 * CC * CC, blin + 2 * CC, SC, w, lane);
    __syncthreads();
    lnres<SRW>(SC, Sst, SRW, Sst, 32, 32, g2 + 2 * CC, b2 + 2 * CC, w, lane);
    __syncthreads();

    mm32s<8, false, false>(Sst, Wv + 3 * CC * CC, bv + 3 * CC, SA, w, lane);
    __syncthreads();
    mm32s<8, false, false>(SA, Wo + 3 * CC * CC, bo + 3 * CC, SC, w, lane);
    __syncthreads();
    lnres<SRW>(SC, Sst, SRW, Sst, 32, 32, g1 + 3 * CC, b1 + 3 * CC, w, lane);
    __syncthreads();
    mm32s<8, false, true>(Sst, Wlin + 3 * CC * CC, blin + 3 * CC, SC, w, lane);
    __syncthreads();
    lnres<SRW>(SC, Sst, SRW, Sst, 32, 32, g2 + 3 * CC, b2 + 3 * CC, w, lane);
    __syncthreads();

    for (int r = w; r < 32; r += 8) {
        float4 v = ((const float4*)(Sst + r * SRW))[lane];
        float o[4] = {v.x, v.y, v.z, v.w};
#pragma unroll
        for (int j = 0; j < 4; j++) {
            float x = o[j];
            if (x != x) x = 0.f;
            x = fminf(fmaxf(x, -3.402823466e38f), 3.402823466e38f);
            o[j] = x;
        }
        ((float4*)(out + (size_t)(g0 + r) * CC))[lane] = make_float4(o[0], o[1], o[2], o[3]);
    }
}

extern "C" void kernel_launch(void* const* d_in, const int* in_sizes, int n_in,
                              void* d_out, int out_size)
{
    const float* rf   = (const float*)d_in[0];
    const float* Wq   = (const float*)d_in[1];
    const float* Wk   = (const float*)d_in[2];
    const float* Wv   = (const float*)d_in[3];
    const float* Wo   = (const float*)d_in[4];
    const float* bq   = (const float*)d_in[5];
    const float* bk   = (const float*)d_in[6];
    const float* bv   = (const float*)d_in[7];
    const float* bo   = (const float*)d_in[8];
    const float* Wlin = (const float*)d_in[9];
    const float* blin = (const float*)d_in[10];
    const float* g1   = (const float*)d_in[11];
    const float* b1   = (const float*)d_in[12];
    const float* g2   = (const float*)d_in[13];
    const float* b2   = (const float*)d_in[14];
    const float* seed = (const float*)d_in[15];
    const int*   rxn  = (const int*)d_in[16];
    const int*   gidx = (const int*)d_in[17];
    int E = in_sizes[16];

    cudaFuncSetAttribute(gene_packed, cudaFuncAttributeMaxDynamicSharedMemorySize, SM32_BYTES);
    cudaFuncSetAttribute(gene_long64, cudaFuncAttributeMaxDynamicSharedMemorySize, SM64_BYTES);
    cudaFuncSetAttribute(gene_tail,   cudaFuncAttributeMaxDynamicSharedMemorySize, SMT_BYTES);

    seg_bounds_kernel<<<(E + 255) / 256, 256>>>(gidx, E);
    classify_kernel<<<(GENES + 255) / 256, 256>>>();
    pack_kernel<<<1, 256>>>();
    prep_qpma_kernel<<<1, 128>>>(Wq, bq, seed);
    gene_packed<<<GENES, 256, SM32_BYTES>>>(rf, Wq, Wk, Wv, Wo, bq, bk, bv, bo,
                                            Wlin, blin, g1, b1, g2, b2, rxn);
    gene_long64<<<128, 256, SM64_BYTES>>>(rf, Wq, Wk, Wv, Wo, bq, bk, bv, bo,
                                          Wlin, blin, g1, b1, g2, b2, rxn);
    gene_tail<<<GENES / 32, 256, SMT_BYTES>>>(Wv, Wo, bv, bo, Wlin, blin,
                                              g1, b1, g2, b2, seed, (float*)d_out);
}

// round 16
// speedup vs baseline: 1.3712x; 1.0519x over previous
#include <cuda_runtime.h>
#include <math.h>

#define CC    128
#define GENES 4096
#define SRW   132                 // row stride (floats)

// ---- 36-row packed kernel geometry ----
#define SKT   37                  // K^T stride (odd -> conflict-free)
#define RMAX  36
#define B36   (RMAX * SRW)        // 4752 floats
#define KT36  (128 * SKT)         // 4736 floats
#define SM36_BYTES ((3 * B36 + KT36) * 4)   // 75,968 B -> 3 CTAs/SM (228KB SM)

// ---- long (len>32) kernel geometry ----
#define SR64  136
#define SKT64 69
#define B64   (64 * SR64)
#define KT64  (128 * SKT64)
#define SM64_BYTES ((3 * B64 + KT64) * 4)

// ---- tail kernel ----
#define B32   (32 * SRW)
#define SMT_BYTES (3 * B32 * 4)

#define MAXPLAN 64

__device__ int   g_starts[GENES + 1];
__device__ int   g_longcount;
__device__ int   g_longlist[GENES];
__device__ int   g_bcnt[9];               // bucket counts, b = 1..8
__device__ int   g_bucketbuf[9 * GENES];
__device__ int   g_ncta;
__device__ int   g_ctaA[GENES];
__device__ int   g_ctaB[GENES];
__device__ float g_qpma[CC];              // seed @ Wq[2] + bq[2]
__device__ float g_pma[GENES * CC];       // PMA attention output per gene

__device__ __forceinline__ float warp_sum(float v) {
#pragma unroll
    for (int o = 16; o; o >>= 1) v += __shfl_xor_sync(0xffffffffu, v, o);
    return v;
}
__device__ __forceinline__ float warp_max(float v) {
#pragma unroll
    for (int o = 16; o; o >>= 1) v = fmaxf(v, __shfl_xor_sync(0xffffffffu, v, o));
    return v;
}

// ============================================================================
// bounds + classify + pack(+qpma)
// ============================================================================
__global__ void seg_bounds_kernel(const int* __restrict__ gene_idx, int E)
{
    int e = blockIdx.x * 256 + threadIdx.x;
    if (e == 0) {
        g_starts[GENES] = E; g_longcount = 0;
        for (int b = 0; b < 9; b++) g_bcnt[b] = 0;
    }
    if (e < E) {
        int gi = gene_idx[e];
        if (e == 0 || gene_idx[e - 1] != gi) g_starts[gi] = e;
    }
}

__global__ void classify_kernel()
{
    int g = blockIdx.x * 256 + threadIdx.x;
    if (g < GENES) {
        int len = g_starts[g + 1] - g_starts[g];
        if (len > 32) {
            int p = atomicAdd(&g_longcount, 1); g_longlist[p] = g;
        } else {
            int b = (len + 3) >> 2;             // 1..8
            int p = atomicAdd(&g_bcnt[b], 1);
            g_bucketbuf[b * GENES + p] = g;
        }
    }
}

// single block: thread 0 plans pairing (cap: bA+bB <= 9), threads 128-255
// compute g_qpma concurrently, then all 256 threads emit the worklist.
__global__ void pack_kernel(const float* __restrict__ Wq,
                            const float* __restrict__ bq,
                            const float* __restrict__ seed)
{
    __shared__ int pAb[MAXPLAN], pAo[MAXPLAN], pBb[MAXPLAN], pBo[MAXPLAN];
    __shared__ int pCnt[MAXPLAN], pBase[MAXPLAN];
    __shared__ int s_nplan;

    int tid = threadIdx.x;

    if (tid >= 128) {                          // qpma (overlaps planning)
        int c = tid - 128;
        float acc = bq[2 * CC + c];
        const float* W2 = Wq + 2 * CC * CC;
#pragma unroll 8
        for (int k = 0; k < CC; k++) acc = fmaf(seed[k], W2[k * CC + c], acc);
        g_qpma[c] = acc;
    }

    if (tid == 0) {
        int rem[9], used[9];
        for (int b = 0; b < 9; b++) { rem[b] = g_bcnt[b]; used[b] = 0; }
        int np = 0, ncta = 0;
        for (int b = 8; b >= 1; b--) {
            while (rem[b] > 0) {
                int cap = 9 - b;                // row budget 36 -> sum of buckets <= 9
                int b2 = -1;
                int chi = cap < 8 ? cap : 8;
                for (int c = chi; c >= 1; c--) {
                    if (c == b) { if (rem[b] >= 2) { b2 = c; break; } }
                    else        { if (rem[c] > 0)  { b2 = c; break; } }
                }
                if (b2 < 0) {                       // emit alone
                    pAb[np] = b; pAo[np] = used[b]; pBb[np] = -1; pBo[np] = 0;
                    pCnt[np] = rem[b]; pBase[np] = ncta;
                    ncta += rem[b]; used[b] += rem[b]; rem[b] = 0; np++;
                } else if (b2 == b) {               // self-pair
                    int m = rem[b] >> 1;
                    pAb[np] = b; pAo[np] = used[b];
                    pBb[np] = b; pBo[np] = used[b] + m;
                    pCnt[np] = m; pBase[np] = ncta;
                    ncta += m; used[b] += 2 * m; rem[b] -= 2 * m; np++;
                    if (rem[b] == 1) {
                        pAb[np] = b; pAo[np] = used[b]; pBb[np] = -1; pBo[np] = 0;
                        pCnt[np] = 1; pBase[np] = ncta;
                        ncta += 1; used[b] += 1; rem[b] = 0; np++;
                    }
                } else {                            // cross-bucket pair
                    int m = rem[b] < rem[b2] ? rem[b] : rem[b2];
                    pAb[np] = b;  pAo[np] = used[b];
                    pBb[np] = b2; pBo[np] = used[b2];
                    pCnt[np] = m; pBase[np] = ncta;
                    ncta += m; used[b] += m; used[b2] += m;
                    rem[b] -= m; rem[b2] -= m; np++;
                }
            }
        }
        s_nplan = np;
        g_ncta = ncta;
    }
    __syncthreads();
    int np = s_nplan;
    for (int e = 0; e < np; e++) {
        int cnt = pCnt[e];
        for (int k = tid; k < cnt; k += 256) {
            g_ctaA[pBase[e] + k] = g_bucketbuf[pAb[e] * GENES + pAo[e] + k];
            g_ctaB[pBase[e] + k] = (pBb[e] >= 0)
                ? g_bucketbuf[pBb[e] * GENES + pBo[e] + k] : -1;
        }
    }
}

// ============================================================================
// mm32s<NS>: X[NS*4 rows,128] @ W + b -> Y. 8 warps = 4 row-groups x 2 halves.
// ============================================================================
template <int NS, bool TRANS, bool RELU>
__device__ __forceinline__ void mm32s(const float* X, const float* __restrict__ W,
                                      const float* __restrict__ bias, float* Y,
                                      int w, int lane)
{
    int rg = w >> 1;
    int ch = w & 1;
    int c0 = ch * 64 + lane * 2;
    float acc[NS][2];
#pragma unroll
    for (int i = 0; i < NS; i++) { acc[i][0] = 0.f; acc[i][1] = 0.f; }

#pragma unroll 2
    for (int kk = 0; kk < CC; kk += 4) {
        float2 w0 = *(const float2*)(W + (kk + 0) * CC + c0);
        float2 w1 = *(const float2*)(W + (kk + 1) * CC + c0);
        float2 w2 = *(const float2*)(W + (kk + 2) * CC + c0);
        float2 w3 = *(const float2*)(W + (kk + 3) * CC + c0);
#pragma unroll
        for (int i = 0; i < NS; i++) {
            float4 xv = *(const float4*)(X + (rg + 4 * i) * SRW + kk);
            acc[i][0] = fmaf(xv.x, w0.x, acc[i][0]);
            acc[i][1] = fmaf(xv.x, w0.y, acc[i][1]);
            acc[i][0] = fmaf(xv.y, w1.x, acc[i][0]);
            acc[i][1] = fmaf(xv.y, w1.y, acc[i][1]);
            acc[i][0] = fmaf(xv.z, w2.x, acc[i][0]);
            acc[i][1] = fmaf(xv.z, w2.y, acc[i][1]);
            acc[i][0] = fmaf(xv.w, w3.x, acc[i][0]);
            acc[i][1] = fmaf(xv.w, w3.y, acc[i][1]);
        }
    }
    float2 bv = *(const float2*)(bias + c0);
#pragma unroll
    for (int i = 0; i < NS; i++) {
        int r = rg + 4 * i;
        float o0 = acc[i][0] + bv.x, o1 = acc[i][1] + bv.y;
        if (RELU) { o0 = fmaxf(o0, 0.f); o1 = fmaxf(o1, 0.f); }
        if (!TRANS) {
            *(float2*)(Y + r * SRW + c0) = make_float2(o0, o1);
        } else {
            Y[(c0 + 0) * SKT + r] = o0;
            Y[(c0 + 1) * SKT + r] = o1;
        }
    }
}

// ============================================================================
// mmKV<NS>: fused K^T + V projection, single X pass (for NS <= 5)
// ============================================================================
template <int NS>
__device__ __forceinline__ void mmKV(const float* X,
                                     const float* __restrict__ Wk_,
                                     const float* __restrict__ bk_,
                                     const float* __restrict__ Wv_,
                                     const float* __restrict__ bv_,
                                     float* Kt, float* V, int w, int lane)
{
    int rg = w >> 1;
    int ch = w & 1;
    int c0 = ch * 64 + lane * 2;
    float aK[NS][2], aV[NS][2];
#pragma unroll
    for (int i = 0; i < NS; i++) { aK[i][0]=0.f; aK[i][1]=0.f; aV[i][0]=0.f; aV[i][1]=0.f; }

#pragma unroll 2
    for (int kk = 0; kk < CC; kk += 4) {
        float2 k0 = *(const float2*)(Wk_ + (kk + 0) * CC + c0);
        float2 k1 = *(const float2*)(Wk_ + (kk + 1) * CC + c0);
        float2 k2 = *(const float2*)(Wk_ + (kk + 2) * CC + c0);
        float2 k3 = *(const float2*)(Wk_ + (kk + 3) * CC + c0);
        float2 v0 = *(const float2*)(Wv_ + (kk + 0) * CC + c0);
        float2 v1 = *(const float2*)(Wv_ + (kk + 1) * CC + c0);
        float2 v2 = *(const float2*)(Wv_ + (kk + 2) * CC + c0);
        float2 v3 = *(const float2*)(Wv_ + (kk + 3) * CC + c0);
#pragma unroll
        for (int i = 0; i < NS; i++) {
            float4 xv = *(const float4*)(X + (rg + 4 * i) * SRW + kk);
            aK[i][0] = fmaf(xv.x, k0.x, aK[i][0]);
            aK[i][1] = fmaf(xv.x, k0.y, aK[i][1]);
            aV[i][0] = fmaf(xv.x, v0.x, aV[i][0]);
            aV[i][1] = fmaf(xv.x, v0.y, aV[i][1]);
            aK[i][0] = fmaf(xv.y, k1.x, aK[i][0]);
            aK[i][1] = fmaf(xv.y, k1.y, aK[i][1]);
            aV[i][0] = fmaf(xv.y, v1.x, aV[i][0]);
            aV[i][1] = fmaf(xv.y, v1.y, aV[i][1]);
            aK[i][0] = fmaf(xv.z, k2.x, aK[i][0]);
            aK[i][1] = fmaf(xv.z, k2.y, aK[i][1]);
            aV[i][0] = fmaf(xv.z, v2.x, aV[i][0]);
            aV[i][1] = fmaf(xv.z, v2.y, aV[i][1]);
            aK[i][0] = fmaf(xv.w, k3.x, aK[i][0]);
            aK[i][1] = fmaf(xv.w, k3.y, aK[i][1]);
            aV[i][0] = fmaf(xv.w, v3.x, aV[i][0]);
            aV[i][1] = fmaf(xv.w, v3.y, aV[i][1]);
        }
    }
    float2 bk2 = *(const float2*)(bk_ + c0);
    float2 bv2 = *(const float2*)(bv_ + c0);
#pragma unroll
    for (int i = 0; i < NS; i++) {
        int r = rg + 4 * i;
        Kt[(c0 + 0) * SKT + r] = aK[i][0] + bk2.x;
        Kt[(c0 + 1) * SKT + r] = aK[i][1] + bk2.y;
        *(float2*)(V + r * SRW + c0) = make_float2(aV[i][0] + bv2.x, aV[i][1] + bv2.y);
    }
}

// ============================================================================
// mm64row: row-split matmul for the long (64-row) kernel
// ============================================================================
template <bool TRANS, bool RELU>
__device__ void mm64row(const float* X, const float* __restrict__ W,
                        const float* __restrict__ bias, float* Y,
                        int rows, int w, int lane)
{
    int nr = (rows > w) ? (((rows - 1 - w) >> 3) + 1) : 0;
    if (nr == 0) return;
    int c0 = lane * 4;
    float acc[8][4];
#pragma unroll
    for (int i = 0; i < 8; i++) { acc[i][0]=0.f; acc[i][1]=0.f; acc[i][2]=0.f; acc[i][3]=0.f; }

#pragma unroll 2
    for (int kk = 0; kk < CC; kk += 4) {
        float4 w0 = *(const float4*)(W + (kk + 0) * CC + c0);
        float4 w1 = *(const float4*)(W + (kk + 1) * CC + c0);
        float4 w2 = *(const float4*)(W + (kk + 2) * CC + c0);
        float4 w3 = *(const float4*)(W + (kk + 3) * CC + c0);
#pragma unroll
        for (int i = 0; i < 8; i++) {
            if (i < nr) {
                float4 xv = *(const float4*)(X + (w + 8 * i) * SR64 + kk);
                acc[i][0]=fmaf(xv.x,w0.x,acc[i][0]); acc[i][1]=fmaf(xv.x,w0.y,acc[i][1]);
                acc[i][2]=fmaf(xv.x,w0.z,acc[i][2]); acc[i][3]=fmaf(xv.x,w0.w,acc[i][3]);
                acc[i][0]=fmaf(xv.y,w1.x,acc[i][0]); acc[i][1]=fmaf(xv.y,w1.y,acc[i][1]);
                acc[i][2]=fmaf(xv.y,w1.z,acc[i][2]); acc[i][3]=fmaf(xv.y,w1.w,acc[i][3]);
                acc[i][0]=fmaf(xv.z,w2.x,acc[i][0]); acc[i][1]=fmaf(xv.z,w2.y,acc[i][1]);
                acc[i][2]=fmaf(xv.z,w2.z,acc[i][2]); acc[i][3]=fmaf(xv.z,w2.w,acc[i][3]);
                acc[i][0]=fmaf(xv.w,w3.x,acc[i][0]); acc[i][1]=fmaf(xv.w,w3.y,acc[i][1]);
                acc[i][2]=fmaf(xv.w,w3.z,acc[i][2]); acc[i][3]=fmaf(xv.w,w3.w,acc[i][3]);
            }
        }
    }
    float4 bv = *(const float4*)(bias + c0);
#pragma unroll
    for (int i = 0; i < 8; i++) {
        if (i < nr) {
            int r = w + 8 * i;
            float o0=acc[i][0]+bv.x, o1=acc[i][1]+bv.y, o2=acc[i][2]+bv.z, o3=acc[i][3]+bv.w;
            if (RELU) { o0=fmaxf(o0,0.f); o1=fmaxf(o1,0.f); o2=fmaxf(o2,0.f); o3=fmaxf(o3,0.f); }
            if (!TRANS) {
                *(float4*)(Y + r * SR64 + c0) = make_float4(o0, o1, o2, o3);
            } else {
                Y[(c0+0)*SKT64 + r]=o0; Y[(c0+1)*SKT64 + r]=o1;
                Y[(c0+2)*SKT64 + r]=o2; Y[(c0+3)*SKT64 + r]=o3;
            }
        }
    }
}

// ============================================================================
// paired encoder attention: task = (rowgroup of 4, head). Window re-based at
// klo (gene's first row): lane-local kv index klo+lane, window length <= 32.
// Masked lanes may read in-smem garbage -> weight exactly 0.
// ============================================================================
template <int KVR>
__device__ __forceinline__ void attn_pair(float* QO, const float* Kt, const float* V,
                                          int offB, int lenA, int lenB, int w, int lane)
{
    const float scale = 0.17677669529663687f;
    int lnA4 = (lenA + 3) & ~3;
    int lnB4 = (lenB + 3) & ~3;
    for (int t = w; t < KVR; t += 8) {
        int r0   = (t >> 2) * 4;
        int base = (t & 3) * 32;
        bool isB = (r0 >= offB);
        int klo  = isB ? offB : 0;
        int ln   = isB ? lenB : lenA;
        int kln  = isB ? lnB4 : lnA4;

        float s0 = 0.f, s1 = 0.f, s2 = 0.f, s3 = 0.f;
#pragma unroll
        for (int d = 0; d < 32; d += 4) {
            float k0 = Kt[(base + d + 0) * SKT + klo + lane];
            float k1 = Kt[(base + d + 1) * SKT + klo + lane];
            float k2 = Kt[(base + d + 2) * SKT + klo + lane];
            float k3 = Kt[(base + d + 3) * SKT + klo + lane];
            float4 qa = *(const float4*)(QO + (r0 + 0) * SRW + base + d);
            float4 qb = *(const float4*)(QO + (r0 + 1) * SRW + base + d);
            float4 qc = *(const float4*)(QO + (r0 + 2) * SRW + base + d);
            float4 qd = *(const float4*)(QO + (r0 + 3) * SRW + base + d);
            s0 = fmaf(qa.x,k0,fmaf(qa.y,k1,fmaf(qa.z,k2,fmaf(qa.w,k3,s0))));
            s1 = fmaf(qb.x,k0,fmaf(qb.y,k1,fmaf(qb.z,k2,fmaf(qb.w,k3,s1))));
            s2 = fmaf(qc.x,k0,fmaf(qc.y,k1,fmaf(qc.z,k2,fmaf(qc.w,k3,s2))));
            s3 = fmaf(qd.x,k0,fmaf(qd.y,k1,fmaf(qd.z,k2,fmaf(qd.w,k3,s3))));
        }
        bool valid = (lane < ln);
        s0 = valid ? s0 * scale : -1e30f;
        s1 = valid ? s1 * scale : -1e30f;
        s2 = valid ? s2 * scale : -1e30f;
        s3 = valid ? s3 * scale : -1e30f;
        float a0, a1, a2, a3;
        { float m = warp_max(s0); float p = __expf(s0 - m); a0 = p * (1.f / warp_sum(p)); }
        { float m = warp_max(s1); float p = __expf(s1 - m); a1 = p * (1.f / warp_sum(p)); }
        { float m = warp_max(s2); float p = __expf(s2 - m); a2 = p * (1.f / warp_sum(p)); }
        { float m = warp_max(s3); float p = __expf(s3 - m); a3 = p * (1.f / warp_sum(p)); }

        float o0 = 0.f, o1 = 0.f, o2 = 0.f, o3 = 0.f;
        for (int k = 0; k < kln; k++) {
            float v = V[(klo + k) * SRW + base + lane];
            o0 = fmaf(__shfl_sync(0xffffffffu, a0, k), v, o0);
            o1 = fmaf(__shfl_sync(0xffffffffu, a1, k), v, o1);
            o2 = fmaf(__shfl_sync(0xffffffffu, a2, k), v, o2);
            o3 = fmaf(__shfl_sync(0xffffffffu, a3, k), v, o3);
        }
        QO[(r0 + 0) * SRW + base + lane] = o0;
        QO[(r0 + 1) * SRW + base + lane] = o1;
        QO[(r0 + 2) * SRW + base + lane] = o2;
        QO[(r0 + 3) * SRW + base + lane] = o3;
    }
}

// paired PMA attention: warps 0-3 gene A heads, 4-7 gene B heads; klo-based
__device__ __forceinline__ void attn_pma_pair(const float* Q, const float* Kt, const float* V,
                                              int gA, int gB, int offB, int lenA, int lenB,
                                              int w, int lane)
{
    const float scale = 0.17677669529663687f;
    int gi   = w >> 2;                  // 0 = gene A, 1 = gene B
    int base = (w & 3) * 32;
    int klo  = gi ? offB : 0;
    int ln   = gi ? lenB : lenA;
    int kln  = gi ? ((lenB + 3) & ~3) : ((lenA + 3) & ~3);
    float s = 0.f;
#pragma unroll
    for (int d = 0; d < 32; d += 4) {
        float4 q = *(const float4*)(Q + base + d);
        s = fmaf(q.x, Kt[(base + d + 0) * SKT + klo + lane],
            fmaf(q.y, Kt[(base + d + 1) * SKT + klo + lane],
            fmaf(q.z, Kt[(base + d + 2) * SKT + klo + lane],
            fmaf(q.w, Kt[(base + d + 3) * SKT + klo + lane], s))));
    }
    s = (lane < ln) ? s * scale : -1e30f;
    float m = warp_max(s);
    float p = __expf(s - m);
    float a = p * (1.f / warp_sum(p));
    float acc = 0.f;
    for (int k = 0; k < kln; k++)
        acc = fmaf(__shfl_sync(0xffffffffu, a, k), V[(klo + k) * SRW + base + lane], acc);
    int gout = gi ? gB : gA;
    if (gout >= 0) g_pma[(size_t)gout * CC + base + lane] = acc;
}

// attention (kv <= 64) for the long kernel
__device__ void attn64(const float* Q, const float* Kt, const float* V,
                       float* outp, int outStride,
                       int Lq, int len, int kvr, int w, int lane)
{
    const float scale = 0.17677669529663687f;
    int ntask = Lq * 4;
    for (int t = w; t < ntask; t += 8) {
        int r = t >> 2, base = (t & 3) * 32;
        float s0 = 0.f, s1 = 0.f;
#pragma unroll
        for (int d = 0; d < 32; d++) {
            float qd = Q[r * SR64 + base + d];
            s0 = fmaf(qd, Kt[(base + d) * SKT64 + lane], s0);
            s1 = fmaf(qd, Kt[(base + d) * SKT64 + lane + 32], s1);
        }
        s0 = (lane < len)      ? s0 * scale : -1e30f;
        s1 = (lane + 32 < len) ? s1 * scale : -1e30f;
        float m = warp_max(fmaxf(s0, s1));
        float p0 = __expf(s0 - m), p1 = __expf(s1 - m);
        float inv = 1.f / warp_sum(p0 + p1);
        float a0 = p0 * inv, a1 = p1 * inv;
        float acc = 0.f;
        int k0 = kvr < 32 ? kvr : 32;
        for (int k = 0; k < k0; k++)
            acc = fmaf(__shfl_sync(0xffffffffu, a0, k), V[k * SR64 + base + lane], acc);
        for (int k = 32; k < kvr; k++)
            acc = fmaf(__shfl_sync(0xffffffffu, a1, k - 32), V[k * SR64 + base + lane], acc);
        outp[r * outStride + base + lane] = acc;
    }
}

// ============================================================================
// LN(residual + masked A). resStride==0 -> broadcast residual.
// ============================================================================
template <int SROW>
__device__ void lnres(const float* A, const float* Res, int resStride, float* Out,
                      int rows, int qmasklen,
                      const float* __restrict__ g, const float* __restrict__ b,
                      int w, int lane)
{
    for (int r = w; r < rows; r += 8) {
        float4 a = (r < qmasklen) ? *(const float4*)(A + r * SROW + lane * 4)
                                  : make_float4(0.f, 0.f, 0.f, 0.f);
        float4 s = *(const float4*)(Res + r * resStride + lane * 4);
        float t0 = a.x + s.x, t1 = a.y + s.y, t2 = a.z + s.z, t3 = a.w + s.w;
        float sum = warp_sum(t0 + t1 + t2 + t3);
        float sq  = warp_sum(t0*t0 + t1*t1 + t2*t2 + t3*t3);
        float mean = sum * (1.f / 128.f);
        float var  = sq * (1.f / 128.f) - mean * mean;
        float rstd = rsqrtf(var + 1e-5f);
        float4 gv = *(const float4*)(g + lane * 4);
        float4 bv = *(const float4*)(b + lane * 4);
        float4 o;
        o.x = (t0 - mean) * rstd * gv.x + bv.x;
        o.y = (t1 - mean) * rstd * gv.y + bv.y;
        o.z = (t2 - mean) * rstd * gv.z + bv.z;
        o.w = (t3 - mean) * rstd * gv.w + bv.w;
        *(float4*)(Out + r * SROW + lane * 4) = o;
    }
}

// paired version: row valid if local index (relative to its gene window) < len
__device__ void lnres_pair(const float* A, const float* Res, float* Out,
                           int rows, int offB, int lenA, int lenB,
                           const float* __restrict__ g, const float* __restrict__ b,
                           int w, int lane)
{
    for (int r = w; r < rows; r += 8) {
        int lo = (r >= offB) ? offB : 0;
        int ln = (r >= offB) ? lenB : lenA;
        float4 a = ((r - lo) < ln) ? *(const float4*)(A + r * SRW + lane * 4)
                                   : make_float4(0.f, 0.f, 0.f, 0.f);
        float4 s = *(const float4*)(Res + r * SRW + lane * 4);
        float t0 = a.x + s.x, t1 = a.y + s.y, t2 = a.z + s.z, t3 = a.w + s.w;
        float sum = warp_sum(t0 + t1 + t2 + t3);
        float sq  = warp_sum(t0*t0 + t1*t1 + t2*t2 + t3*t3);
        float mean = sum * (1.f / 128.f);
        float var  = sq * (1.f / 128.f) - mean * mean;
        float rstd = rsqrtf(var + 1e-5f);
        float4 gv = *(const float4*)(g + lane * 4);
        float4 bv = *(const float4*)(b + lane * 4);
        float4 o;
        o.x = (t0 - mean) * rstd * gv.x + bv.x;
        o.y = (t1 - mean) * rstd * gv.y + bv.y;
        o.z = (t2 - mean) * rstd * gv.z + bv.z;
        o.w = (t3 - mean) * rstd * gv.w + bv.w;
        *(float4*)(Out + r * SRW + lane * 4) = o;
    }
}

// ============================================================================
// unified encoder(x2) + PMA attention for 1 or 2 genes in NS*4 rows (NS<=9)
// ============================================================================
template <int NS>
__device__ __forceinline__ void enc_pair(
    float* Sst, float* SA, float* SB, float* SC,
    const float* __restrict__ Wq, const float* __restrict__ Wk,
    const float* __restrict__ Wv, const float* __restrict__ Wo,
    const float* __restrict__ bq, const float* __restrict__ bk,
    const float* __restrict__ bv, const float* __restrict__ bo,
    const float* __restrict__ Wlin, const float* __restrict__ blin,
    const float* __restrict__ g1, const float* __restrict__ b1,
    const float* __restrict__ g2, const float* __restrict__ b2,
    int gA, int gB, int offB, int lenA, int lenB,
    int w, int lane, int tid)
{
    constexpr int ROWS = NS * 4;
#pragma unroll 1
    for (int blk = 0; blk < 2; blk++) {
        const float* wq = Wq + blk * CC * CC;  const float* wk = Wk + blk * CC * CC;
        const float* wv = Wv + blk * CC * CC;  const float* wo = Wo + blk * CC * CC;
        const float* wl = Wlin + blk * CC * CC;
        mm32s<NS, false, false>(Sst, wq, bq + blk * CC, SA, w, lane);
        if constexpr (NS <= 5) {
            mmKV<NS>(Sst, wk, bk + blk * CC, wv, bv + blk * CC, SB, SC, w, lane);
        } else {
            mm32s<NS, true,  false>(Sst, wk, bk + blk * CC, SB, w, lane);
            mm32s<NS, false, false>(Sst, wv, bv + blk * CC, SC, w, lane);
        }
        __syncthreads();
        attn_pair<ROWS>(SA, SB, SC, offB, lenA, lenB, w, lane);
        __syncthreads();
        mm32s<NS, false, false>(SA, wo, bo + blk * CC, SB, w, lane);
        __syncthreads();
        lnres_pair(SB, Sst, Sst, ROWS, offB, lenA, lenB,
                   g1 + blk * CC, b1 + blk * CC, w, lane);
        __syncthreads();
        mm32s<NS, false, true>(Sst, wl, blin + blk * CC, SC, w, lane);
        __syncthreads();
        lnres<SRW>(SC, Sst, SRW, Sst, ROWS, ROWS, g2 + blk * CC, b2 + blk * CC, w, lane);
        __syncthreads();
    }
    if (tid < CC) SA[tid] = g_qpma[tid];
    if constexpr (NS <= 5) {
        mmKV<NS>(Sst, Wk + 2 * CC * CC, bk + 2 * CC, Wv + 2 * CC * CC, bv + 2 * CC,
                 SB, SC, w, lane);
    } else {
        mm32s<NS, true,  false>(Sst, Wk + 2 * CC * CC, bk + 2 * CC, SB, w, lane);
        mm32s<NS, false, false>(Sst, Wv + 2 * CC * CC, bv + 2 * CC, SC, w, lane);
    }
    __syncthreads();
    attn_pma_pair(SA, SB, SC, gA, gB, offB, lenA, lenB, w, lane);
}

// ============================================================================
// PACKED kernel: bin-packed 1-2 genes per CTA, up to 36 rows
// ============================================================================
__global__ __launch_bounds__(256, 3)
void gene_packed(const float* __restrict__ rf,
                 const float* __restrict__ Wq, const float* __restrict__ Wk,
                 const float* __restrict__ Wv, const float* __restrict__ Wo,
                 const float* __restrict__ bq, const float* __restrict__ bk,
                 const float* __restrict__ bv, const float* __restrict__ bo,
                 const float* __restrict__ Wlin, const float* __restrict__ blin,
                 const float* __restrict__ g1, const float* __restrict__ b1,
                 const float* __restrict__ g2, const float* __restrict__ b2,
                 const int* __restrict__ rxn_idx)
{
    extern __shared__ float sm[];
    float* Sst = sm;                    // [<=36][SRW]
    float* SA  = sm + B36;
    float* SB  = SA + B36;              // K^T [128][SKT]
    float* SC  = SB + KT36;

    int i    = blockIdx.x;
    if (i >= g_ncta) return;
    int tid  = threadIdx.x;
    int w    = tid >> 5;
    int lane = tid & 31;

    int gA = g_ctaA[i];
    int gB = g_ctaB[i];
    int sA = g_starts[gA];
    int lenA = g_starts[gA + 1] - sA;
    int sB = 0, lenB = 0;
    if (gB >= 0) { sB = g_starts[gB]; lenB = g_starts[gB + 1] - sB; }

    int offB = (lenA + 3) & ~3;
    int lenr = offB + ((lenB + 3) & ~3);     // multiple of 4, <= 36
    int NS   = lenr >> 2;                    // 1..9

    // gather
    for (int r = w; r < lenr; r += 8) {
        bool isB  = r >= offB;
        int local = isB ? (r - offB) : r;
        int ln    = isB ? lenB : lenA;
        int st    = isB ? sB   : sA;
        if (local < ln) {
            int rx = rxn_idx[st + local];
            ((float4*)(Sst + r * SRW))[lane] = ((const float4*)(rf + (size_t)rx * CC))[lane];
        } else {
            ((float4*)(Sst + r * SRW))[lane] = make_float4(0.f, 0.f, 0.f, 0.f);
        }
    }
    __syncthreads();

#define CALL_ENC(NSV) enc_pair<NSV>(Sst, SA, SB, SC, Wq, Wk, Wv, Wo, bq, bk, bv, bo, \
                                    Wlin, blin, g1, b1, g2, b2, gA, gB, offB, lenA, lenB, w, lane, tid)
    switch (NS) {
    case 1: CALL_ENC(1); break;
    case 2: CALL_ENC(2); break;
    case 3: CALL_ENC(3); break;
    case 4: CALL_ENC(4); break;
    case 5: CALL_ENC(5); break;
    case 6: CALL_ENC(6); break;
    case 7: CALL_ENC(7); break;
    case 8: CALL_ENC(8); break;
    default: CALL_ENC(9); break;
    }
#undef CALL_ENC
}

// ============================================================================
// LONG kernel: genes with len > 32 (rare); ends after PMA attention
// ============================================================================
__global__ __launch_bounds__(256, 1)
void gene_long64(const float* __restrict__ rf,
                 const float* __restrict__ Wq, const float* __restrict__ Wk,
                 const float* __restrict__ Wv, const float* __restrict__ Wo,
                 const float* __restrict__ bq, const float* __restrict__ bk,
                 const float* __restrict__ bv, const float* __restrict__ bo,
                 const float* __restrict__ Wlin, const float* __restrict__ blin,
                 const float* __restrict__ g1, const float* __restrict__ b1,
                 const float* __restrict__ g2, const float* __restrict__ b2,
                 const int* __restrict__ rxn_idx)
{
    extern __shared__ float sm[];
    float* Sst = sm;                    // [64][SR64]
    float* SA  = sm + B64;
    float* SB  = SA + B64;
    float* SC  = SB + KT64;

    int tid  = threadIdx.x;
    int w    = tid >> 5;
    int lane = tid & 31;
    int nlong = g_longcount;

    for (int i = blockIdx.x; i < nlong; i += gridDim.x) {
        int g     = g_longlist[i];
        int start = g_starts[g];
        int cnt   = g_starts[g + 1] - start;
        int len   = cnt < 64 ? cnt : 64;
        int lenr  = (len + 7) & ~7;
        if (lenr > 64) lenr = 64;

        for (int r = w; r < lenr; r += 8) {
            if (r < len) {
                int rx = rxn_idx[start + r];
                ((float4*)(Sst + r * SR64))[lane] = ((const float4*)(rf + (size_t)rx * CC))[lane];
            } else {
                ((float4*)(Sst + r * SR64))[lane] = make_float4(0.f, 0.f, 0.f, 0.f);
            }
        }
        __syncthreads();

        for (int blk = 0; blk < 2; blk++) {
            const float* wq = Wq + blk * CC * CC;  const float* wk = Wk + blk * CC * CC;
            const float* wv = Wv + blk * CC * CC;  const float* wo = Wo + blk * CC * CC;
            const float* wl = Wlin + blk * CC * CC;
            mm64row<false, false>(Sst, wq, bq + blk * CC, SA, lenr, w, lane);
            mm64row<true,  false>(Sst, wk, bk + blk * CC, SB, lenr, w, lane);
            mm64row<false, false>(Sst, wv, bv + blk * CC, SC, lenr, w, lane);
            __syncthreads();
            attn64(SA, SB, SC, SA, SR64, lenr, len, lenr, w, lane);
            __syncthreads();
            mm64row<false, false>(SA, wo, bo + blk * CC, SB, lenr, w, lane);
            __syncthreads();
            lnres<SR64>(SB, Sst, SR64, Sst, lenr, len, g1 + blk * CC, b1 + blk * CC, w, lane);
            __syncthreads();
            mm64row<false, true>(Sst, wl, blin + blk * CC, SC, lenr, w, lane);
            __syncthreads();
            lnres<SR64>(SC, Sst, SR64, Sst, lenr, lenr, g2 + blk * CC, b2 + blk * CC, w, lane);
            __syncthreads();
        }
        if (tid < CC) SA[tid] = g_qpma[tid];
        mm64row<true,  false>(Sst, Wk + 2 * CC * CC, bk + 2 * CC, SB, lenr, w, lane);
        mm64row<false, false>(Sst, Wv + 2 * CC * CC, bv + 2 * CC, SC, lenr, w, lane);
        __syncthreads();
        attn64(SA, SB, SC, g_pma + (size_t)g * CC, CC, 1, len, lenr, w, lane);
        __syncthreads();
    }
}

// ============================================================================
// TAIL kernel: batched PMA-projection + decoder over 32 genes per CTA
// ============================================================================
__global__ __launch_bounds__(256)
void gene_tail(const float* __restrict__ Wv, const float* __restrict__ Wo,
               const float* __restrict__ bv, const float* __restrict__ bo,
               const float* __restrict__ Wlin, const float* __restrict__ blin,
               const float* __restrict__ g1, const float* __restrict__ b1,
               const float* __restrict__ g2, const float* __restrict__ b2,
               const float* __restrict__ seed,
               float* __restrict__ out)
{
    extern __shared__ float sm[];
    float* Sst = sm;                    // [32][SRW]
    float* SA  = sm + B32;
    float* SC  = SA + B32;

    int g0   = blockIdx.x * 32;
    int tid  = threadIdx.x;
    int w    = tid >> 5;
    int lane = tid & 31;

    for (int r = w; r < 32; r += 8)
        ((float4*)(Sst + r * SRW))[lane] = ((const float4*)(g_pma + (size_t)(g0 + r) * CC))[lane];
    __syncthreads();

    mm32s<8, false, false>(Sst, Wo + 2 * CC * CC, bo + 2 * CC, SA, w, lane);
    __syncthreads();
    lnres<SRW>(SA, seed, 0, Sst, 32, 32, g1 + 2 * CC, b1 + 2 * CC, w, lane);
    __syncthreads();
    mm32s<8, false, true>(Sst, Wlin + 2 * CC * CC, blin + 2 * CC, SC, w, lane);
    __syncthreads();
    lnres<SRW>(SC, Sst, SRW, Sst, 32, 32, g2 + 2 * CC, b2 + 2 * CC, w, lane);
    __syncthreads();

    mm32s<8, false, false>(Sst, Wv + 3 * CC * CC, bv + 3 * CC, SA, w, lane);
    __syncthreads();
    mm32s<8, false, false>(SA, Wo + 3 * CC * CC, bo + 3 * CC, SC, w, lane);
    __syncthreads();
    lnres<SRW>(SC, Sst, SRW, Sst, 32, 32, g1 + 3 * CC, b1 + 3 * CC, w, lane);
    __syncthreads();
    mm32s<8, false, true>(Sst, Wlin + 3 * CC * CC, blin + 3 * CC, SC, w, lane);
    __syncthreads();
    lnres<SRW>(SC, Sst, SRW, Sst, 32, 32, g2 + 3 * CC, b2 + 3 * CC, w, lane);
    __syncthreads();

    for (int r = w; r < 32; r += 8) {
        float4 v = ((const float4*)(Sst + r * SRW))[lane];
        float o[4] = {v.x, v.y, v.z, v.w};
#pragma unroll
        for (int j = 0; j < 4; j++) {
            float x = o[j];
            if (x != x) x = 0.f;
            x = fminf(fmaxf(x, -3.402823466e38f), 3.402823466e38f);
            o[j] = x;
        }
        ((float4*)(out + (size_t)(g0 + r) * CC))[lane] = make_float4(o[0], o[1], o[2], o[3]);
    }
}

extern "C" void kernel_launch(void* const* d_in, const int* in_sizes, int n_in,
                              void* d_out, int out_size)
{
    const float* rf   = (const float*)d_in[0];
    const float* Wq   = (const float*)d_in[1];
    const float* Wk   = (const float*)d_in[2];
    const float* Wv   = (const float*)d_in[3];
    const float* Wo   = (const float*)d_in[4];
    const float* bq   = (const float*)d_in[5];
    const float* bk   = (const float*)d_in[6];
    const float* bv   = (const float*)d_in[7];
    const float* bo   = (const float*)d_in[8];
    const float* Wlin = (const float*)d_in[9];
    const float* blin = (const float*)d_in[10];
    const float* g1   = (const float*)d_in[11];
    const float* b1   = (const float*)d_in[12];
    const float* g2   = (const float*)d_in[13];
    const float* b2   = (const float*)d_in[14];
    const float* seed = (const float*)d_in[15];
    const int*   rxn  = (const int*)d_in[16];
    const int*   gidx = (const int*)d_in[17];
    int E = in_sizes[16];

    cudaFuncSetAttribute(gene_packed, cudaFuncAttributeMaxDynamicSharedMemorySize, SM36_BYTES);
    cudaFuncSetAttribute(gene_long64, cudaFuncAttributeMaxDynamicSharedMemorySize, SM64_BYTES);
    cudaFuncSetAttribute(gene_tail,   cudaFuncAttributeMaxDynamicSharedMemorySize, SMT_BYTES);

    seg_bounds_kernel<<<(E + 255) / 256, 256>>>(gidx, E);
    classify_kernel<<<(GENES + 255) / 256, 256>>>();
    pack_kernel<<<1, 256>>>(Wq, bq, seed);
    gene_packed<<<GENES, 256, SM36_BYTES>>>(rf, Wq, Wk, Wv, Wo, bq, bk, bv, bo,
                                            Wlin, blin, g1, b1, g2, b2, rxn);
    gene_long64<<<128, 256, SM64_BYTES>>>(rf, Wq, Wk, Wv, Wo, bq, bk, bv, bo,
                                          Wlin, blin, g1, b1, g2, b2, rxn);
    gene_tail<<<GENES / 32, 256, SMT_BYTES>>>(Wv, Wo, bv, bo, Wlin, blin,
                                              g1, b1, g2, b2, seed, (float*)d_out);
}

// round 17
// speedup vs baseline: 1.4582x; 1.0634x over previous
#include <cuda_runtime.h>
#include <math.h>

#define CC    128
#define GENES 4096
#define SRW   132                 // row stride (floats)

// ---- 36-row packed kernel geometry ----
#define SKT   37                  // K^T stride (odd -> conflict-free)
#define RMAX  36
#define B36   (RMAX * SRW)        // 4752 floats
#define KT36  (128 * SKT)         // 4736 floats
#define SM36_BYTES ((3 * B36 + KT36) * 4)   // 75,968 B -> 3 CTAs/SM

// ---- long (len>32) kernel geometry ----
#define SR64  136
#define SKT64 69
#define B64   (64 * SR64)
#define KT64  (128 * SKT64)
#define SM64_BYTES ((3 * B64 + KT64) * 4)

// ---- tail kernel: 16 genes per CTA ----
#define B16T  (16 * SRW)
#define SMT_BYTES (3 * B16T * 4)

#define MAXPLAN 64

__device__ int   g_starts[GENES + 1];
__device__ int   g_longcount;
__device__ int   g_longlist[GENES];
__device__ int   g_bcnt[9];               // bucket counts, b = 1..8
__device__ int   g_bucketbuf[9 * GENES];
__device__ int   g_ncta;
__device__ int   g_ctaA[GENES];
__device__ int   g_ctaB[GENES];
__device__ float g_qpma[CC];              // seed @ Wq[2] + bq[2]
__device__ float g_pma[GENES * CC];       // PMA attention output per gene

__device__ __forceinline__ float warp_sum(float v) {
#pragma unroll
    for (int o = 16; o; o >>= 1) v += __shfl_xor_sync(0xffffffffu, v, o);
    return v;
}
__device__ __forceinline__ float warp_max(float v) {
#pragma unroll
    for (int o = 16; o; o >>= 1) v = fmaxf(v, __shfl_xor_sync(0xffffffffu, v, o));
    return v;
}

// ============================================================================
// bounds + classify + pack(+qpma)
// ============================================================================
__global__ void seg_bounds_kernel(const int* __restrict__ gene_idx, int E)
{
    int e = blockIdx.x * 256 + threadIdx.x;
    if (e == 0) {
        g_starts[GENES] = E; g_longcount = 0;
        for (int b = 0; b < 9; b++) g_bcnt[b] = 0;
    }
    if (e < E) {
        int gi = gene_idx[e];
        if (e == 0 || gene_idx[e - 1] != gi) g_starts[gi] = e;
    }
}

__global__ void classify_kernel()
{
    int g = blockIdx.x * 256 + threadIdx.x;
    if (g < GENES) {
        int len = g_starts[g + 1] - g_starts[g];
        if (len > 32) {
            int p = atomicAdd(&g_longcount, 1); g_longlist[p] = g;
        } else {
            int b = (len + 3) >> 2;             // 1..8
            int p = atomicAdd(&g_bcnt[b], 1);
            g_bucketbuf[b * GENES + p] = g;
        }
    }
}

// single block: thread 0 plans pairing (cap: bA+bB <= 9), threads 128-255
// compute g_qpma concurrently, then all 256 threads emit the worklist.
__global__ void pack_kernel(const float* __restrict__ Wq,
                            const float* __restrict__ bq,
                            const float* __restrict__ seed)
{
    __shared__ int pAb[MAXPLAN], pAo[MAXPLAN], pBb[MAXPLAN], pBo[MAXPLAN];
    __shared__ int pCnt[MAXPLAN], pBase[MAXPLAN];
    __shared__ int s_nplan;

    int tid = threadIdx.x;

    if (tid >= 128) {                          // qpma (overlaps planning)
        int c = tid - 128;
        float acc = bq[2 * CC + c];
        const float* W2 = Wq + 2 * CC * CC;
#pragma unroll 8
        for (int k = 0; k < CC; k++) acc = fmaf(seed[k], W2[k * CC + c], acc);
        g_qpma[c] = acc;
    }

    if (tid == 0) {
        int rem[9], used[9];
        for (int b = 0; b < 9; b++) { rem[b] = g_bcnt[b]; used[b] = 0; }
        int np = 0, ncta = 0;
        for (int b = 8; b >= 1; b--) {
            while (rem[b] > 0) {
                int cap = 9 - b;
                int b2 = -1;
                int chi = cap < 8 ? cap : 8;
                for (int c = chi; c >= 1; c--) {
                    if (c == b) { if (rem[b] >= 2) { b2 = c; break; } }
                    else        { if (rem[c] > 0)  { b2 = c; break; } }
                }
                if (b2 < 0) {                       // emit alone
                    pAb[np] = b; pAo[np] = used[b]; pBb[np] = -1; pBo[np] = 0;
                    pCnt[np] = rem[b]; pBase[np] = ncta;
                    ncta += rem[b]; used[b] += rem[b]; rem[b] = 0; np++;
                } else if (b2 == b) {               // self-pair
                    int m = rem[b] >> 1;
                    pAb[np] = b; pAo[np] = used[b];
                    pBb[np] = b; pBo[np] = used[b] + m;
                    pCnt[np] = m; pBase[np] = ncta;
                    ncta += m; used[b] += 2 * m; rem[b] -= 2 * m; np++;
                    if (rem[b] == 1) {
                        pAb[np] = b; pAo[np] = used[b]; pBb[np] = -1; pBo[np] = 0;
                        pCnt[np] = 1; pBase[np] = ncta;
                        ncta += 1; used[b] += 1; rem[b] = 0; np++;
                    }
                } else {                            // cross-bucket pair
                    int m = rem[b] < rem[b2] ? rem[b] : rem[b2];
                    pAb[np] = b;  pAo[np] = used[b];
                    pBb[np] = b2; pBo[np] = used[b2];
                    pCnt[np] = m; pBase[np] = ncta;
                    ncta += m; used[b] += m; used[b2] += m;
                    rem[b] -= m; rem[b2] -= m; np++;
                }
            }
        }
        s_nplan = np;
        g_ncta = ncta;
    }
    __syncthreads();
    int np = s_nplan;
    for (int e = 0; e < np; e++) {
        int cnt = pCnt[e];
        for (int k = tid; k < cnt; k += 256) {
            g_ctaA[pBase[e] + k] = g_bucketbuf[pAb[e] * GENES + pAo[e] + k];
            g_ctaB[pBase[e] + k] = (pBb[e] >= 0)
                ? g_bucketbuf[pBb[e] * GENES + pBo[e] + k] : -1;
        }
    }
}

// ============================================================================
// mm32s<NS>: X[NS*4 rows,128] @ W + b -> Y. 8 warps = 4 row-groups x 2 halves.
// ============================================================================
template <int NS, bool TRANS, bool RELU>
__device__ __forceinline__ void mm32s(const float* X, const float* __restrict__ W,
                                      const float* __restrict__ bias, float* Y,
                                      int w, int lane)
{
    int rg = w >> 1;
    int ch = w & 1;
    int c0 = ch * 64 + lane * 2;
    float acc[NS][2];
#pragma unroll
    for (int i = 0; i < NS; i++) { acc[i][0] = 0.f; acc[i][1] = 0.f; }

#pragma unroll 2
    for (int kk = 0; kk < CC; kk += 4) {
        float2 w0 = *(const float2*)(W + (kk + 0) * CC + c0);
        float2 w1 = *(const float2*)(W + (kk + 1) * CC + c0);
        float2 w2 = *(const float2*)(W + (kk + 2) * CC + c0);
        float2 w3 = *(const float2*)(W + (kk + 3) * CC + c0);
#pragma unroll
        for (int i = 0; i < NS; i++) {
            float4 xv = *(const float4*)(X + (rg + 4 * i) * SRW + kk);
            acc[i][0] = fmaf(xv.x, w0.x, acc[i][0]);
            acc[i][1] = fmaf(xv.x, w0.y, acc[i][1]);
            acc[i][0] = fmaf(xv.y, w1.x, acc[i][0]);
            acc[i][1] = fmaf(xv.y, w1.y, acc[i][1]);
            acc[i][0] = fmaf(xv.z, w2.x, acc[i][0]);
            acc[i][1] = fmaf(xv.z, w2.y, acc[i][1]);
            acc[i][0] = fmaf(xv.w, w3.x, acc[i][0]);
            acc[i][1] = fmaf(xv.w, w3.y, acc[i][1]);
        }
    }
    float2 bv = *(const float2*)(bias + c0);
#pragma unroll
    for (int i = 0; i < NS; i++) {
        int r = rg + 4 * i;
        float o0 = acc[i][0] + bv.x, o1 = acc[i][1] + bv.y;
        if (RELU) { o0 = fmaxf(o0, 0.f); o1 = fmaxf(o1, 0.f); }
        if (!TRANS) {
            *(float2*)(Y + r * SRW + c0) = make_float2(o0, o1);
        } else {
            Y[(c0 + 0) * SKT + r] = o0;
            Y[(c0 + 1) * SKT + r] = o1;
        }
    }
}

// ============================================================================
// mmKV<NS>: fused K^T + V projection, single X pass (all NS)
// ============================================================================
template <int NS>
__device__ __forceinline__ void mmKV(const float* X,
                                     const float* __restrict__ Wk_,
                                     const float* __restrict__ bk_,
                                     const float* __restrict__ Wv_,
                                     const float* __restrict__ bv_,
                                     float* Kt, float* V, int w, int lane)
{
    int rg = w >> 1;
    int ch = w & 1;
    int c0 = ch * 64 + lane * 2;
    float aK[NS][2], aV[NS][2];
#pragma unroll
    for (int i = 0; i < NS; i++) { aK[i][0]=0.f; aK[i][1]=0.f; aV[i][0]=0.f; aV[i][1]=0.f; }

#pragma unroll 1
    for (int kk = 0; kk < CC; kk += 4) {
        float2 k0 = *(const float2*)(Wk_ + (kk + 0) * CC + c0);
        float2 k1 = *(const float2*)(Wk_ + (kk + 1) * CC + c0);
        float2 k2 = *(const float2*)(Wk_ + (kk + 2) * CC + c0);
        float2 k3 = *(const float2*)(Wk_ + (kk + 3) * CC + c0);
        float2 v0 = *(const float2*)(Wv_ + (kk + 0) * CC + c0);
        float2 v1 = *(const float2*)(Wv_ + (kk + 1) * CC + c0);
        float2 v2 = *(const float2*)(Wv_ + (kk + 2) * CC + c0);
        float2 v3 = *(const float2*)(Wv_ + (kk + 3) * CC + c0);
#pragma unroll
        for (int i = 0; i < NS; i++) {
            float4 xv = *(const float4*)(X + (rg + 4 * i) * SRW + kk);
            aK[i][0] = fmaf(xv.x, k0.x, aK[i][0]);
            aK[i][1] = fmaf(xv.x, k0.y, aK[i][1]);
            aV[i][0] = fmaf(xv.x, v0.x, aV[i][0]);
            aV[i][1] = fmaf(xv.x, v0.y, aV[i][1]);
            aK[i][0] = fmaf(xv.y, k1.x, aK[i][0]);
            aK[i][1] = fmaf(xv.y, k1.y, aK[i][1]);
            aV[i][0] = fmaf(xv.y, v1.x, aV[i][0]);
            aV[i][1] = fmaf(xv.y, v1.y, aV[i][1]);
            aK[i][0] = fmaf(xv.z, k2.x, aK[i][0]);
            aK[i][1] = fmaf(xv.z, k2.y, aK[i][1]);
            aV[i][0] = fmaf(xv.z, v2.x, aV[i][0]);
            aV[i][1] = fmaf(xv.z, v2.y, aV[i][1]);
            aK[i][0] = fmaf(xv.w, k3.x, aK[i][0]);
            aK[i][1] = fmaf(xv.w, k3.y, aK[i][1]);
            aV[i][0] = fmaf(xv.w, v3.x, aV[i][0]);
            aV[i][1] = fmaf(xv.w, v3.y, aV[i][1]);
        }
    }
    float2 bk2 = *(const float2*)(bk_ + c0);
    float2 bv2 = *(const float2*)(bv_ + c0);
#pragma unroll
    for (int i = 0; i < NS; i++) {
        int r = rg + 4 * i;
        Kt[(c0 + 0) * SKT + r] = aK[i][0] + bk2.x;
        Kt[(c0 + 1) * SKT + r] = aK[i][1] + bk2.y;
        *(float2*)(V + r * SRW + c0) = make_float2(aV[i][0] + bv2.x, aV[i][1] + bv2.y);
    }
}

// ============================================================================
// mm64row: row-split matmul for the long (64-row) kernel
// ============================================================================
template <bool TRANS, bool RELU>
__device__ void mm64row(const float* X, const float* __restrict__ W,
                        const float* __restrict__ bias, float* Y,
                        int rows, int w, int lane)
{
    int nr = (rows > w) ? (((rows - 1 - w) >> 3) + 1) : 0;
    if (nr == 0) return;
    int c0 = lane * 4;
    float acc[8][4];
#pragma unroll
    for (int i = 0; i < 8; i++) { acc[i][0]=0.f; acc[i][1]=0.f; acc[i][2]=0.f; acc[i][3]=0.f; }

#pragma unroll 2
    for (int kk = 0; kk < CC; kk += 4) {
        float4 w0 = *(const float4*)(W + (kk + 0) * CC + c0);
        float4 w1 = *(const float4*)(W + (kk + 1) * CC + c0);
        float4 w2 = *(const float4*)(W + (kk + 2) * CC + c0);
        float4 w3 = *(const float4*)(W + (kk + 3) * CC + c0);
#pragma unroll
        for (int i = 0; i < 8; i++) {
            if (i < nr) {
                float4 xv = *(const float4*)(X + (w + 8 * i) * SR64 + kk);
                acc[i][0]=fmaf(xv.x,w0.x,acc[i][0]); acc[i][1]=fmaf(xv.x,w0.y,acc[i][1]);
                acc[i][2]=fmaf(xv.x,w0.z,acc[i][2]); acc[i][3]=fmaf(xv.x,w0.w,acc[i][3]);
                acc[i][0]=fmaf(xv.y,w1.x,acc[i][0]); acc[i][1]=fmaf(xv.y,w1.y,acc[i][1]);
                acc[i][2]=fmaf(xv.y,w1.z,acc[i][2]); acc[i][3]=fmaf(xv.y,w1.w,acc[i][3]);
                acc[i][0]=fmaf(xv.z,w2.x,acc[i][0]); acc[i][1]=fmaf(xv.z,w2.y,acc[i][1]);
                acc[i][2]=fmaf(xv.z,w2.z,acc[i][2]); acc[i][3]=fmaf(xv.z,w2.w,acc[i][3]);
                acc[i][0]=fmaf(xv.w,w3.x,acc[i][0]); acc[i][1]=fmaf(xv.w,w3.y,acc[i][1]);
                acc[i][2]=fmaf(xv.w,w3.z,acc[i][2]); acc[i][3]=fmaf(xv.w,w3.w,acc[i][3]);
            }
        }
    }
    float4 bv = *(const float4*)(bias + c0);
#pragma unroll
    for (int i = 0; i < 8; i++) {
        if (i < nr) {
            int r = w + 8 * i;
            float o0=acc[i][0]+bv.x, o1=acc[i][1]+bv.y, o2=acc[i][2]+bv.z, o3=acc[i][3]+bv.w;
            if (RELU) { o0=fmaxf(o0,0.f); o1=fmaxf(o1,0.f); o2=fmaxf(o2,0.f); o3=fmaxf(o3,0.f); }
            if (!TRANS) {
                *(float4*)(Y + r * SR64 + c0) = make_float4(o0, o1, o2, o3);
            } else {
                Y[(c0+0)*SKT64 + r]=o0; Y[(c0+1)*SKT64 + r]=o1;
                Y[(c0+2)*SKT64 + r]=o2; Y[(c0+3)*SKT64 + r]=o3;
            }
        }
    }
}

// ============================================================================
// paired encoder attention: task = (rowgroup of 4, head). Window re-based at
// klo (gene's first row): lane-local kv index klo+lane, window length <= 32.
// ============================================================================
template <int KVR>
__device__ __forceinline__ void attn_pair(float* QO, const float* Kt, const float* V,
                                          int offB, int lenA, int lenB, int w, int lane)
{
    const float scale = 0.17677669529663687f;
    int lnA4 = (lenA + 3) & ~3;
    int lnB4 = (lenB + 3) & ~3;
    for (int t = w; t < KVR; t += 8) {
        int r0   = (t >> 2) * 4;
        int base = (t & 3) * 32;
        bool isB = (r0 >= offB);
        int klo  = isB ? offB : 0;
        int ln   = isB ? lenB : lenA;
        int kln  = isB ? lnB4 : lnA4;

        float s0 = 0.f, s1 = 0.f, s2 = 0.f, s3 = 0.f;
#pragma unroll
        for (int d = 0; d < 32; d += 4) {
            float k0 = Kt[(base + d + 0) * SKT + klo + lane];
            float k1 = Kt[(base + d + 1) * SKT + klo + lane];
            float k2 = Kt[(base + d + 2) * SKT + klo + lane];
            float k3 = Kt[(base + d + 3) * SKT + klo + lane];
            float4 qa = *(const float4*)(QO + (r0 + 0) * SRW + base + d);
            float4 qb = *(const float4*)(QO + (r0 + 1) * SRW + base + d);
            float4 qc = *(const float4*)(QO + (r0 + 2) * SRW + base + d);
            float4 qd = *(const float4*)(QO + (r0 + 3) * SRW + base + d);
            s0 = fmaf(qa.x,k0,fmaf(qa.y,k1,fmaf(qa.z,k2,fmaf(qa.w,k3,s0))));
            s1 = fmaf(qb.x,k0,fmaf(qb.y,k1,fmaf(qb.z,k2,fmaf(qb.w,k3,s1))));
            s2 = fmaf(qc.x,k0,fmaf(qc.y,k1,fmaf(qc.z,k2,fmaf(qc.w,k3,s2))));
            s3 = fmaf(qd.x,k0,fmaf(qd.y,k1,fmaf(qd.z,k2,fmaf(qd.w,k3,s3))));
        }
        bool valid = (lane < ln);
        s0 = valid ? s0 * scale : -1e30f;
        s1 = valid ? s1 * scale : -1e30f;
        s2 = valid ? s2 * scale : -1e30f;
        s3 = valid ? s3 * scale : -1e30f;
        float a0, a1, a2, a3;
        { float m = warp_max(s0); float p = __expf(s0 - m); a0 = p * (1.f / warp_sum(p)); }
        { float m = warp_max(s1); float p = __expf(s1 - m); a1 = p * (1.f / warp_sum(p)); }
        { float m = warp_max(s2); float p = __expf(s2 - m); a2 = p * (1.f / warp_sum(p)); }
        { float m = warp_max(s3); float p = __expf(s3 - m); a3 = p * (1.f / warp_sum(p)); }

        float o0 = 0.f, o1 = 0.f, o2 = 0.f, o3 = 0.f;
        for (int k = 0; k < kln; k++) {
            float v = V[(klo + k) * SRW + base + lane];
            o0 = fmaf(__shfl_sync(0xffffffffu, a0, k), v, o0);
            o1 = fmaf(__shfl_sync(0xffffffffu, a1, k), v, o1);
            o2 = fmaf(__shfl_sync(0xffffffffu, a2, k), v, o2);
            o3 = fmaf(__shfl_sync(0xffffffffu, a3, k), v, o3);
        }
        QO[(r0 + 0) * SRW + base + lane] = o0;
        QO[(r0 + 1) * SRW + base + lane] = o1;
        QO[(r0 + 2) * SRW + base + lane] = o2;
        QO[(r0 + 3) * SRW + base + lane] = o3;
    }
}

// paired PMA attention: warps 0-3 gene A heads, 4-7 gene B heads; klo-based
__device__ __forceinline__ void attn_pma_pair(const float* Q, const float* Kt, const float* V,
                                              int gA, int gB, int offB, int lenA, int lenB,
                                              int w, int lane)
{
    const float scale = 0.17677669529663687f;
    int gi   = w >> 2;                  // 0 = gene A, 1 = gene B
    int base = (w & 3) * 32;
    int klo  = gi ? offB : 0;
    int ln   = gi ? lenB : lenA;
    int kln  = gi ? ((lenB + 3) & ~3) : ((lenA + 3) & ~3);
    float s = 0.f;
#pragma unroll
    for (int d = 0; d < 32; d += 4) {
        float4 q = *(const float4*)(Q + base + d);
        s = fmaf(q.x, Kt[(base + d + 0) * SKT + klo + lane],
            fmaf(q.y, Kt[(base + d + 1) * SKT + klo + lane],
            fmaf(q.z, Kt[(base + d + 2) * SKT + klo + lane],
            fmaf(q.w, Kt[(base + d + 3) * SKT + klo + lane], s))));
    }
    s = (lane < ln) ? s * scale : -1e30f;
    float m = warp_max(s);
    float p = __expf(s - m);
    float a = p * (1.f / warp_sum(p));
    float acc = 0.f;
    for (int k = 0; k < kln; k++)
        acc = fmaf(__shfl_sync(0xffffffffu, a, k), V[(klo + k) * SRW + base + lane], acc);
    int gout = gi ? gB : gA;
    if (gout >= 0) g_pma[(size_t)gout * CC + base + lane] = acc;
}

// attention (kv <= 64) for the long kernel
__device__ void attn64(const float* Q, const float* Kt, const float* V,
                       float* outp, int outStride,
                       int Lq, int len, int kvr, int w, int lane)
{
    const float scale = 0.17677669529663687f;
    int ntask = Lq * 4;
    for (int t = w; t < ntask; t += 8) {
        int r = t >> 2, base = (t & 3) * 32;
        float s0 = 0.f, s1 = 0.f;
#pragma unroll
        for (int d = 0; d < 32; d++) {
            float qd = Q[r * SR64 + base + d];
            s0 = fmaf(qd, Kt[(base + d) * SKT64 + lane], s0);
            s1 = fmaf(qd, Kt[(base + d) * SKT64 + lane + 32], s1);
        }
        s0 = (lane < len)      ? s0 * scale : -1e30f;
        s1 = (lane + 32 < len) ? s1 * scale : -1e30f;
        float m = warp_max(fmaxf(s0, s1));
        float p0 = __expf(s0 - m), p1 = __expf(s1 - m);
        float inv = 1.f / warp_sum(p0 + p1);
        float a0 = p0 * inv, a1 = p1 * inv;
        float acc = 0.f;
        int k0 = kvr < 32 ? kvr : 32;
        for (int k = 0; k < k0; k++)
            acc = fmaf(__shfl_sync(0xffffffffu, a0, k), V[k * SR64 + base + lane], acc);
        for (int k = 32; k < kvr; k++)
            acc = fmaf(__shfl_sync(0xffffffffu, a1, k - 32), V[k * SR64 + base + lane], acc);
        outp[r * outStride + base + lane] = acc;
    }
}

// ============================================================================
// LN(residual + masked A). resStride==0 -> broadcast residual.
// ============================================================================
template <int SROW>
__device__ void lnres(const float* A, const float* Res, int resStride, float* Out,
                      int rows, int qmasklen,
                      const float* __restrict__ g, const float* __restrict__ b,
                      int w, int lane)
{
    for (int r = w; r < rows; r += 8) {
        float4 a = (r < qmasklen) ? *(const float4*)(A + r * SROW + lane * 4)
                                  : make_float4(0.f, 0.f, 0.f, 0.f);
        float4 s = *(const float4*)(Res + r * resStride + lane * 4);
        float t0 = a.x + s.x, t1 = a.y + s.y, t2 = a.z + s.z, t3 = a.w + s.w;
        float sum = warp_sum(t0 + t1 + t2 + t3);
        float sq  = warp_sum(t0*t0 + t1*t1 + t2*t2 + t3*t3);
        float mean = sum * (1.f / 128.f);
        float var  = sq * (1.f / 128.f) - mean * mean;
        float rstd = rsqrtf(var + 1e-5f);
        float4 gv = *(const float4*)(g + lane * 4);
        float4 bv = *(const float4*)(b + lane * 4);
        float4 o;
        o.x = (t0 - mean) * rstd * gv.x + bv.x;
        o.y = (t1 - mean) * rstd * gv.y + bv.y;
        o.z = (t2 - mean) * rstd * gv.z + bv.z;
        o.w = (t3 - mean) * rstd * gv.w + bv.w;
        *(float4*)(Out + r * SROW + lane * 4) = o;
    }
}

// paired version: row valid if local index (relative to its gene window) < len
__device__ void lnres_pair(const float* A, const float* Res, float* Out,
                           int rows, int offB, int lenA, int lenB,
                           const float* __restrict__ g, const float* __restrict__ b,
                           int w, int lane)
{
    for (int r = w; r < rows; r += 8) {
        int lo = (r >= offB) ? offB : 0;
        int ln = (r >= offB) ? lenB : lenA;
        float4 a = ((r - lo) < ln) ? *(const float4*)(A + r * SRW + lane * 4)
                                   : make_float4(0.f, 0.f, 0.f, 0.f);
        float4 s = *(const float4*)(Res + r * SRW + lane * 4);
        float t0 = a.x + s.x, t1 = a.y + s.y, t2 = a.z + s.z, t3 = a.w + s.w;
        float sum = warp_sum(t0 + t1 + t2 + t3);
        float sq  = warp_sum(t0*t0 + t1*t1 + t2*t2 + t3*t3);
        float mean = sum * (1.f / 128.f);
        float var  = sq * (1.f / 128.f) - mean * mean;
        float rstd = rsqrtf(var + 1e-5f);
        float4 gv = *(const float4*)(g + lane * 4);
        float4 bv = *(const float4*)(b + lane * 4);
        float4 o;
        o.x = (t0 - mean) * rstd * gv.x + bv.x;
        o.y = (t1 - mean) * rstd * gv.y + bv.y;
        o.z = (t2 - mean) * rstd * gv.z + bv.z;
        o.w = (t3 - mean) * rstd * gv.w + bv.w;
        *(float4*)(Out + r * SRW + lane * 4) = o;
    }
}

// ============================================================================
// unified encoder(x2) + PMA attention for 1 or 2 genes in NS*4 rows (NS<=9)
// ============================================================================
template <int NS>
__device__ __forceinline__ void enc_pair(
    float* Sst, float* SA, float* SB, float* SC,
    const float* __restrict__ Wq, const float* __restrict__ Wk,
    const float* __restrict__ Wv, const float* __restrict__ Wo,
    const float* __restrict__ bq, const float* __restrict__ bk,
    const float* __restrict__ bv, const float* __restrict__ bo,
    const float* __restrict__ Wlin, const float* __restrict__ blin,
    const float* __restrict__ g1, const float* __restrict__ b1,
    const float* __restrict__ g2, const float* __restrict__ b2,
    int gA, int gB, int offB, int lenA, int lenB,
    int w, int lane, int tid)
{
    constexpr int ROWS = NS * 4;
#pragma unroll 1
    for (int blk = 0; blk < 2; blk++) {
        const float* wq = Wq + blk * CC * CC;  const float* wk = Wk + blk * CC * CC;
        const float* wv = Wv + blk * CC * CC;  const float* wo = Wo + blk * CC * CC;
        const float* wl = Wlin + blk * CC * CC;
        mm32s<NS, false, false>(Sst, wq, bq + blk * CC, SA, w, lane);
        mmKV<NS>(Sst, wk, bk + blk * CC, wv, bv + blk * CC, SB, SC, w, lane);
        __syncthreads();
        attn_pair<ROWS>(SA, SB, SC, offB, lenA, lenB, w, lane);
        __syncthreads();
        mm32s<NS, false, false>(SA, wo, bo + blk * CC, SB, w, lane);
        __syncthreads();
        lnres_pair(SB, Sst, Sst, ROWS, offB, lenA, lenB,
                   g1 + blk * CC, b1 + blk * CC, w, lane);
        __syncthreads();
        mm32s<NS, false, true>(Sst, wl, blin + blk * CC, SC, w, lane);
        __syncthreads();
        lnres<SRW>(SC, Sst, SRW, Sst, ROWS, ROWS, g2 + blk * CC, b2 + blk * CC, w, lane);
        __syncthreads();
    }
    if (tid < CC) SA[tid] = g_qpma[tid];
    mmKV<NS>(Sst, Wk + 2 * CC * CC, bk + 2 * CC, Wv + 2 * CC * CC, bv + 2 * CC,
             SB, SC, w, lane);
    __syncthreads();
    attn_pma_pair(SA, SB, SC, gA, gB, offB, lenA, lenB, w, lane);
}

// ============================================================================
// PACKED kernel: bin-packed 1-2 genes per CTA, up to 36 rows
// ============================================================================
__global__ __launch_bounds__(256, 3)
void gene_packed(const float* __restrict__ rf,
                 const float* __restrict__ Wq, const float* __restrict__ Wk,
                 const float* __restrict__ Wv, const float* __restrict__ Wo,
                 const float* __restrict__ bq, const float* __restrict__ bk,
                 const float* __restrict__ bv, const float* __restrict__ bo,
                 const float* __restrict__ Wlin, const float* __restrict__ blin,
                 const float* __restrict__ g1, const float* __restrict__ b1,
                 const float* __restrict__ g2, const float* __restrict__ b2,
                 const int* __restrict__ rxn_idx)
{
    extern __shared__ float sm[];
    float* Sst = sm;                    // [<=36][SRW]
    float* SA  = sm + B36;
    float* SB  = SA + B36;              // K^T [128][SKT]
    float* SC  = SB + KT36;

    int i    = blockIdx.x;
    if (i >= g_ncta) return;
    int tid  = threadIdx.x;
    int w    = tid >> 5;
    int lane = tid & 31;

    int gA = g_ctaA[i];
    int gB = g_ctaB[i];
    int sA = g_starts[gA];
    int lenA = g_starts[gA + 1] - sA;
    int sB = 0, lenB = 0;
    if (gB >= 0) { sB = g_starts[gB]; lenB = g_starts[gB + 1] - sB; }

    int offB = (lenA + 3) & ~3;
    int lenr = offB + ((lenB + 3) & ~3);     // multiple of 4, <= 36
    int NS   = lenr >> 2;                    // 1..9

    // gather
    for (int r = w; r < lenr; r += 8) {
        bool isB  = r >= offB;
        int local = isB ? (r - offB) : r;
        int ln    = isB ? lenB : lenA;
        int st    = isB ? sB   : sA;
        if (local < ln) {
            int rx = rxn_idx[st + local];
            ((float4*)(Sst + r * SRW))[lane] = ((const float4*)(rf + (size_t)rx * CC))[lane];
        } else {
            ((float4*)(Sst + r * SRW))[lane] = make_float4(0.f, 0.f, 0.f, 0.f);
        }
    }
    __syncthreads();

#define CALL_ENC(NSV) enc_pair<NSV>(Sst, SA, SB, SC, Wq, Wk, Wv, Wo, bq, bk, bv, bo, \
                                    Wlin, blin, g1, b1, g2, b2, gA, gB, offB, lenA, lenB, w, lane, tid)
    switch (NS) {
    case 1: CALL_ENC(1); break;
    case 2: CALL_ENC(2); break;
    case 3: CALL_ENC(3); break;
    case 4: CALL_ENC(4); break;
    case 5: CALL_ENC(5); break;
    case 6: CALL_ENC(6); break;
    case 7: CALL_ENC(7); break;
    case 8: CALL_ENC(8); break;
    default: CALL_ENC(9); break;
    }
#undef CALL_ENC
}

// ============================================================================
// LONG kernel: genes with len > 32 (rare); ends after PMA attention
// ============================================================================
__global__ __launch_bounds__(256, 1)
void gene_long64(const float* __restrict__ rf,
                 const float* __restrict__ Wq, const float* __restrict__ Wk,
                 const float* __restrict__ Wv, const float* __restrict__ Wo,
                 const float* __restrict__ bq, const float* __restrict__ bk,
                 const float* __restrict__ bv, const float* __restrict__ bo,
                 const float* __restrict__ Wlin, const float* __restrict__ blin,
                 const float* __restrict__ g1, const float* __restrict__ b1,
                 const float* __restrict__ g2, const float* __restrict__ b2,
                 const int* __restrict__ rxn_idx)
{
    extern __shared__ float sm[];
    float* Sst = sm;                    // [64][SR64]
    float* SA  = sm + B64;
    float* SB  = SA + B64;
    float* SC  = SB + KT64;

    int tid  = threadIdx.x;
    int w    = tid >> 5;
    int lane = tid & 31;
    int nlong = g_longcount;

    for (int i = blockIdx.x; i < nlong; i += gridDim.x) {
        int g     = g_longlist[i];
        int start = g_starts[g];
        int cnt   = g_starts[g + 1] - start;
        int len   = cnt < 64 ? cnt : 64;
        int lenr  = (len + 7) & ~7;
        if (lenr > 64) lenr = 64;

        for (int r = w; r < lenr; r += 8) {
            if (r < len) {
                int rx = rxn_idx[start + r];
                ((float4*)(Sst + r * SR64))[lane] = ((const float4*)(rf + (size_t)rx * CC))[lane];
            } else {
                ((float4*)(Sst + r * SR64))[lane] = make_float4(0.f, 0.f, 0.f, 0.f);
            }
        }
        __syncthreads();

        for (int blk = 0; blk < 2; blk++) {
            const float* wq = Wq + blk * CC * CC;  const float* wk = Wk + blk * CC * CC;
            const float* wv = Wv + blk * CC * CC;  const float* wo = Wo + blk * CC * CC;
            const float* wl = Wlin + blk * CC * CC;
            mm64row<false, false>(Sst, wq, bq + blk * CC, SA, lenr, w, lane);
            mm64row<true,  false>(Sst, wk, bk + blk * CC, SB, lenr, w, lane);
            mm64row<false, false>(Sst, wv, bv + blk * CC, SC, lenr, w, lane);
            __syncthreads();
            attn64(SA, SB, SC, SA, SR64, lenr, len, lenr, w, lane);
            __syncthreads();
            mm64row<false, false>(SA, wo, bo + blk * CC, SB, lenr, w, lane);
            __syncthreads();
            lnres<SR64>(SB, Sst, SR64, Sst, lenr, len, g1 + blk * CC, b1 + blk * CC, w, lane);
            __syncthreads();
            mm64row<false, true>(Sst, wl, blin + blk * CC, SC, lenr, w, lane);
            __syncthreads();
            lnres<SR64>(SC, Sst, SR64, Sst, lenr, lenr, g2 + blk * CC, b2 + blk * CC, w, lane);
            __syncthreads();
        }
        if (tid < CC) SA[tid] = g_qpma[tid];
        mm64row<true,  false>(Sst, Wk + 2 * CC * CC, bk + 2 * CC, SB, lenr, w, lane);
        mm64row<false, false>(Sst, Wv + 2 * CC * CC, bv + 2 * CC, SC, lenr, w, lane);
        __syncthreads();
        attn64(SA, SB, SC, g_pma + (size_t)g * CC, CC, 1, len, lenr, w, lane);
        __syncthreads();
    }
}

// ============================================================================
// TAIL kernel: batched PMA-projection + decoder over 16 genes per CTA
// ============================================================================
__global__ __launch_bounds__(256)
void gene_tail(const float* __restrict__ Wv, const float* __restrict__ Wo,
               const float* __restrict__ bv, const float* __restrict__ bo,
               const float* __restrict__ Wlin, const float* __restrict__ blin,
               const float* __restrict__ g1, const float* __restrict__ b1,
               const float* __restrict__ g2, const float* __restrict__ b2,
               const float* __restrict__ seed,
               float* __restrict__ out)
{
    extern __shared__ float sm[];
    float* Sst = sm;                    // [16][SRW]
    float* SA  = sm + B16T;
    float* SC  = SA + B16T;

    int g0   = blockIdx.x * 16;
    int tid  = threadIdx.x;
    int w    = tid >> 5;
    int lane = tid & 31;

    for (int r = w; r < 16; r += 8)
        ((float4*)(Sst + r * SRW))[lane] = ((const float4*)(g_pma + (size_t)(g0 + r) * CC))[lane];
    __syncthreads();

    mm32s<4, false, false>(Sst, Wo + 2 * CC * CC, bo + 2 * CC, SA, w, lane);
    __syncthreads();
    lnres<SRW>(SA, seed, 0, Sst, 16, 16, g1 + 2 * CC, b1 + 2 * CC, w, lane);
    __syncthreads();
    mm32s<4, false, true>(Sst, Wlin + 2 * CC * CC, blin + 2 * CC, SC, w, lane);
    __syncthreads();
    lnres<SRW>(SC, Sst, SRW, Sst, 16, 16, g2 + 2 * CC, b2 + 2 * CC, w, lane);
    __syncthreads();

    mm32s<4, false, false>(Sst, Wv + 3 * CC * CC, bv + 3 * CC, SA, w, lane);
    __syncthreads();
    mm32s<4, false, false>(SA, Wo + 3 * CC * CC, bo + 3 * CC, SC, w, lane);
    __syncthreads();
    lnres<SRW>(SC, Sst, SRW, Sst, 16, 16, g1 + 3 * CC, b1 + 3 * CC, w, lane);
    __syncthreads();
    mm32s<4, false, true>(Sst, Wlin + 3 * CC * CC, blin + 3 * CC, SC, w, lane);
    __syncthreads();
    lnres<SRW>(SC, Sst, SRW, Sst, 16, 16, g2 + 3 * CC, b2 + 3 * CC, w, lane);
    __syncthreads();

    for (int r = w; r < 16; r += 8) {
        float4 v = ((const float4*)(Sst + r * SRW))[lane];
        float o[4] = {v.x, v.y, v.z, v.w};
#pragma unroll
        for (int j = 0; j < 4; j++) {
            float x = o[j];
            if (x != x) x = 0.f;
            x = fminf(fmaxf(x, -3.402823466e38f), 3.402823466e38f);
            o[j] = x;
        }
        ((float4*)(out + (size_t)(g0 + r) * CC))[lane] = make_float4(o[0], o[1], o[2], o[3]);
    }
}

extern "C" void kernel_launch(void* const* d_in, const int* in_sizes, int n_in,
                              void* d_out, int out_size)
{
    const float* rf   = (const float*)d_in[0];
    const float* Wq   = (const float*)d_in[1];
    const float* Wk   = (const float*)d_in[2];
    const float* Wv   = (const float*)d_in[3];
    const float* Wo   = (const float*)d_in[4];
    const float* bq   = (const float*)d_in[5];
    const float* bk   = (const float*)d_in[6];
    const float* bv   = (const float*)d_in[7];
    const float* bo   = (const float*)d_in[8];
    const float* Wlin = (const float*)d_in[9];
    const float* blin = (const float*)d_in[10];
    const float* g1   = (const float*)d_in[11];
    const float* b1   = (const float*)d_in[12];
    const float* g2   = (const float*)d_in[13];
    const float* b2   = (const float*)d_in[14];
    const float* seed = (const float*)d_in[15];
    const int*   rxn  = (const int*)d_in[16];
    const int*   gidx = (const int*)d_in[17];
    int E = in_sizes[16];

    cudaFuncSetAttribute(gene_packed, cudaFuncAttributeMaxDynamicSharedMemorySize, SM36_BYTES);
    cudaFuncSetAttribute(gene_long64, cudaFuncAttributeMaxDynamicSharedMemorySize, SM64_BYTES);
    cudaFuncSetAttribute(gene_tail,   cudaFuncAttributeMaxDynamicSharedMemorySize, SMT_BYTES);

    seg_bounds_kernel<<<(E + 255) / 256, 256>>>(gidx, E);
    classify_kernel<<<(GENES + 255) / 256, 256>>>();
    pack_kernel<<<1, 256>>>(Wq, bq, seed);
    gene_packed<<<GENES, 256, SM36_BYTES>>>(rf, Wq, Wk, Wv, Wo, bq, bk, bv, bo,
                                            Wlin, blin, g1, b1, g2, b2, rxn);
    gene_long64<<<128, 256, SM64_BYTES>>>(rf, Wq, Wk, Wv, Wo, bq, bk, bv, bo,
                                          Wlin, blin, g1, b1, g2, b2, rxn);
    gene_tail<<<GENES / 16, 256, SMT_BYTES>>>(Wv, Wo, bv, bo, Wlin, blin,
                                              g1, b1, g2, b2, seed, (float*)d_out);
}